// round 8
// baseline (speedup 1.0000x reference)
#include <cuda_runtime.h>
#include <cstddef>
#include <cstdint>

#define S_    1024
#define H_    1024
#define HD_   64
#define NH_   16
#define KVH_  8
#define E_    64
#define TOPK_ 8
#define CAP_  512
#define I_    3072
#define QKVN_ 2048

// ---------------- static scratch ----------------
static const size_t OFF_X      = 0;
static const size_t OFF_QKV    = 1048576;
static const size_t OFF_Q      = 3145728;
static const size_t OFF_K      = 4194304;
static const size_t OFF_V      = 4718592;
static const size_t OFF_ATTN   = 5242880;
static const size_t OFF_H1     = 6291456;
static const size_t OFF_X2     = 7340032;
static const size_t OFF_ACTSH  = 8388608;
static const size_t OFF_W8     = 11599872;
static const size_t OFF_EXPW   = 11608064;
static const size_t OFF_ACTEXP = 11640832;
static const size_t FBUF_TOT   = 112304128;

static const size_t IOFF_IDX8   = 0;
static const size_t IOFF_EXPTOK = 8192;
static const size_t IOFF_EXPCNT = 40960;

__device__ float g_fbuf[FBUF_TOT];
__device__ int   g_ibuf[41028];

__device__ __forceinline__ uint32_t f2tf32(float f) {
    uint32_t r; asm("cvt.rna.tf32.f32 %0, %1;" : "=r"(r) : "f"(f)); return r;
}

__device__ __forceinline__ void mma_tf32(float* c, const uint32_t* a, const uint32_t* b) {
    asm volatile(
        "mma.sync.aligned.m16n8k8.row.col.f32.tf32.tf32.f32 "
        "{%0,%1,%2,%3}, {%4,%5,%6,%7}, {%8,%9}, {%0,%1,%2,%3};"
        : "+f"(c[0]), "+f"(c[1]), "+f"(c[2]), "+f"(c[3])
        : "r"(a[0]), "r"(a[1]), "r"(a[2]), "r"(a[3]), "r"(b[0]), "r"(b[1]));
}

// ---------------- tf32 mma.sync GEMM (R3 config: 128x128, 2x4 warps, 2 CTA/SM) ----
// MODE 0: plain  1: plain+add  2: shared swiglu  3: expert swiglu (gather rows)
// MODE 4: expert down-proj + weighted atomic scatter
// Expert modes (3/4) only handle slots [0, 128*gridDim.y); overflow handled separately.
#define A_STRIDE 20
#define B_STRIDE 136

template<int MODE>
__global__ void __launch_bounds__(256, 2) mma_gemm(
    const float* __restrict__ A, int lda,
    const float* __restrict__ B, int ldb,
    const float* __restrict__ Dadd,
    float* __restrict__ out, int ldc, int Kdim,
    const int* __restrict__ etok, const float* __restrict__ ew,
    const int* __restrict__ ecnt) {
    constexpr bool IS_SWI = (MODE == 2 || MODE == 3);
    constexpr bool IS_EXP = (MODE == 3 || MODE == 4);

    int e = IS_EXP ? blockIdx.z : 0;
    int cnt = IS_EXP ? ecnt[e] : S_;
    if (IS_EXP) { int mx = 128 * gridDim.y; cnt = (cnt < mx) ? cnt : mx; }
    int row0 = blockIdx.y * 128;
    if (IS_EXP && row0 >= cnt) return;
    int bx = blockIdx.x;

    __shared__ float As[2][128][A_STRIDE];
    __shared__ float Bs[2][16][B_STRIDE];
    __shared__ int   toks_s[128];
    __shared__ float ws_s[128];

    int tid = threadIdx.x;
    int wid = tid >> 5;
    int lane = tid & 31;
    int g = lane >> 2, t = lane & 3;
    int wm = wid & 1, wn = wid >> 1;

    const float* Ab = A;
    const float* Bb = B;
    float* outp = out;
    if (MODE == 3) { Bb = B + (size_t)e * H_ * 2 * I_; outp = out + (size_t)e * CAP_ * I_; }
    if (MODE == 4) { Ab = A + (size_t)e * CAP_ * I_; Bb = B + (size_t)e * I_ * H_; }

    if (IS_EXP && tid < 128) {
        int rr = row0 + tid;
        bool v = rr < cnt;
        toks_s[tid] = v ? etok[e * CAP_ + rr] : 0;
        ws_s[tid]   = v ? ew[e * CAP_ + rr] : 0.f;
    }
    if (IS_EXP) __syncthreads();

    const float* arow_ptr[2];
    int aq[2];
#pragma unroll
    for (int s = 0; s < 2; s++) {
        int f4 = tid + 256 * s;
        int r = f4 >> 2; aq[s] = (f4 & 3) * 4;
        if (MODE == 3) arow_ptr[s] = A + (size_t)toks_s[r] * lda;
        else           arow_ptr[s] = Ab + (size_t)(row0 + r) * lda;
    }
    const float* brow_base[2];
    int bk_[2];
#pragma unroll
    for (int s = 0; s < 2; s++) {
        int f4 = tid + 256 * s;
        int k = f4 >> 5, nq = f4 & 31;
        int col;
        if (IS_SWI) col = (nq < 16) ? (bx * 64 + nq * 4) : (I_ + bx * 64 + (nq - 16) * 4);
        else        col = bx * 128 + nq * 4;
        bk_[s] = k;
        brow_base[s] = Bb + (size_t)k * ldb + col;
    }

    float4 aR[2], bR[2];
    auto ldg = [&](int kt) {
#pragma unroll
        for (int s = 0; s < 2; s++) {
            aR[s] = *(const float4*)(arow_ptr[s] + kt + aq[s]);
            bR[s] = *(const float4*)(brow_base[s] + (size_t)kt * ldb);
        }
    };
    auto sts = [&](int buf) {
#pragma unroll
        for (int s = 0; s < 2; s++) {
            int f4 = tid + 256 * s;
            int r = f4 >> 2, q = (f4 & 3) * 4;
            float* d = &As[buf][r][q];
            d[0] = __uint_as_float(f2tf32(aR[s].x));
            d[1] = __uint_as_float(f2tf32(aR[s].y));
            d[2] = __uint_as_float(f2tf32(aR[s].z));
            d[3] = __uint_as_float(f2tf32(aR[s].w));
            int nq = f4 & 31;
            float* d2 = &Bs[buf][bk_[s]][nq * 4];
            d2[0] = __uint_as_float(f2tf32(bR[s].x));
            d2[1] = __uint_as_float(f2tf32(bR[s].y));
            d2[2] = __uint_as_float(f2tf32(bR[s].z));
            d2[3] = __uint_as_float(f2tf32(bR[s].w));
        }
    };

    float acc[4][4][4];
#pragma unroll
    for (int mi = 0; mi < 4; mi++)
#pragma unroll
        for (int ni = 0; ni < 4; ni++)
#pragma unroll
            for (int p = 0; p < 4; p++) acc[mi][ni][p] = 0.f;

    ldg(0); sts(0);
    __syncthreads();

    int NC = Kdim / 16;
    for (int c = 0; c < NC; c++) {
        int cur = c & 1;
        if (c + 1 < NC) ldg((c + 1) * 16);
#pragma unroll
        for (int k0 = 0; k0 < 16; k0 += 8) {
            uint32_t af[4][4], bf[4][2];
#pragma unroll
            for (int mi = 0; mi < 4; mi++) {
                int m0 = wm * 64 + mi * 16;
                af[mi][0] = __float_as_uint(As[cur][m0 + g][k0 + t]);
                af[mi][1] = __float_as_uint(As[cur][m0 + g + 8][k0 + t]);
                af[mi][2] = __float_as_uint(As[cur][m0 + g][k0 + t + 4]);
                af[mi][3] = __float_as_uint(As[cur][m0 + g + 8][k0 + t + 4]);
            }
#pragma unroll
            for (int ni = 0; ni < 4; ni++) {
                int n0;
                if (IS_SWI) n0 = (ni < 2) ? (wn * 16 + ni * 8) : (64 + wn * 16 + (ni - 2) * 8);
                else        n0 = wn * 32 + ni * 8;
                bf[ni][0] = __float_as_uint(Bs[cur][k0 + t][n0 + g]);
                bf[ni][1] = __float_as_uint(Bs[cur][k0 + t + 4][n0 + g]);
            }
#pragma unroll
            for (int mi = 0; mi < 4; mi++)
#pragma unroll
                for (int ni = 0; ni < 4; ni++)
                    mma_tf32(acc[mi][ni], af[mi], bf[ni]);
        }
        if (c + 1 < NC) sts(cur ^ 1);
        __syncthreads();
    }

    // ---------------- epilogue ----------------
    if (MODE == 0 || MODE == 1) {
#pragma unroll
        for (int mi = 0; mi < 4; mi++) {
            int r = row0 + wm * 64 + mi * 16 + g;
#pragma unroll
            for (int ni = 0; ni < 4; ni++) {
                int col = bx * 128 + wn * 32 + ni * 8 + 2 * t;
                float2 v0 = make_float2(acc[mi][ni][0], acc[mi][ni][1]);
                float2 v1 = make_float2(acc[mi][ni][2], acc[mi][ni][3]);
                if (MODE == 1) {
                    float2 d0 = *(const float2*)(Dadd + (size_t)r * ldc + col);
                    float2 d1 = *(const float2*)(Dadd + (size_t)(r + 8) * ldc + col);
                    v0.x += d0.x; v0.y += d0.y; v1.x += d1.x; v1.y += d1.y;
                }
                *(float2*)(outp + (size_t)r * ldc + col) = v0;
                *(float2*)(outp + (size_t)(r + 8) * ldc + col) = v1;
            }
        }
    } else if (IS_SWI) {
#pragma unroll
        for (int mi = 0; mi < 4; mi++) {
            int rl = wm * 64 + mi * 16 + g;
            int r = row0 + rl;
#pragma unroll
            for (int ni = 0; ni < 2; ni++) {
                int col = bx * 64 + wn * 16 + ni * 8 + 2 * t;
#pragma unroll
                for (int h = 0; h < 2; h++) {
                    int rg = r + 8 * h;
                    if (MODE == 3 && rg >= cnt) continue;
                    float gg0 = acc[mi][ni][2 * h + 0], gg1 = acc[mi][ni][2 * h + 1];
                    float uu0 = acc[mi][ni + 2][2 * h + 0], uu1 = acc[mi][ni + 2][2 * h + 1];
                    float s0 = 1.f / (1.f + __expf(-uu0));
                    float s1 = 1.f / (1.f + __expf(-uu1));
                    float2 v = make_float2(gg0 * uu0 * s0, gg1 * uu1 * s1);
                    *(float2*)(outp + (size_t)rg * I_ + col) = v;
                }
            }
        }
    } else {  // MODE 4
#pragma unroll
        for (int mi = 0; mi < 4; mi++) {
            int rl = wm * 64 + mi * 16 + g;
#pragma unroll
            for (int h = 0; h < 2; h++) {
                int rr = rl + 8 * h;
                if (row0 + rr >= cnt) continue;
                int tok = toks_s[rr];
                float wv = ws_s[rr];
#pragma unroll
                for (int ni = 0; ni < 4; ni++) {
                    int col = bx * 128 + wn * 32 + ni * 8 + 2 * t;
                    atomicAdd(out + (size_t)tok * H_ + col,     acc[mi][ni][2 * h + 0] * wv);
                    atomicAdd(out + (size_t)tok * H_ + col + 1, acc[mi][ni][2 * h + 1] * wv);
                }
            }
        }
    }
}

// ---------------- overflow expert kernels (slots >= 128, ~4-12 rows/expert) ----------
// fp32 FFMA, 16-row chunks, compute only real rows.
__global__ void __launch_bounds__(128) ovf_gu_kernel(
    const float* __restrict__ x2, const float* __restrict__ Wgu_e,
    const int* __restrict__ etok, const int* __restrict__ ecnt,
    float* __restrict__ actexp) {
    int e = blockIdx.z;
    int cnt = ecnt[e];
    int novf = cnt - 128;
    if (novf <= 0) return;
    int col0 = blockIdx.x * 128;
    int c = threadIdx.x;
    const float* Bg = Wgu_e + (size_t)e * H_ * 2 * I_;
    __shared__ float Asm[16][33];
    __shared__ int   tk[16];
    for (int rb = 0; rb < novf; rb += 16) {
        int nr = min(16, novf - rb);
        if (c < 16) tk[c] = (c < nr) ? etok[e * CAP_ + 128 + rb + c] : 0;
        __syncthreads();
        float accg[16], accu[16];
#pragma unroll
        for (int r = 0; r < 16; r++) { accg[r] = 0.f; accu[r] = 0.f; }
        for (int kc = 0; kc < H_; kc += 32) {
            for (int idx = c; idx < 16 * 32; idx += 128) {
                int r = idx >> 5, k = idx & 31;
                Asm[r][k] = (r < nr) ? x2[(size_t)tk[r] * H_ + kc + k] : 0.f;
            }
            __syncthreads();
#pragma unroll 4
            for (int k = 0; k < 32; k++) {
                float bg = Bg[(size_t)(kc + k) * (2 * I_) + col0 + c];
                float bu = Bg[(size_t)(kc + k) * (2 * I_) + I_ + col0 + c];
#pragma unroll
                for (int r = 0; r < 16; r++) {
                    accg[r] = fmaf(Asm[r][k], bg, accg[r]);
                    accu[r] = fmaf(Asm[r][k], bu, accu[r]);
                }
            }
            __syncthreads();
        }
        for (int r = 0; r < nr; r++) {
            float gg = accg[r], uu = accu[r];
            float sg = 1.f / (1.f + __expf(-uu));
            actexp[((size_t)e * CAP_ + 128 + rb + r) * I_ + col0 + c] = gg * uu * sg;
        }
        __syncthreads();
    }
}

__global__ void __launch_bounds__(128) ovf_down_kernel(
    const float* __restrict__ actexp, const float* __restrict__ Wd_e,
    const int* __restrict__ etok, const float* __restrict__ ew,
    const int* __restrict__ ecnt, float* __restrict__ out) {
    int e = blockIdx.z;
    int cnt = ecnt[e];
    int novf = cnt - 128;
    if (novf <= 0) return;
    int col0 = blockIdx.x * 128;
    int c = threadIdx.x;
    const float* B = Wd_e + (size_t)e * I_ * H_;
    __shared__ float Asm[16][33];
    __shared__ int   tk[16];
    __shared__ float wsh[16];
    for (int rb = 0; rb < novf; rb += 16) {
        int nr = min(16, novf - rb);
        if (c < 16) {
            bool v = c < nr;
            tk[c]  = v ? etok[e * CAP_ + 128 + rb + c] : 0;
            wsh[c] = v ? ew[e * CAP_ + 128 + rb + c] : 0.f;
        }
        __syncthreads();
        float acc[16];
#pragma unroll
        for (int r = 0; r < 16; r++) acc[r] = 0.f;
        for (int kc = 0; kc < I_; kc += 32) {
            for (int idx = c; idx < 16 * 32; idx += 128) {
                int r = idx >> 5, k = idx & 31;
                Asm[r][k] = (r < nr) ? actexp[((size_t)e * CAP_ + 128 + rb + r) * I_ + kc + k] : 0.f;
            }
            __syncthreads();
#pragma unroll 4
            for (int k = 0; k < 32; k++) {
                float b = B[(size_t)(kc + k) * H_ + col0 + c];
#pragma unroll
                for (int r = 0; r < 16; r++) acc[r] = fmaf(Asm[r][k], b, acc[r]);
            }
            __syncthreads();
        }
        for (int r = 0; r < nr; r++)
            atomicAdd(&out[(size_t)tk[r] * H_ + col0 + c], acc[r] * wsh[r]);
        __syncthreads();
    }
}

// ---------------- RMSNorm ----------------
__global__ void rmsnorm_kernel(const float* __restrict__ in, const float* __restrict__ w,
                               float* __restrict__ out) {
    int row = blockIdx.x, tid = threadIdx.x;
    const float* x = in + (size_t)row * H_;
    float s = 0.f;
    for (int i = tid; i < H_; i += 256) { float v = x[i]; s += v * v; }
    __shared__ float red[256];
    red[tid] = s; __syncthreads();
    for (int o = 128; o > 0; o >>= 1) { if (tid < o) red[tid] += red[tid + o]; __syncthreads(); }
    float sc = rsqrtf(red[0] * (1.f / H_) + 1e-6f);
    for (int i = tid; i < H_; i += 256) out[(size_t)row * H_ + i] = x[i] * sc * w[i];
}

// ---------------- QKV postprocess ----------------
__global__ void qkvproc_kernel(const float* __restrict__ qkv, const float* __restrict__ cosb,
                               const float* __restrict__ sinb, const float* __restrict__ qnw,
                               const float* __restrict__ knw, float* __restrict__ q,
                               float* __restrict__ k, float* __restrict__ v) {
    int s = blockIdx.x, tid = threadIdx.x;
    int w = tid >> 5, lane = tid & 31;
#pragma unroll
    for (int p = 0; p < 4; p++) {
        int r = w + 8 * p;
        int kv = r >> 2, slot = r & 3;
        int base = s * QKVN_ + kv * 256 + slot * 64;
        int d0 = lane * 2, d1 = d0 + 1;
        float x0 = qkv[base + d0], x1 = qkv[base + d1];
        float y0, y1;
        if (slot == 3) { y0 = x0; y1 = x1; }
        else {
            float p0 = __shfl_xor_sync(0xffffffffu, x0, 16);
            float p1 = __shfl_xor_sync(0xffffffffu, x1, 16);
            float rh0 = (lane < 16) ? -p0 : p0;
            float rh1 = (lane < 16) ? -p1 : p1;
            float c0 = cosb[s * HD_ + d0], s0 = sinb[s * HD_ + d0];
            float c1 = cosb[s * HD_ + d1], s1 = sinb[s * HD_ + d1];
            y0 = x0 * c0 + rh0 * s0;
            y1 = x1 * c1 + rh1 * s1;
            float ss = y0 * y0 + y1 * y1;
            for (int off = 16; off > 0; off >>= 1) ss += __shfl_xor_sync(0xffffffffu, ss, off);
            float scn = rsqrtf(ss * (1.f / HD_) + 1e-6f);
            const float* wn = (slot < 2) ? qnw : knw;
            y0 = y0 * scn * wn[d0];
            y1 = y1 * scn * wn[d1];
        }
        if (slot < 2) {
            int hh = kv * 2 + slot;
            size_t off = ((size_t)hh * S_ + s) * HD_;
            q[off + d0] = y0; q[off + d1] = y1;
        } else if (slot == 2) {
            size_t off = ((size_t)kv * S_ + s) * HD_;
            k[off + d0] = y0; k[off + d1] = y1;
        } else {
            size_t off = ((size_t)kv * S_ + s) * HD_;
            v[off + d0] = y0; v[off + d1] = y1;
        }
    }
}

// ---------------- flash attention ----------------
__global__ void attn_kernel(const float* __restrict__ qg, const float* __restrict__ kg,
                            const float* __restrict__ vg, float* __restrict__ attn) {
    int qt = blockIdx.x, h = blockIdx.y;
    int q0 = qt * 64;
    const float* Q = qg + ((size_t)h * S_ + q0) * HD_;
    const float* Kp = kg + ((size_t)(h >> 1) * S_) * HD_;
    const float* Vp = vg + ((size_t)(h >> 1) * S_) * HD_;
    __shared__ float Qs[64][65];
    __shared__ float U[64][33];
    __shared__ float Vs[32][64];
    int tid = threadIdx.x;
    int ty = tid >> 4, tx = tid & 15;
    {
        int d = tid & 63, r0 = (tid >> 6) * 16;
#pragma unroll
        for (int qq = 0; qq < 16; qq++) Qs[r0 + qq][d] = Q[(size_t)(r0 + qq) * HD_ + d];
    }
    float o[4][4]; float m[4], l[4];
#pragma unroll
    for (int i = 0; i < 4; i++) {
        m[i] = -1e30f; l[i] = 0.f;
#pragma unroll
        for (int j = 0; j < 4; j++) o[i][j] = 0.f;
    }
    int nkt = (q0 + 64) / 32;
    for (int kt = 0; kt < nkt; kt++) {
        int k0 = kt * 32;
        {
            int d = tid & 63, kgp = tid >> 6;
#pragma unroll
            for (int qq = 0; qq < 8; qq++) {
                int key = kgp * 8 + qq;
                U[d][key]  = Kp[(size_t)(k0 + key) * HD_ + d];
                Vs[key][d] = Vp[(size_t)(k0 + key) * HD_ + d];
            }
        }
        __syncthreads();
        float sc[4][2];
#pragma unroll
        for (int i = 0; i < 4; i++) { sc[i][0] = 0.f; sc[i][1] = 0.f; }
        for (int d = 0; d < 64; d++) {
            float qv[4], kv[2];
#pragma unroll
            for (int i = 0; i < 4; i++) qv[i] = Qs[ty * 4 + i][d];
#pragma unroll
            for (int j = 0; j < 2; j++) kv[j] = U[d][tx * 2 + j];
#pragma unroll
            for (int i = 0; i < 4; i++)
#pragma unroll
                for (int j = 0; j < 2; j++) sc[i][j] = fmaf(qv[i], kv[j], sc[i][j]);
        }
        __syncthreads();
        float pr[4][2];
#pragma unroll
        for (int i = 0; i < 4; i++) {
            int qrow = q0 + ty * 4 + i;
            float mi = -1e30f;
            bool msk[2];
#pragma unroll
            for (int j = 0; j < 2; j++) {
                int kc = k0 + tx * 2 + j;
                msk[j] = (kc > qrow);
                float vv = msk[j] ? -1e30f : sc[i][j] * 0.125f;
                sc[i][j] = vv;
                mi = fmaxf(mi, vv);
            }
            for (int off = 8; off > 0; off >>= 1) mi = fmaxf(mi, __shfl_xor_sync(0xffffffffu, mi, off));
            float mn = fmaxf(m[i], mi);
            float corr = __expf(m[i] - mn);
            float rs = 0.f;
#pragma unroll
            for (int j = 0; j < 2; j++) {
                pr[i][j] = msk[j] ? 0.f : __expf(sc[i][j] - mn);
                rs += pr[i][j];
            }
            for (int off = 8; off > 0; off >>= 1) rs += __shfl_xor_sync(0xffffffffu, rs, off);
            l[i] = l[i] * corr + rs;
            m[i] = mn;
#pragma unroll
            for (int jj = 0; jj < 4; jj++) o[i][jj] *= corr;
        }
#pragma unroll
        for (int i = 0; i < 4; i++)
#pragma unroll
            for (int j = 0; j < 2; j++) U[ty * 4 + i][tx * 2 + j] = pr[i][j];
        __syncthreads();
        for (int k = 0; k < 32; k++) {
            float pv[4], vv[4];
#pragma unroll
            for (int i = 0; i < 4; i++) pv[i] = U[ty * 4 + i][k];
#pragma unroll
            for (int jj = 0; jj < 4; jj++) vv[jj] = Vs[k][tx * 4 + jj];
#pragma unroll
            for (int i = 0; i < 4; i++)
#pragma unroll
                for (int jj = 0; jj < 4; jj++) o[i][jj] = fmaf(pv[i], vv[jj], o[i][jj]);
        }
        __syncthreads();
    }
#pragma unroll
    for (int i = 0; i < 4; i++) {
        float inv = 1.f / l[i];
#pragma unroll
        for (int jj = 0; jj < 4; jj++)
            attn[(size_t)(q0 + ty * 4 + i) * H_ + h * HD_ + tx * 4 + jj] = o[i][jj] * inv;
    }
}

// ---------------- gate + top-8 ----------------
__global__ void gate_topk_kernel(const float* __restrict__ x2, const float* __restrict__ Wg,
                                 float* __restrict__ w8, int* __restrict__ idx8) {
    int tt = blockIdx.x, tid = threadIdx.x;
    const float* xr = x2 + (size_t)tt * H_;
    float a0 = 0.f, a1 = 0.f, a2 = 0.f, a3 = 0.f;
    for (int h = 0; h < H_; h += 4) {
        a0 = fmaf(xr[h],     Wg[(size_t)h * E_ + tid],       a0);
        a1 = fmaf(xr[h + 1], Wg[(size_t)(h + 1) * E_ + tid], a1);
        a2 = fmaf(xr[h + 2], Wg[(size_t)(h + 2) * E_ + tid], a2);
        a3 = fmaf(xr[h + 3], Wg[(size_t)(h + 3) * E_ + tid], a3);
    }
    float logit = (a0 + a1) + (a2 + a3);
    __shared__ float red[64];
    __shared__ float gv[64];
    red[tid] = logit; __syncthreads();
    for (int o = 32; o > 0; o >>= 1) { if (tid < o) red[tid] = fmaxf(red[tid], red[tid + o]); __syncthreads(); }
    float mx = red[0]; __syncthreads();
    float ex = __expf(logit - mx);
    red[tid] = ex; __syncthreads();
    for (int o = 32; o > 0; o >>= 1) { if (tid < o) red[tid] += red[tid + o]; __syncthreads(); }
    float sum = red[0];
    gv[tid] = ex / sum; __syncthreads();
    if (tid == 0) {
        bool used[E_];
        for (int e = 0; e < E_; e++) used[e] = false;
        float wv[TOPK_]; int id[TOPK_]; float wsum = 0.f;
        for (int r = 0; r < TOPK_; r++) {
            int best = 0; float bv = -1e30f;
            for (int e = 0; e < E_; e++)
                if (!used[e] && gv[e] > bv) { bv = gv[e]; best = e; }
            used[best] = true; wv[r] = bv; id[r] = best; wsum += bv;
        }
        wsum = fmaxf(wsum, 1.1920929e-07f);
        for (int r = 0; r < TOPK_; r++) {
            w8[tt * TOPK_ + r] = wv[r] / wsum;
            idx8[tt * TOPK_ + r] = id[r];
        }
    }
}

// ---------------- routing ----------------
__global__ void route_kernel(const int* __restrict__ idx8, const float* __restrict__ w8,
                             int* __restrict__ etok, float* __restrict__ ew, int* __restrict__ ecnt) {
    int e = blockIdx.x, lane = threadIdx.x;
    int cnt = 0;
    for (int base = 0; base < S_ * TOPK_; base += 32) {
        int j = base + lane;
        int ee = idx8[j];
        bool match = (ee == e);
        unsigned bal = __ballot_sync(0xffffffffu, match);
        int pre = __popc(bal & ((1u << lane) - 1u));
        if (match) {
            int p = cnt + pre;
            if (p < CAP_) {
                etok[e * CAP_ + p] = j >> 3;
                ew[e * CAP_ + p] = w8[j];
            }
        }
        cnt += __popc(bal);
    }
    if (lane == 0) ecnt[e] = (cnt < CAP_) ? cnt : CAP_;
}

// ---------------- launch ----------------
extern "C" void kernel_launch(void* const* d_in, const int* in_sizes, int n_in,
                              void* d_out, int out_size) {
    (void)in_sizes; (void)n_in; (void)out_size;
    const float* hidden = (const float*)d_in[0];
    const float* cosb   = (const float*)d_in[1];
    const float* sinb   = (const float*)d_in[2];
    const float* ln1    = (const float*)d_in[3];
    const float* ln2    = (const float*)d_in[4];
    const float* Wqkv   = (const float*)d_in[5];
    const float* Wo     = (const float*)d_in[6];
    const float* qnw    = (const float*)d_in[7];
    const float* knw    = (const float*)d_in[8];
    const float* Wgu_sh = (const float*)d_in[9];
    const float* Wd_sh  = (const float*)d_in[10];
    const float* Wgate  = (const float*)d_in[11];
    const float* Wgu_e  = (const float*)d_in[12];
    const float* Wd_e   = (const float*)d_in[13];
    float* out = (float*)d_out;

    float* fb = nullptr; int* ib = nullptr;
    cudaGetSymbolAddress((void**)&fb, g_fbuf);
    cudaGetSymbolAddress((void**)&ib, g_ibuf);

    float* x      = fb + OFF_X;
    float* qkv    = fb + OFF_QKV;
    float* q      = fb + OFF_Q;
    float* k      = fb + OFF_K;
    float* v      = fb + OFF_V;
    float* attn   = fb + OFF_ATTN;
    float* h1     = fb + OFF_H1;
    float* x2     = fb + OFF_X2;
    float* actsh  = fb + OFF_ACTSH;
    float* w8     = fb + OFF_W8;
    float* expw   = fb + OFF_EXPW;
    float* actexp = fb + OFF_ACTEXP;
    int* idx8   = ib + IOFF_IDX8;
    int* exptok = ib + IOFF_EXPTOK;
    int* expcnt = ib + IOFF_EXPCNT;

    // 1. x = rmsnorm(hidden, ln1)
    rmsnorm_kernel<<<S_, 256>>>(hidden, ln1, x);
    // 2. qkv = x @ Wqkv
    mma_gemm<0><<<dim3(QKVN_ / 128, S_ / 128), 256>>>(
        x, H_, Wqkv, QKVN_, nullptr, qkv, QKVN_, H_, nullptr, nullptr, nullptr);
    // 3. RoPE + QK-norm
    qkvproc_kernel<<<S_, 256>>>(qkv, cosb, sinb, qnw, knw, q, k, v);
    // 4. attention
    attn_kernel<<<dim3(S_ / 64, NH_), 256>>>(q, k, v, attn);
    // 5. h1 = attn @ Wo + hidden
    mma_gemm<1><<<dim3(H_ / 128, S_ / 128), 256>>>(
        attn, H_, Wo, H_, hidden, h1, H_, H_, nullptr, nullptr, nullptr);
    // 6. x2 = rmsnorm(h1, ln2)
    rmsnorm_kernel<<<S_, 256>>>(h1, ln2, x2);
    // 7. shared swiglu activation
    mma_gemm<2><<<dim3(I_ / 64, S_ / 128), 256>>>(
        x2, H_, Wgu_sh, 2 * I_, nullptr, actsh, I_, H_, nullptr, nullptr, nullptr);
    // 8. out = actsh @ Wd_sh + h1
    mma_gemm<1><<<dim3(H_ / 128, S_ / 128), 256>>>(
        actsh, I_, Wd_sh, H_, h1, out, H_, I_, nullptr, nullptr, nullptr);
    // 9. gate + top-8
    gate_topk_kernel<<<S_, 64>>>(x2, Wgate, w8, idx8);
    // 10. routing
    route_kernel<<<E_, 32>>>(idx8, w8, exptok, expw, expcnt);
    // 11a. expert swiglu, slots 0-127 (mma)
    mma_gemm<3><<<dim3(I_ / 64, 1, E_), 256>>>(
        x2, H_, Wgu_e, 2 * I_, nullptr, actexp, I_, H_, exptok, nullptr, expcnt);
    // 11b. expert swiglu overflow slots 128+ (ffma, exact rows)
    ovf_gu_kernel<<<dim3(I_ / 128, 1, E_), 128>>>(x2, Wgu_e, exptok, expcnt, actexp);
    // 12a. expert down + scatter, slots 0-127 (mma)
    mma_gemm<4><<<dim3(H_ / 128, 1, E_), 256>>>(
        actexp, I_, Wd_e, H_, nullptr, out, H_, I_, exptok, expw, expcnt);
    // 12b. expert down overflow slots 128+ (ffma, exact rows)
    ovf_down_kernel<<<dim3(H_ / 128, 1, E_), 128>>>(actexp, Wd_e, exptok, expw, expcnt, out);
}

// round 9
// speedup vs baseline: 1.6027x; 1.6027x over previous
#include <cuda_runtime.h>
#include <cstddef>
#include <cstdint>

#define S_    1024
#define H_    1024
#define HD_   64
#define NH_   16
#define KVH_  8
#define E_    64
#define TOPK_ 8
#define CAP_  512
#define I_    3072
#define QKVN_ 2048

// ---------------- static scratch ----------------
static const size_t OFF_X      = 0;
static const size_t OFF_QKV    = 1048576;
static const size_t OFF_Q      = 3145728;
static const size_t OFF_K      = 4194304;
static const size_t OFF_V      = 4718592;
static const size_t OFF_ATTN   = 5242880;
static const size_t OFF_H1     = 6291456;
static const size_t OFF_X2     = 7340032;
static const size_t OFF_ACTSH  = 8388608;
static const size_t OFF_W8     = 11599872;
static const size_t OFF_EXPW   = 11608064;
static const size_t OFF_ACTEXP = 11640832;
static const size_t FBUF_TOT   = 112304128;

static const size_t IOFF_IDX8   = 0;
static const size_t IOFF_EXPTOK = 8192;
static const size_t IOFF_EXPCNT = 40960;

__device__ float g_fbuf[FBUF_TOT];
__device__ int   g_ibuf[41028];

__device__ __forceinline__ uint32_t f2tf32(float f) {
    uint32_t r; asm("cvt.rna.tf32.f32 %0, %1;" : "=r"(r) : "f"(f)); return r;
}

__device__ __forceinline__ void mma_tf32(float* c, const uint32_t* a, const uint32_t* b) {
    asm volatile(
        "mma.sync.aligned.m16n8k8.row.col.f32.tf32.tf32.f32 "
        "{%0,%1,%2,%3}, {%4,%5,%6,%7}, {%8,%9}, {%0,%1,%2,%3};"
        : "+f"(c[0]), "+f"(c[1]), "+f"(c[2]), "+f"(c[3])
        : "r"(a[0]), "r"(a[1]), "r"(a[2]), "r"(a[3]), "r"(b[0]), "r"(b[1]));
}

// ---------------- tf32 mma.sync GEMM (128x128, 2x4 warps, 2 CTA/SM) ----------------
// MODE 0: plain  1: plain+add  2: shared swiglu  3: expert swiglu (gather rows)
// MODE 4: expert down-proj + weighted atomic scatter
// Expert modes handle slots [0, 128*gridDim.y); overflow handled by mma_gemm_s.
#define A_STRIDE 20
#define B_STRIDE 136

template<int MODE>
__global__ void __launch_bounds__(256, 2) mma_gemm(
    const float* __restrict__ A, int lda,
    const float* __restrict__ B, int ldb,
    const float* __restrict__ Dadd,
    float* __restrict__ out, int ldc, int Kdim,
    const int* __restrict__ etok, const float* __restrict__ ew,
    const int* __restrict__ ecnt) {
    constexpr bool IS_SWI = (MODE == 2 || MODE == 3);
    constexpr bool IS_EXP = (MODE == 3 || MODE == 4);

    int e = IS_EXP ? blockIdx.z : 0;
    int cnt = IS_EXP ? ecnt[e] : S_;
    if (IS_EXP) { int mx = 128 * gridDim.y; cnt = (cnt < mx) ? cnt : mx; }
    int row0 = blockIdx.y * 128;
    if (IS_EXP && row0 >= cnt) return;
    int bx = blockIdx.x;

    __shared__ float As[2][128][A_STRIDE];
    __shared__ float Bs[2][16][B_STRIDE];
    __shared__ int   toks_s[128];
    __shared__ float ws_s[128];

    int tid = threadIdx.x;
    int wid = tid >> 5;
    int lane = tid & 31;
    int g = lane >> 2, t = lane & 3;
    int wm = wid & 1, wn = wid >> 1;

    const float* Ab = A;
    const float* Bb = B;
    float* outp = out;
    if (MODE == 3) { Bb = B + (size_t)e * H_ * 2 * I_; outp = out + (size_t)e * CAP_ * I_; }
    if (MODE == 4) { Ab = A + (size_t)e * CAP_ * I_; Bb = B + (size_t)e * I_ * H_; }

    if (IS_EXP && tid < 128) {
        int rr = row0 + tid;
        bool v = rr < cnt;
        toks_s[tid] = v ? etok[e * CAP_ + rr] : 0;
        ws_s[tid]   = v ? ew[e * CAP_ + rr] : 0.f;
    }
    if (IS_EXP) __syncthreads();

    const float* arow_ptr[2];
    int aq[2];
#pragma unroll
    for (int s = 0; s < 2; s++) {
        int f4 = tid + 256 * s;
        int r = f4 >> 2; aq[s] = (f4 & 3) * 4;
        if (MODE == 3) arow_ptr[s] = A + (size_t)toks_s[r] * lda;
        else           arow_ptr[s] = Ab + (size_t)(row0 + r) * lda;
    }
    const float* brow_base[2];
    int bk_[2];
#pragma unroll
    for (int s = 0; s < 2; s++) {
        int f4 = tid + 256 * s;
        int k = f4 >> 5, nq = f4 & 31;
        int col;
        if (IS_SWI) col = (nq < 16) ? (bx * 64 + nq * 4) : (I_ + bx * 64 + (nq - 16) * 4);
        else        col = bx * 128 + nq * 4;
        bk_[s] = k;
        brow_base[s] = Bb + (size_t)k * ldb + col;
    }

    float4 aR[2], bR[2];
    auto ldg = [&](int kt) {
#pragma unroll
        for (int s = 0; s < 2; s++) {
            aR[s] = *(const float4*)(arow_ptr[s] + kt + aq[s]);
            bR[s] = *(const float4*)(brow_base[s] + (size_t)kt * ldb);
        }
    };
    auto sts = [&](int buf) {
#pragma unroll
        for (int s = 0; s < 2; s++) {
            int f4 = tid + 256 * s;
            int r = f4 >> 2, q = (f4 & 3) * 4;
            float* d = &As[buf][r][q];
            d[0] = __uint_as_float(f2tf32(aR[s].x));
            d[1] = __uint_as_float(f2tf32(aR[s].y));
            d[2] = __uint_as_float(f2tf32(aR[s].z));
            d[3] = __uint_as_float(f2tf32(aR[s].w));
            int nq = f4 & 31;
            float* d2 = &Bs[buf][bk_[s]][nq * 4];
            d2[0] = __uint_as_float(f2tf32(bR[s].x));
            d2[1] = __uint_as_float(f2tf32(bR[s].y));
            d2[2] = __uint_as_float(f2tf32(bR[s].z));
            d2[3] = __uint_as_float(f2tf32(bR[s].w));
        }
    };

    float acc[4][4][4];
#pragma unroll
    for (int mi = 0; mi < 4; mi++)
#pragma unroll
        for (int ni = 0; ni < 4; ni++)
#pragma unroll
            for (int p = 0; p < 4; p++) acc[mi][ni][p] = 0.f;

    ldg(0); sts(0);
    __syncthreads();

    int NC = Kdim / 16;
    for (int c = 0; c < NC; c++) {
        int cur = c & 1;
        if (c + 1 < NC) ldg((c + 1) * 16);
#pragma unroll
        for (int k0 = 0; k0 < 16; k0 += 8) {
            uint32_t af[4][4], bf[4][2];
#pragma unroll
            for (int mi = 0; mi < 4; mi++) {
                int m0 = wm * 64 + mi * 16;
                af[mi][0] = __float_as_uint(As[cur][m0 + g][k0 + t]);
                af[mi][1] = __float_as_uint(As[cur][m0 + g + 8][k0 + t]);
                af[mi][2] = __float_as_uint(As[cur][m0 + g][k0 + t + 4]);
                af[mi][3] = __float_as_uint(As[cur][m0 + g + 8][k0 + t + 4]);
            }
#pragma unroll
            for (int ni = 0; ni < 4; ni++) {
                int n0;
                if (IS_SWI) n0 = (ni < 2) ? (wn * 16 + ni * 8) : (64 + wn * 16 + (ni - 2) * 8);
                else        n0 = wn * 32 + ni * 8;
                bf[ni][0] = __float_as_uint(Bs[cur][k0 + t][n0 + g]);
                bf[ni][1] = __float_as_uint(Bs[cur][k0 + t + 4][n0 + g]);
            }
#pragma unroll
            for (int mi = 0; mi < 4; mi++)
#pragma unroll
                for (int ni = 0; ni < 4; ni++)
                    mma_tf32(acc[mi][ni], af[mi], bf[ni]);
        }
        if (c + 1 < NC) sts(cur ^ 1);
        __syncthreads();
    }

    // ---------------- epilogue ----------------
    if (MODE == 0 || MODE == 1) {
#pragma unroll
        for (int mi = 0; mi < 4; mi++) {
            int r = row0 + wm * 64 + mi * 16 + g;
#pragma unroll
            for (int ni = 0; ni < 4; ni++) {
                int col = bx * 128 + wn * 32 + ni * 8 + 2 * t;
                float2 v0 = make_float2(acc[mi][ni][0], acc[mi][ni][1]);
                float2 v1 = make_float2(acc[mi][ni][2], acc[mi][ni][3]);
                if (MODE == 1) {
                    float2 d0 = *(const float2*)(Dadd + (size_t)r * ldc + col);
                    float2 d1 = *(const float2*)(Dadd + (size_t)(r + 8) * ldc + col);
                    v0.x += d0.x; v0.y += d0.y; v1.x += d1.x; v1.y += d1.y;
                }
                *(float2*)(outp + (size_t)r * ldc + col) = v0;
                *(float2*)(outp + (size_t)(r + 8) * ldc + col) = v1;
            }
        }
    } else if (IS_SWI) {
#pragma unroll
        for (int mi = 0; mi < 4; mi++) {
            int rl = wm * 64 + mi * 16 + g;
            int r = row0 + rl;
#pragma unroll
            for (int ni = 0; ni < 2; ni++) {
                int col = bx * 64 + wn * 16 + ni * 8 + 2 * t;
#pragma unroll
                for (int h = 0; h < 2; h++) {
                    int rg = r + 8 * h;
                    if (MODE == 3 && rg >= cnt) continue;
                    float gg0 = acc[mi][ni][2 * h + 0], gg1 = acc[mi][ni][2 * h + 1];
                    float uu0 = acc[mi][ni + 2][2 * h + 0], uu1 = acc[mi][ni + 2][2 * h + 1];
                    float s0 = 1.f / (1.f + __expf(-uu0));
                    float s1 = 1.f / (1.f + __expf(-uu1));
                    float2 v = make_float2(gg0 * uu0 * s0, gg1 * uu1 * s1);
                    *(float2*)(outp + (size_t)rg * I_ + col) = v;
                }
            }
        }
    } else {  // MODE 4
#pragma unroll
        for (int mi = 0; mi < 4; mi++) {
            int rl = wm * 64 + mi * 16 + g;
#pragma unroll
            for (int h = 0; h < 2; h++) {
                int rr = rl + 8 * h;
                if (row0 + rr >= cnt) continue;
                int tok = toks_s[rr];
                float wv = ws_s[rr];
#pragma unroll
                for (int ni = 0; ni < 4; ni++) {
                    int col = bx * 128 + wn * 32 + ni * 8 + 2 * t;
                    atomicAdd(out + (size_t)tok * H_ + col,     acc[mi][ni][2 * h + 0] * wv);
                    atomicAdd(out + (size_t)tok * H_ + col + 1, acc[mi][ni][2 * h + 1] * wv);
                }
            }
        }
    }
}

// ---------------- small-M (32-row) expert mma kernel for overflow slots ----------------
// Same pipeline/B-layout as mma_gemm; 8 warps laid out 1x8 over N.
// MODE 3: swiglu gather; MODE 4: down-proj + scatter. row0 = 128 + blockIdx.y*32.
template<int MODE>
__global__ void __launch_bounds__(256, 2) mma_gemm_s(
    const float* __restrict__ A, int lda,
    const float* __restrict__ B, int ldb,
    float* __restrict__ out, int Kdim,
    const int* __restrict__ etok, const float* __restrict__ ew,
    const int* __restrict__ ecnt) {
    constexpr bool IS_SWI = (MODE == 3);

    int e = blockIdx.z;
    int cnt = ecnt[e];
    int row0 = 128 + blockIdx.y * 32;
    if (row0 >= cnt) return;
    int bx = blockIdx.x;

    __shared__ float As[2][32][A_STRIDE];
    __shared__ float Bs[2][16][B_STRIDE];
    __shared__ int   toks_s[32];
    __shared__ float ws_s[32];

    int tid = threadIdx.x;
    int wid = tid >> 5;
    int lane = tid & 31;
    int g = lane >> 2, t = lane & 3;
    int wn = wid;  // 0..7

    const float* Ab = A;
    const float* Bb = B;
    float* outp = out;
    if (MODE == 3) { Bb = B + (size_t)e * H_ * 2 * I_; outp = out + (size_t)e * CAP_ * I_; }
    if (MODE == 4) { Ab = A + (size_t)e * CAP_ * I_; Bb = B + (size_t)e * I_ * H_; }

    if (tid < 32) {
        int rr = row0 + tid;
        bool v = rr < cnt;
        toks_s[tid] = v ? etok[e * CAP_ + rr] : 0;
        ws_s[tid]   = v ? ew[e * CAP_ + rr] : 0.f;
    }
    __syncthreads();

    // A: 128 float4 per chunk; threads tid<128, r = tid>>2, q = tid&3
    const float* arow_ptr = nullptr;
    int aq = 0;
    if (tid < 128) {
        int r = tid >> 2; aq = (tid & 3) * 4;
        if (MODE == 3) arow_ptr = A + (size_t)toks_s[r] * lda;
        else           arow_ptr = Ab + (size_t)(row0 + r) * lda;
    }
    // B: identical to large kernel
    const float* brow_base[2];
    int bk_[2];
#pragma unroll
    for (int s = 0; s < 2; s++) {
        int f4 = tid + 256 * s;
        int k = f4 >> 5, nq = f4 & 31;
        int col;
        if (IS_SWI) col = (nq < 16) ? (bx * 64 + nq * 4) : (I_ + bx * 64 + (nq - 16) * 4);
        else        col = bx * 128 + nq * 4;
        bk_[s] = k;
        brow_base[s] = Bb + (size_t)k * ldb + col;
    }

    float4 aR, bR[2];
    auto ldg = [&](int kt) {
        if (tid < 128) aR = *(const float4*)(arow_ptr + kt + aq);
#pragma unroll
        for (int s = 0; s < 2; s++) bR[s] = *(const float4*)(brow_base[s] + (size_t)kt * ldb);
    };
    auto sts = [&](int buf) {
        if (tid < 128) {
            int r = tid >> 2, q = (tid & 3) * 4;
            float* d = &As[buf][r][q];
            d[0] = __uint_as_float(f2tf32(aR.x));
            d[1] = __uint_as_float(f2tf32(aR.y));
            d[2] = __uint_as_float(f2tf32(aR.z));
            d[3] = __uint_as_float(f2tf32(aR.w));
        }
#pragma unroll
        for (int s = 0; s < 2; s++) {
            int f4 = tid + 256 * s;
            int nq = f4 & 31;
            float* d2 = &Bs[buf][bk_[s]][nq * 4];
            d2[0] = __uint_as_float(f2tf32(bR[s].x));
            d2[1] = __uint_as_float(f2tf32(bR[s].y));
            d2[2] = __uint_as_float(f2tf32(bR[s].z));
            d2[3] = __uint_as_float(f2tf32(bR[s].w));
        }
    };

    float acc[2][2][4];
#pragma unroll
    for (int mi = 0; mi < 2; mi++)
#pragma unroll
        for (int ni = 0; ni < 2; ni++)
#pragma unroll
            for (int p = 0; p < 4; p++) acc[mi][ni][p] = 0.f;

    ldg(0); sts(0);
    __syncthreads();

    int NC = Kdim / 16;
    for (int c = 0; c < NC; c++) {
        int cur = c & 1;
        if (c + 1 < NC) ldg((c + 1) * 16);
#pragma unroll
        for (int k0 = 0; k0 < 16; k0 += 8) {
            uint32_t af[2][4], bf[2][2];
#pragma unroll
            for (int mi = 0; mi < 2; mi++) {
                int m0 = mi * 16;
                af[mi][0] = __float_as_uint(As[cur][m0 + g][k0 + t]);
                af[mi][1] = __float_as_uint(As[cur][m0 + g + 8][k0 + t]);
                af[mi][2] = __float_as_uint(As[cur][m0 + g][k0 + t + 4]);
                af[mi][3] = __float_as_uint(As[cur][m0 + g + 8][k0 + t + 4]);
            }
#pragma unroll
            for (int ni = 0; ni < 2; ni++) {
                int n0;
                if (IS_SWI) n0 = (ni == 0) ? (wn * 8) : (64 + wn * 8);
                else        n0 = wn * 16 + ni * 8;
                bf[ni][0] = __float_as_uint(Bs[cur][k0 + t][n0 + g]);
                bf[ni][1] = __float_as_uint(Bs[cur][k0 + t + 4][n0 + g]);
            }
#pragma unroll
            for (int mi = 0; mi < 2; mi++)
#pragma unroll
                for (int ni = 0; ni < 2; ni++)
                    mma_tf32(acc[mi][ni], af[mi], bf[ni]);
        }
        if (c + 1 < NC) sts(cur ^ 1);
        __syncthreads();
    }

    if (MODE == 3) {
#pragma unroll
        for (int mi = 0; mi < 2; mi++) {
            int col = bx * 64 + wn * 8 + 2 * t;
#pragma unroll
            for (int h = 0; h < 2; h++) {
                int rl = mi * 16 + g + 8 * h;
                int rg = row0 + rl;
                if (rg >= cnt) continue;
                float gg0 = acc[mi][0][2 * h + 0], gg1 = acc[mi][0][2 * h + 1];
                float uu0 = acc[mi][1][2 * h + 0], uu1 = acc[mi][1][2 * h + 1];
                float s0 = 1.f / (1.f + __expf(-uu0));
                float s1 = 1.f / (1.f + __expf(-uu1));
                float2 v = make_float2(gg0 * uu0 * s0, gg1 * uu1 * s1);
                *(float2*)(outp + (size_t)rg * I_ + col) = v;
            }
        }
    } else {  // MODE 4
#pragma unroll
        for (int mi = 0; mi < 2; mi++) {
#pragma unroll
            for (int h = 0; h < 2; h++) {
                int rl = mi * 16 + g + 8 * h;
                if (row0 + rl >= cnt) continue;
                int tok = toks_s[rl];
                float wv = ws_s[rl];
#pragma unroll
                for (int ni = 0; ni < 2; ni++) {
                    int col = bx * 128 + wn * 16 + ni * 8 + 2 * t;
                    atomicAdd(out + (size_t)tok * H_ + col,     acc[mi][ni][2 * h + 0] * wv);
                    atomicAdd(out + (size_t)tok * H_ + col + 1, acc[mi][ni][2 * h + 1] * wv);
                }
            }
        }
    }
}

// ---------------- RMSNorm ----------------
__global__ void rmsnorm_kernel(const float* __restrict__ in, const float* __restrict__ w,
                               float* __restrict__ out) {
    int row = blockIdx.x, tid = threadIdx.x;
    const float* x = in + (size_t)row * H_;
    float s = 0.f;
    for (int i = tid; i < H_; i += 256) { float v = x[i]; s += v * v; }
    __shared__ float red[256];
    red[tid] = s; __syncthreads();
    for (int o = 128; o > 0; o >>= 1) { if (tid < o) red[tid] += red[tid + o]; __syncthreads(); }
    float sc = rsqrtf(red[0] * (1.f / H_) + 1e-6f);
    for (int i = tid; i < H_; i += 256) out[(size_t)row * H_ + i] = x[i] * sc * w[i];
}

// ---------------- QKV postprocess ----------------
__global__ void qkvproc_kernel(const float* __restrict__ qkv, const float* __restrict__ cosb,
                               const float* __restrict__ sinb, const float* __restrict__ qnw,
                               const float* __restrict__ knw, float* __restrict__ q,
                               float* __restrict__ k, float* __restrict__ v) {
    int s = blockIdx.x, tid = threadIdx.x;
    int w = tid >> 5, lane = tid & 31;
#pragma unroll
    for (int p = 0; p < 4; p++) {
        int r = w + 8 * p;
        int kv = r >> 2, slot = r & 3;
        int base = s * QKVN_ + kv * 256 + slot * 64;
        int d0 = lane * 2, d1 = d0 + 1;
        float x0 = qkv[base + d0], x1 = qkv[base + d1];
        float y0, y1;
        if (slot == 3) { y0 = x0; y1 = x1; }
        else {
            float p0 = __shfl_xor_sync(0xffffffffu, x0, 16);
            float p1 = __shfl_xor_sync(0xffffffffu, x1, 16);
            float rh0 = (lane < 16) ? -p0 : p0;
            float rh1 = (lane < 16) ? -p1 : p1;
            float c0 = cosb[s * HD_ + d0], s0 = sinb[s * HD_ + d0];
            float c1 = cosb[s * HD_ + d1], s1 = sinb[s * HD_ + d1];
            y0 = x0 * c0 + rh0 * s0;
            y1 = x1 * c1 + rh1 * s1;
            float ss = y0 * y0 + y1 * y1;
            for (int off = 16; off > 0; off >>= 1) ss += __shfl_xor_sync(0xffffffffu, ss, off);
            float scn = rsqrtf(ss * (1.f / HD_) + 1e-6f);
            const float* wn = (slot < 2) ? qnw : knw;
            y0 = y0 * scn * wn[d0];
            y1 = y1 * scn * wn[d1];
        }
        if (slot < 2) {
            int hh = kv * 2 + slot;
            size_t off = ((size_t)hh * S_ + s) * HD_;
            q[off + d0] = y0; q[off + d1] = y1;
        } else if (slot == 2) {
            size_t off = ((size_t)kv * S_ + s) * HD_;
            k[off + d0] = y0; k[off + d1] = y1;
        } else {
            size_t off = ((size_t)kv * S_ + s) * HD_;
            v[off + d0] = y0; v[off + d1] = y1;
        }
    }
}

// ---------------- flash attention ----------------
__global__ void attn_kernel(const float* __restrict__ qg, const float* __restrict__ kg,
                            const float* __restrict__ vg, float* __restrict__ attn) {
    int qt = blockIdx.x, h = blockIdx.y;
    int q0 = qt * 64;
    const float* Q = qg + ((size_t)h * S_ + q0) * HD_;
    const float* Kp = kg + ((size_t)(h >> 1) * S_) * HD_;
    const float* Vp = vg + ((size_t)(h >> 1) * S_) * HD_;
    __shared__ float Qs[64][65];
    __shared__ float U[64][33];
    __shared__ float Vs[32][64];
    int tid = threadIdx.x;
    int ty = tid >> 4, tx = tid & 15;
    {
        int d = tid & 63, r0 = (tid >> 6) * 16;
#pragma unroll
        for (int qq = 0; qq < 16; qq++) Qs[r0 + qq][d] = Q[(size_t)(r0 + qq) * HD_ + d];
    }
    float o[4][4]; float m[4], l[4];
#pragma unroll
    for (int i = 0; i < 4; i++) {
        m[i] = -1e30f; l[i] = 0.f;
#pragma unroll
        for (int j = 0; j < 4; j++) o[i][j] = 0.f;
    }
    int nkt = (q0 + 64) / 32;
    for (int kt = 0; kt < nkt; kt++) {
        int k0 = kt * 32;
        {
            int d = tid & 63, kgp = tid >> 6;
#pragma unroll
            for (int qq = 0; qq < 8; qq++) {
                int key = kgp * 8 + qq;
                U[d][key]  = Kp[(size_t)(k0 + key) * HD_ + d];
                Vs[key][d] = Vp[(size_t)(k0 + key) * HD_ + d];
            }
        }
        __syncthreads();
        float sc[4][2];
#pragma unroll
        for (int i = 0; i < 4; i++) { sc[i][0] = 0.f; sc[i][1] = 0.f; }
        for (int d = 0; d < 64; d++) {
            float qv[4], kv[2];
#pragma unroll
            for (int i = 0; i < 4; i++) qv[i] = Qs[ty * 4 + i][d];
#pragma unroll
            for (int j = 0; j < 2; j++) kv[j] = U[d][tx * 2 + j];
#pragma unroll
            for (int i = 0; i < 4; i++)
#pragma unroll
                for (int j = 0; j < 2; j++) sc[i][j] = fmaf(qv[i], kv[j], sc[i][j]);
        }
        __syncthreads();
        float pr[4][2];
#pragma unroll
        for (int i = 0; i < 4; i++) {
            int qrow = q0 + ty * 4 + i;
            float mi = -1e30f;
            bool msk[2];
#pragma unroll
            for (int j = 0; j < 2; j++) {
                int kc = k0 + tx * 2 + j;
                msk[j] = (kc > qrow);
                float vv = msk[j] ? -1e30f : sc[i][j] * 0.125f;
                sc[i][j] = vv;
                mi = fmaxf(mi, vv);
            }
            for (int off = 8; off > 0; off >>= 1) mi = fmaxf(mi, __shfl_xor_sync(0xffffffffu, mi, off));
            float mn = fmaxf(m[i], mi);
            float corr = __expf(m[i] - mn);
            float rs = 0.f;
#pragma unroll
            for (int j = 0; j < 2; j++) {
                pr[i][j] = msk[j] ? 0.f : __expf(sc[i][j] - mn);
                rs += pr[i][j];
            }
            for (int off = 8; off > 0; off >>= 1) rs += __shfl_xor_sync(0xffffffffu, rs, off);
            l[i] = l[i] * corr + rs;
            m[i] = mn;
#pragma unroll
            for (int jj = 0; jj < 4; jj++) o[i][jj] *= corr;
        }
#pragma unroll
        for (int i = 0; i < 4; i++)
#pragma unroll
            for (int j = 0; j < 2; j++) U[ty * 4 + i][tx * 2 + j] = pr[i][j];
        __syncthreads();
        for (int k = 0; k < 32; k++) {
            float pv[4], vv[4];
#pragma unroll
            for (int i = 0; i < 4; i++) pv[i] = U[ty * 4 + i][k];
#pragma unroll
            for (int jj = 0; jj < 4; jj++) vv[jj] = Vs[k][tx * 4 + jj];
#pragma unroll
            for (int i = 0; i < 4; i++)
#pragma unroll
                for (int jj = 0; jj < 4; jj++) o[i][jj] = fmaf(pv[i], vv[jj], o[i][jj]);
        }
        __syncthreads();
    }
#pragma unroll
    for (int i = 0; i < 4; i++) {
        float inv = 1.f / l[i];
#pragma unroll
        for (int jj = 0; jj < 4; jj++)
            attn[(size_t)(q0 + ty * 4 + i) * H_ + h * HD_ + tx * 4 + jj] = o[i][jj] * inv;
    }
}

// ---------------- gate + top-8 ----------------
__global__ void gate_topk_kernel(const float* __restrict__ x2, const float* __restrict__ Wg,
                                 float* __restrict__ w8, int* __restrict__ idx8) {
    int tt = blockIdx.x, tid = threadIdx.x;
    const float* xr = x2 + (size_t)tt * H_;
    float a0 = 0.f, a1 = 0.f, a2 = 0.f, a3 = 0.f;
    for (int h = 0; h < H_; h += 4) {
        a0 = fmaf(xr[h],     Wg[(size_t)h * E_ + tid],       a0);
        a1 = fmaf(xr[h + 1], Wg[(size_t)(h + 1) * E_ + tid], a1);
        a2 = fmaf(xr[h + 2], Wg[(size_t)(h + 2) * E_ + tid], a2);
        a3 = fmaf(xr[h + 3], Wg[(size_t)(h + 3) * E_ + tid], a3);
    }
    float logit = (a0 + a1) + (a2 + a3);
    __shared__ float red[64];
    __shared__ float gv[64];
    red[tid] = logit; __syncthreads();
    for (int o = 32; o > 0; o >>= 1) { if (tid < o) red[tid] = fmaxf(red[tid], red[tid + o]); __syncthreads(); }
    float mx = red[0]; __syncthreads();
    float ex = __expf(logit - mx);
    red[tid] = ex; __syncthreads();
    for (int o = 32; o > 0; o >>= 1) { if (tid < o) red[tid] += red[tid + o]; __syncthreads(); }
    float sum = red[0];
    gv[tid] = ex / sum; __syncthreads();
    if (tid == 0) {
        bool used[E_];
        for (int e = 0; e < E_; e++) used[e] = false;
        float wv[TOPK_]; int id[TOPK_]; float wsum = 0.f;
        for (int r = 0; r < TOPK_; r++) {
            int best = 0; float bv = -1e30f;
            for (int e = 0; e < E_; e++)
                if (!used[e] && gv[e] > bv) { bv = gv[e]; best = e; }
            used[best] = true; wv[r] = bv; id[r] = best; wsum += bv;
        }
        wsum = fmaxf(wsum, 1.1920929e-07f);
        for (int r = 0; r < TOPK_; r++) {
            w8[tt * TOPK_ + r] = wv[r] / wsum;
            idx8[tt * TOPK_ + r] = id[r];
        }
    }
}

// ---------------- routing ----------------
__global__ void route_kernel(const int* __restrict__ idx8, const float* __restrict__ w8,
                             int* __restrict__ etok, float* __restrict__ ew, int* __restrict__ ecnt) {
    int e = blockIdx.x, lane = threadIdx.x;
    int cnt = 0;
    for (int base = 0; base < S_ * TOPK_; base += 32) {
        int j = base + lane;
        int ee = idx8[j];
        bool match = (ee == e);
        unsigned bal = __ballot_sync(0xffffffffu, match);
        int pre = __popc(bal & ((1u << lane) - 1u));
        if (match) {
            int p = cnt + pre;
            if (p < CAP_) {
                etok[e * CAP_ + p] = j >> 3;
                ew[e * CAP_ + p] = w8[j];
            }
        }
        cnt += __popc(bal);
    }
    if (lane == 0) ecnt[e] = (cnt < CAP_) ? cnt : CAP_;
}

// ---------------- launch ----------------
extern "C" void kernel_launch(void* const* d_in, const int* in_sizes, int n_in,
                              void* d_out, int out_size) {
    (void)in_sizes; (void)n_in; (void)out_size;
    const float* hidden = (const float*)d_in[0];
    const float* cosb   = (const float*)d_in[1];
    const float* sinb   = (const float*)d_in[2];
    const float* ln1    = (const float*)d_in[3];
    const float* ln2    = (const float*)d_in[4];
    const float* Wqkv   = (const float*)d_in[5];
    const float* Wo     = (const float*)d_in[6];
    const float* qnw    = (const float*)d_in[7];
    const float* knw    = (const float*)d_in[8];
    const float* Wgu_sh = (const float*)d_in[9];
    const float* Wd_sh  = (const float*)d_in[10];
    const float* Wgate  = (const float*)d_in[11];
    const float* Wgu_e  = (const float*)d_in[12];
    const float* Wd_e   = (const float*)d_in[13];
    float* out = (float*)d_out;

    float* fb = nullptr; int* ib = nullptr;
    cudaGetSymbolAddress((void**)&fb, g_fbuf);
    cudaGetSymbolAddress((void**)&ib, g_ibuf);

    float* x      = fb + OFF_X;
    float* qkv    = fb + OFF_QKV;
    float* q      = fb + OFF_Q;
    float* k      = fb + OFF_K;
    float* v      = fb + OFF_V;
    float* attn   = fb + OFF_ATTN;
    float* h1     = fb + OFF_H1;
    float* x2     = fb + OFF_X2;
    float* actsh  = fb + OFF_ACTSH;
    float* w8     = fb + OFF_W8;
    float* expw   = fb + OFF_EXPW;
    float* actexp = fb + OFF_ACTEXP;
    int* idx8   = ib + IOFF_IDX8;
    int* exptok = ib + IOFF_EXPTOK;
    int* expcnt = ib + IOFF_EXPCNT;

    // 1. x = rmsnorm(hidden, ln1)
    rmsnorm_kernel<<<S_, 256>>>(hidden, ln1, x);
    // 2. qkv = x @ Wqkv
    mma_gemm<0><<<dim3(QKVN_ / 128, S_ / 128), 256>>>(
        x, H_, Wqkv, QKVN_, nullptr, qkv, QKVN_, H_, nullptr, nullptr, nullptr);
    // 3. RoPE + QK-norm
    qkvproc_kernel<<<S_, 256>>>(qkv, cosb, sinb, qnw, knw, q, k, v);
    // 4. attention
    attn_kernel<<<dim3(S_ / 64, NH_), 256>>>(q, k, v, attn);
    // 5. h1 = attn @ Wo + hidden
    mma_gemm<1><<<dim3(H_ / 128, S_ / 128), 256>>>(
        attn, H_, Wo, H_, hidden, h1, H_, H_, nullptr, nullptr, nullptr);
    // 6. x2 = rmsnorm(h1, ln2)
    rmsnorm_kernel<<<S_, 256>>>(h1, ln2, x2);
    // 7. shared swiglu activation
    mma_gemm<2><<<dim3(I_ / 64, S_ / 128), 256>>>(
        x2, H_, Wgu_sh, 2 * I_, nullptr, actsh, I_, H_, nullptr, nullptr, nullptr);
    // 8. out = actsh @ Wd_sh + h1
    mma_gemm<1><<<dim3(H_ / 128, S_ / 128), 256>>>(
        actsh, I_, Wd_sh, H_, h1, out, H_, I_, nullptr, nullptr, nullptr);
    // 9. gate + top-8
    gate_topk_kernel<<<S_, 64>>>(x2, Wgate, w8, idx8);
    // 10. routing
    route_kernel<<<E_, 32>>>(idx8, w8, exptok, expw, expcnt);
    // 11a. expert swiglu, slots 0-127 (128-row mma)
    mma_gemm<3><<<dim3(I_ / 64, 1, E_), 256>>>(
        x2, H_, Wgu_e, 2 * I_, nullptr, actexp, I_, H_, exptok, nullptr, expcnt);
    // 11b. expert swiglu overflow slots 128..511 (32-row mma, early-exit)
    mma_gemm_s<3><<<dim3(I_ / 64, 12, E_), 256>>>(
        x2, H_, Wgu_e, 2 * I_, actexp, H_, exptok, nullptr, expcnt);
    // 12a. expert down + scatter, slots 0-127 (128-row mma)
    mma_gemm<4><<<dim3(H_ / 128, 1, E_), 256>>>(
        actexp, I_, Wd_e, H_, nullptr, out, H_, I_, exptok, expw, expcnt);
    // 12b. expert down overflow slots 128..511 (32-row mma, early-exit)
    mma_gemm_s<4><<<dim3(H_ / 128, 12, E_), 256>>>(
        actexp, I_, Wd_e, H_, out, I_, exptok, expw, expcnt);
}

// round 11
// speedup vs baseline: 1.8848x; 1.1760x over previous
#include <cuda_runtime.h>
#include <cstddef>
#include <cstdint>

#define S_    1024
#define H_    1024
#define HD_   64
#define NH_   16
#define KVH_  8
#define E_    64
#define TOPK_ 8
#define CAP_  512
#define I_    3072
#define QKVN_ 2048

// ---------------- static scratch ----------------
static const size_t OFF_X      = 0;
static const size_t OFF_QKV    = 1048576;
static const size_t OFF_Q      = 3145728;
static const size_t OFF_K      = 4194304;
static const size_t OFF_V      = 4718592;
static const size_t OFF_ATTN   = 5242880;
static const size_t OFF_H1     = 6291456;
static const size_t OFF_X2     = 7340032;
static const size_t OFF_ACTSH  = 8388608;
static const size_t OFF_W8     = 11599872;
static const size_t OFF_EXPW   = 11608064;
static const size_t OFF_ACTEXP = 11640832;
static const size_t FBUF_TOT   = 112304128;

static const size_t IOFF_IDX8   = 0;
static const size_t IOFF_EXPTOK = 8192;
static const size_t IOFF_EXPCNT = 40960;

__device__ float g_fbuf[FBUF_TOT];
__device__ int   g_ibuf[41028];

// pack two fp32 -> f16x2 word, round-to-nearest-even; lo = first arg
__device__ __forceinline__ uint32_t pack_f16(float lo, float hi) {
    uint32_t r;
    asm("cvt.rn.f16x2.f32 %0, %1, %2;" : "=r"(r) : "f"(hi), "f"(lo));
    return r;
}

__device__ __forceinline__ void mma_f16(float* c, const uint32_t* a, const uint32_t* b) {
    asm volatile(
        "mma.sync.aligned.m16n8k16.row.col.f32.f16.f16.f32 "
        "{%0,%1,%2,%3}, {%4,%5,%6,%7}, {%8,%9}, {%0,%1,%2,%3};"
        : "+f"(c[0]), "+f"(c[1]), "+f"(c[2]), "+f"(c[3])
        : "r"(a[0]), "r"(a[1]), "r"(a[2]), "r"(a[3]), "r"(b[0]), "r"(b[1]));
}

// ---------------- fp16 mma.sync GEMM (128x128, 2x4 warps, 2 CTA/SM) ----------------
// Smem: A words [2][128][12] (f16x2 along k, row stride 12 words, k=16/chunk)
//       B words [2][8][132]  (f16x2 = k-pair, kp rows, n stride 132 words)
// MODE 0: plain  1: plain+add  2: shared swiglu  3: expert swiglu (gather rows)
// MODE 4: expert down-proj + weighted atomic scatter
#define AWS 12
#define BWS 132

template<int MODE>
__global__ void __launch_bounds__(256, 2) mma_gemm(
    const float* __restrict__ A, int lda,
    const float* __restrict__ B, int ldb,
    const float* __restrict__ Dadd,
    float* __restrict__ out, int ldc, int Kdim,
    const int* __restrict__ etok, const float* __restrict__ ew,
    const int* __restrict__ ecnt) {
    constexpr bool IS_SWI = (MODE == 2 || MODE == 3);
    constexpr bool IS_EXP = (MODE == 3 || MODE == 4);

    int e = IS_EXP ? blockIdx.z : 0;
    int cnt = IS_EXP ? ecnt[e] : S_;
    if (IS_EXP) { int mx = 128 * gridDim.y; cnt = (cnt < mx) ? cnt : mx; }
    int row0 = blockIdx.y * 128;
    if (IS_EXP && row0 >= cnt) return;
    int bx = blockIdx.x;

    __shared__ uint32_t Aw[2][128 * AWS];
    __shared__ uint32_t Bw[2][8 * BWS];
    __shared__ int   toks_s[128];
    __shared__ float ws_s[128];

    int tid = threadIdx.x;
    int wid = tid >> 5;
    int lane = tid & 31;
    int g = lane >> 2, t = lane & 3;
    int wm = wid & 1, wn = wid >> 1;

    const float* Ab = A;
    const float* Bb = B;
    float* outp = out;
    if (MODE == 3) { Bb = B + (size_t)e * H_ * 2 * I_; outp = out + (size_t)e * CAP_ * I_; }
    if (MODE == 4) { Ab = A + (size_t)e * CAP_ * I_; Bb = B + (size_t)e * I_ * H_; }

    if (IS_EXP && tid < 128) {
        int rr = row0 + tid;
        bool v = rr < cnt;
        toks_s[tid] = v ? etok[e * CAP_ + rr] : 0;
        ws_s[tid]   = v ? ew[e * CAP_ + rr] : 0.f;
    }
    if (IS_EXP) __syncthreads();

    // A: 2 float4 tasks/thread: f4 = tid + 256*s, row = f4>>2, q = f4&3
    const float* arow_ptr[2];
    int aq[2];
#pragma unroll
    for (int s = 0; s < 2; s++) {
        int f4 = tid + 256 * s;
        int r = f4 >> 2; aq[s] = (f4 & 3) * 4;
        if (MODE == 3) arow_ptr[s] = A + (size_t)toks_s[r] * lda;
        else           arow_ptr[s] = Ab + (size_t)(row0 + r) * lda;
    }
    // B: 1 pack task/thread: kp = tid>>5 (0..7), nq = tid&31 (float4 col group)
    int kp = tid >> 5, nq = tid & 31;
    int bcol;
    if (IS_SWI) bcol = (nq < 16) ? (bx * 64 + nq * 4) : (I_ + bx * 64 + (nq - 16) * 4);
    else        bcol = bx * 128 + nq * 4;
    const float* b_even = Bb + (size_t)(2 * kp) * ldb + bcol;
    const float* b_odd  = Bb + (size_t)(2 * kp + 1) * ldb + bcol;

    float4 aR[2], bE, bO;
    auto ldg = [&](int kt) {
#pragma unroll
        for (int s = 0; s < 2; s++) aR[s] = *(const float4*)(arow_ptr[s] + kt + aq[s]);
        bE = *(const float4*)(b_even + (size_t)kt * ldb);
        bO = *(const float4*)(b_odd  + (size_t)kt * ldb);
    };
    auto sts = [&](int buf) {
#pragma unroll
        for (int s = 0; s < 2; s++) {
            int f4 = tid + 256 * s;
            int r = f4 >> 2, q = f4 & 3;
            uint2 w;
            w.x = pack_f16(aR[s].x, aR[s].y);
            w.y = pack_f16(aR[s].z, aR[s].w);
            *(uint2*)&Aw[buf][r * AWS + 2 * q] = w;
        }
        uint4 wb;
        wb.x = pack_f16(bE.x, bO.x);
        wb.y = pack_f16(bE.y, bO.y);
        wb.z = pack_f16(bE.z, bO.z);
        wb.w = pack_f16(bE.w, bO.w);
        *(uint4*)&Bw[buf][kp * BWS + nq * 4] = wb;
    };

    float acc[4][4][4];
#pragma unroll
    for (int mi = 0; mi < 4; mi++)
#pragma unroll
        for (int ni = 0; ni < 4; ni++)
#pragma unroll
            for (int p = 0; p < 4; p++) acc[mi][ni][p] = 0.f;

    ldg(0); sts(0);
    __syncthreads();

    int NC = Kdim / 16;
    for (int c = 0; c < NC; c++) {
        int cur = c & 1;
        if (c + 1 < NC) ldg((c + 1) * 16);
        {
            uint32_t af[4][4], bf[4][2];
#pragma unroll
            for (int mi = 0; mi < 4; mi++) {
                int base = (wm * 64 + mi * 16 + g) * AWS;
                af[mi][0] = Aw[cur][base + t];
                af[mi][1] = Aw[cur][base + 8 * AWS + t];
                af[mi][2] = Aw[cur][base + t + 4];
                af[mi][3] = Aw[cur][base + 8 * AWS + t + 4];
            }
#pragma unroll
            for (int ni = 0; ni < 4; ni++) {
                int n0;
                if (IS_SWI) n0 = (ni < 2) ? (wn * 16 + ni * 8) : (64 + wn * 16 + (ni - 2) * 8);
                else        n0 = wn * 32 + ni * 8;
                bf[ni][0] = Bw[cur][t * BWS + n0 + g];
                bf[ni][1] = Bw[cur][(t + 4) * BWS + n0 + g];
            }
#pragma unroll
            for (int mi = 0; mi < 4; mi++)
#pragma unroll
                for (int ni = 0; ni < 4; ni++)
                    mma_f16(acc[mi][ni], af[mi], bf[ni]);
        }
        if (c + 1 < NC) sts(cur ^ 1);
        __syncthreads();
    }

    // ---------------- epilogue ----------------
    if (MODE == 0 || MODE == 1) {
#pragma unroll
        for (int mi = 0; mi < 4; mi++) {
            int r = row0 + wm * 64 + mi * 16 + g;
#pragma unroll
            for (int ni = 0; ni < 4; ni++) {
                int col = bx * 128 + wn * 32 + ni * 8 + 2 * t;
                float2 v0 = make_float2(acc[mi][ni][0], acc[mi][ni][1]);
                float2 v1 = make_float2(acc[mi][ni][2], acc[mi][ni][3]);
                if (MODE == 1) {
                    float2 d0 = *(const float2*)(Dadd + (size_t)r * ldc + col);
                    float2 d1 = *(const float2*)(Dadd + (size_t)(r + 8) * ldc + col);
                    v0.x += d0.x; v0.y += d0.y; v1.x += d1.x; v1.y += d1.y;
                }
                *(float2*)(outp + (size_t)r * ldc + col) = v0;
                *(float2*)(outp + (size_t)(r + 8) * ldc + col) = v1;
            }
        }
    } else if (IS_SWI) {
#pragma unroll
        for (int mi = 0; mi < 4; mi++) {
            int r = row0 + wm * 64 + mi * 16 + g;
#pragma unroll
            for (int ni = 0; ni < 2; ni++) {
                int col = bx * 64 + wn * 16 + ni * 8 + 2 * t;
#pragma unroll
                for (int h = 0; h < 2; h++) {
                    int rg = r + 8 * h;
                    if (MODE == 3 && rg >= cnt) continue;
                    float gg0 = acc[mi][ni][2 * h + 0], gg1 = acc[mi][ni][2 * h + 1];
                    float uu0 = acc[mi][ni + 2][2 * h + 0], uu1 = acc[mi][ni + 2][2 * h + 1];
                    float s0 = 1.f / (1.f + __expf(-uu0));
                    float s1 = 1.f / (1.f + __expf(-uu1));
                    float2 v = make_float2(gg0 * uu0 * s0, gg1 * uu1 * s1);
                    *(float2*)(outp + (size_t)rg * I_ + col) = v;
                }
            }
        }
    } else {  // MODE 4
#pragma unroll
        for (int mi = 0; mi < 4; mi++) {
            int rl = wm * 64 + mi * 16 + g;
#pragma unroll
            for (int h = 0; h < 2; h++) {
                int rr = rl + 8 * h;
                if (row0 + rr >= cnt) continue;
                int tok = toks_s[rr];
                float wv = ws_s[rr];
#pragma unroll
                for (int ni = 0; ni < 4; ni++) {
                    int col = bx * 128 + wn * 32 + ni * 8 + 2 * t;
                    atomicAdd(out + (size_t)tok * H_ + col,     acc[mi][ni][2 * h + 0] * wv);
                    atomicAdd(out + (size_t)tok * H_ + col + 1, acc[mi][ni][2 * h + 1] * wv);
                }
            }
        }
    }
}

// ---------------- small-M (32-row) fp16 expert mma kernel for overflow slots ----------
// 8 warps 1x8 over N. MODE 3: swiglu gather; MODE 4: down + scatter. row0 = 128 + by*32.
template<int MODE>
__global__ void __launch_bounds__(256, 2) mma_gemm_s(
    const float* __restrict__ A, int lda,
    const float* __restrict__ B, int ldb,
    float* __restrict__ out, int Kdim,
    const int* __restrict__ etok, const float* __restrict__ ew,
    const int* __restrict__ ecnt) {
    constexpr bool IS_SWI = (MODE == 3);

    int e = blockIdx.z;
    int cnt = ecnt[e];
    int row0 = 128 + blockIdx.y * 32;
    if (row0 >= cnt) return;
    int bx = blockIdx.x;

    __shared__ uint32_t Aw[2][32 * AWS];
    __shared__ uint32_t Bw[2][8 * BWS];
    __shared__ int   toks_s[32];
    __shared__ float ws_s[32];

    int tid = threadIdx.x;
    int wid = tid >> 5;
    int lane = tid & 31;
    int g = lane >> 2, t = lane & 3;
    int wn = wid;

    const float* Ab = A;
    const float* Bb = B;
    float* outp = out;
    if (MODE == 3) { Bb = B + (size_t)e * H_ * 2 * I_; outp = out + (size_t)e * CAP_ * I_; }
    if (MODE == 4) { Ab = A + (size_t)e * CAP_ * I_; Bb = B + (size_t)e * I_ * H_; }

    if (tid < 32) {
        int rr = row0 + tid;
        bool v = rr < cnt;
        toks_s[tid] = v ? etok[e * CAP_ + rr] : 0;
        ws_s[tid]   = v ? ew[e * CAP_ + rr] : 0.f;
    }
    __syncthreads();

    // A: 1 float4 task for tid<128: row = tid>>2, q = tid&3
    const float* arow_ptr = nullptr;
    int aq = 0;
    if (tid < 128) {
        int r = tid >> 2; aq = (tid & 3) * 4;
        if (MODE == 3) arow_ptr = A + (size_t)toks_s[r] * lda;
        else           arow_ptr = Ab + (size_t)(row0 + r) * lda;
    }
    int kp = tid >> 5, nq = tid & 31;
    int bcol;
    if (IS_SWI) bcol = (nq < 16) ? (bx * 64 + nq * 4) : (I_ + bx * 64 + (nq - 16) * 4);
    else        bcol = bx * 128 + nq * 4;
    const float* b_even = Bb + (size_t)(2 * kp) * ldb + bcol;
    const float* b_odd  = Bb + (size_t)(2 * kp + 1) * ldb + bcol;

    float4 aR, bE, bO;
    auto ldg = [&](int kt) {
        if (tid < 128) aR = *(const float4*)(arow_ptr + kt + aq);
        bE = *(const float4*)(b_even + (size_t)kt * ldb);
        bO = *(const float4*)(b_odd  + (size_t)kt * ldb);
    };
    auto sts = [&](int buf) {
        if (tid < 128) {
            int r = tid >> 2, q = tid & 3;
            uint2 w;
            w.x = pack_f16(aR.x, aR.y);
            w.y = pack_f16(aR.z, aR.w);
            *(uint2*)&Aw[buf][r * AWS + 2 * q] = w;
        }
        uint4 wb;
        wb.x = pack_f16(bE.x, bO.x);
        wb.y = pack_f16(bE.y, bO.y);
        wb.z = pack_f16(bE.z, bO.z);
        wb.w = pack_f16(bE.w, bO.w);
        *(uint4*)&Bw[buf][kp * BWS + nq * 4] = wb;
    };

    float acc[2][2][4];
#pragma unroll
    for (int mi = 0; mi < 2; mi++)
#pragma unroll
        for (int ni = 0; ni < 2; ni++)
#pragma unroll
            for (int p = 0; p < 4; p++) acc[mi][ni][p] = 0.f;

    ldg(0); sts(0);
    __syncthreads();

    int NC = Kdim / 16;
    for (int c = 0; c < NC; c++) {
        int cur = c & 1;
        if (c + 1 < NC) ldg((c + 1) * 16);
        {
            uint32_t af[2][4], bf[2][2];
#pragma unroll
            for (int mi = 0; mi < 2; mi++) {
                int base = (mi * 16 + g) * AWS;
                af[mi][0] = Aw[cur][base + t];
                af[mi][1] = Aw[cur][base + 8 * AWS + t];
                af[mi][2] = Aw[cur][base + t + 4];
                af[mi][3] = Aw[cur][base + 8 * AWS + t + 4];
            }
#pragma unroll
            for (int ni = 0; ni < 2; ni++) {
                int n0;
                if (IS_SWI) n0 = (ni == 0) ? (wn * 8) : (64 + wn * 8);
                else        n0 = wn * 16 + ni * 8;
                bf[ni][0] = Bw[cur][t * BWS + n0 + g];
                bf[ni][1] = Bw[cur][(t + 4) * BWS + n0 + g];
            }
#pragma unroll
            for (int mi = 0; mi < 2; mi++)
#pragma unroll
                for (int ni = 0; ni < 2; ni++)
                    mma_f16(acc[mi][ni], af[mi], bf[ni]);
        }
        if (c + 1 < NC) sts(cur ^ 1);
        __syncthreads();
    }

    if (MODE == 3) {
#pragma unroll
        for (int mi = 0; mi < 2; mi++) {
            int col = bx * 64 + wn * 8 + 2 * t;
#pragma unroll
            for (int h = 0; h < 2; h++) {
                int rl = mi * 16 + g + 8 * h;
                int rg = row0 + rl;
                if (rg >= cnt) continue;
                float gg0 = acc[mi][0][2 * h + 0], gg1 = acc[mi][0][2 * h + 1];
                float uu0 = acc[mi][1][2 * h + 0], uu1 = acc[mi][1][2 * h + 1];
                float s0 = 1.f / (1.f + __expf(-uu0));
                float s1 = 1.f / (1.f + __expf(-uu1));
                float2 v = make_float2(gg0 * uu0 * s0, gg1 * uu1 * s1);
                *(float2*)(outp + (size_t)rg * I_ + col) = v;
            }
        }
    } else {  // MODE 4
#pragma unroll
        for (int mi = 0; mi < 2; mi++) {
#pragma unroll
            for (int h = 0; h < 2; h++) {
                int rl = mi * 16 + g + 8 * h;
                if (row0 + rl >= cnt) continue;
                int tok = toks_s[rl];
                float wv = ws_s[rl];
#pragma unroll
                for (int ni = 0; ni < 2; ni++) {
                    int col = bx * 128 + wn * 16 + ni * 8 + 2 * t;
                    atomicAdd(out + (size_t)tok * H_ + col,     acc[mi][ni][2 * h + 0] * wv);
                    atomicAdd(out + (size_t)tok * H_ + col + 1, acc[mi][ni][2 * h + 1] * wv);
                }
            }
        }
    }
}

// ---------------- RMSNorm ----------------
__global__ void rmsnorm_kernel(const float* __restrict__ in, const float* __restrict__ w,
                               float* __restrict__ out) {
    int row = blockIdx.x, tid = threadIdx.x;
    const float* x = in + (size_t)row * H_;
    float s = 0.f;
    for (int i = tid; i < H_; i += 256) { float v = x[i]; s += v * v; }
    __shared__ float red[256];
    red[tid] = s; __syncthreads();
    for (int o = 128; o > 0; o >>= 1) { if (tid < o) red[tid] += red[tid + o]; __syncthreads(); }
    float sc = rsqrtf(red[0] * (1.f / H_) + 1e-6f);
    for (int i = tid; i < H_; i += 256) out[(size_t)row * H_ + i] = x[i] * sc * w[i];
}

// ---------------- QKV postprocess ----------------
__global__ void qkvproc_kernel(const float* __restrict__ qkv, const float* __restrict__ cosb,
                               const float* __restrict__ sinb, const float* __restrict__ qnw,
                               const float* __restrict__ knw, float* __restrict__ q,
                               float* __restrict__ k, float* __restrict__ v) {
    int s = blockIdx.x, tid = threadIdx.x;
    int w = tid >> 5, lane = tid & 31;
#pragma unroll
    for (int p = 0; p < 4; p++) {
        int r = w + 8 * p;
        int kv = r >> 2, slot = r & 3;
        int base = s * QKVN_ + kv * 256 + slot * 64;
        int d0 = lane * 2, d1 = d0 + 1;
        float x0 = qkv[base + d0], x1 = qkv[base + d1];
        float y0, y1;
        if (slot == 3) { y0 = x0; y1 = x1; }
        else {
            float p0 = __shfl_xor_sync(0xffffffffu, x0, 16);
            float p1 = __shfl_xor_sync(0xffffffffu, x1, 16);
            float rh0 = (lane < 16) ? -p0 : p0;
            float rh1 = (lane < 16) ? -p1 : p1;
            float c0 = cosb[s * HD_ + d0], s0 = sinb[s * HD_ + d0];
            float c1 = cosb[s * HD_ + d1], s1 = sinb[s * HD_ + d1];
            y0 = x0 * c0 + rh0 * s0;
            y1 = x1 * c1 + rh1 * s1;
            float ss = y0 * y0 + y1 * y1;
            for (int off = 16; off > 0; off >>= 1) ss += __shfl_xor_sync(0xffffffffu, ss, off);
            float scn = rsqrtf(ss * (1.f / HD_) + 1e-6f);
            const float* wn = (slot < 2) ? qnw : knw;
            y0 = y0 * scn * wn[d0];
            y1 = y1 * scn * wn[d1];
        }
        if (slot < 2) {
            int hh = kv * 2 + slot;
            size_t off = ((size_t)hh * S_ + s) * HD_;
            q[off + d0] = y0; q[off + d1] = y1;
        } else if (slot == 2) {
            size_t off = ((size_t)kv * S_ + s) * HD_;
            k[off + d0] = y0; k[off + d1] = y1;
        } else {
            size_t off = ((size_t)kv * S_ + s) * HD_;
            v[off + d0] = y0; v[off + d1] = y1;
        }
    }
}

// ---------------- flash attention ----------------
__global__ void attn_kernel(const float* __restrict__ qg, const float* __restrict__ kg,
                            const float* __restrict__ vg, float* __restrict__ attn) {
    int qt = blockIdx.x, h = blockIdx.y;
    int q0 = qt * 64;
    const float* Q = qg + ((size_t)h * S_ + q0) * HD_;
    const float* Kp = kg + ((size_t)(h >> 1) * S_) * HD_;
    const float* Vp = vg + ((size_t)(h >> 1) * S_) * HD_;
    __shared__ float Qs[64][65];
    __shared__ float U[64][33];
    __shared__ float Vs[32][64];
    int tid = threadIdx.x;
    int ty = tid >> 4, tx = tid & 15;
    {
        int d = tid & 63, r0 = (tid >> 6) * 16;
#pragma unroll
        for (int qq = 0; qq < 16; qq++) Qs[r0 + qq][d] = Q[(size_t)(r0 + qq) * HD_ + d];
    }
    float o[4][4]; float m[4], l[4];
#pragma unroll
    for (int i = 0; i < 4; i++) {
        m[i] = -1e30f; l[i] = 0.f;
#pragma unroll
        for (int j = 0; j < 4; j++) o[i][j] = 0.f;
    }
    int nkt = (q0 + 64) / 32;
    for (int kt = 0; kt < nkt; kt++) {
        int k0 = kt * 32;
        {
            int d = tid & 63, kgp = tid >> 6;
#pragma unroll
            for (int qq = 0; qq < 8; qq++) {
                int key = kgp * 8 + qq;
                U[d][key]  = Kp[(size_t)(k0 + key) * HD_ + d];
                Vs[key][d] = Vp[(size_t)(k0 + key) * HD_ + d];
            }
        }
        __syncthreads();
        float sc[4][2];
#pragma unroll
        for (int i = 0; i < 4; i++) { sc[i][0] = 0.f; sc[i][1] = 0.f; }
        for (int d = 0; d < 64; d++) {
            float qv[4], kv[2];
#pragma unroll
            for (int i = 0; i < 4; i++) qv[i] = Qs[ty * 4 + i][d];
#pragma unroll
            for (int j = 0; j < 2; j++) kv[j] = U[d][tx * 2 + j];
#pragma unroll
            for (int i = 0; i < 4; i++)
#pragma unroll
                for (int j = 0; j < 2; j++) sc[i][j] = fmaf(qv[i], kv[j], sc[i][j]);
        }
        __syncthreads();
        float pr[4][2];
#pragma unroll
        for (int i = 0; i < 4; i++) {
            int qrow = q0 + ty * 4 + i;
            float mi = -1e30f;
            bool msk[2];
#pragma unroll
            for (int j = 0; j < 2; j++) {
                int kc = k0 + tx * 2 + j;
                msk[j] = (kc > qrow);
                float vv = msk[j] ? -1e30f : sc[i][j] * 0.125f;
                sc[i][j] = vv;
                mi = fmaxf(mi, vv);
            }
            for (int off = 8; off > 0; off >>= 1) mi = fmaxf(mi, __shfl_xor_sync(0xffffffffu, mi, off));
            float mn = fmaxf(m[i], mi);
            float corr = __expf(m[i] - mn);
            float rs = 0.f;
#pragma unroll
            for (int j = 0; j < 2; j++) {
                pr[i][j] = msk[j] ? 0.f : __expf(sc[i][j] - mn);
                rs += pr[i][j];
            }
            for (int off = 8; off > 0; off >>= 1) rs += __shfl_xor_sync(0xffffffffu, rs, off);
            l[i] = l[i] * corr + rs;
            m[i] = mn;
#pragma unroll
            for (int jj = 0; jj < 4; jj++) o[i][jj] *= corr;
        }
#pragma unroll
        for (int i = 0; i < 4; i++)
#pragma unroll
            for (int j = 0; j < 2; j++) U[ty * 4 + i][tx * 2 + j] = pr[i][j];
        __syncthreads();
        for (int k = 0; k < 32; k++) {
            float pv[4], vv[4];
#pragma unroll
            for (int i = 0; i < 4; i++) pv[i] = U[ty * 4 + i][k];
#pragma unroll
            for (int jj = 0; jj < 4; jj++) vv[jj] = Vs[k][tx * 4 + jj];
#pragma unroll
            for (int i = 0; i < 4; i++)
#pragma unroll
                for (int jj = 0; jj < 4; jj++) o[i][jj] = fmaf(pv[i], vv[jj], o[i][jj]);
        }
        __syncthreads();
    }
#pragma unroll
    for (int i = 0; i < 4; i++) {
        float inv = 1.f / l[i];
#pragma unroll
        for (int jj = 0; jj < 4; jj++)
            attn[(size_t)(q0 + ty * 4 + i) * H_ + h * HD_ + tx * 4 + jj] = o[i][jj] * inv;
    }
}

// ---------------- gate + top-8 ----------------
__global__ void gate_topk_kernel(const float* __restrict__ x2, const float* __restrict__ Wg,
                                 float* __restrict__ w8, int* __restrict__ idx8) {
    int tt = blockIdx.x, tid = threadIdx.x;
    const float* xr = x2 + (size_t)tt * H_;
    float a0 = 0.f, a1 = 0.f, a2 = 0.f, a3 = 0.f;
    for (int h = 0; h < H_; h += 4) {
        a0 = fmaf(xr[h],     Wg[(size_t)h * E_ + tid],       a0);
        a1 = fmaf(xr[h + 1], Wg[(size_t)(h + 1) * E_ + tid], a1);
        a2 = fmaf(xr[h + 2], Wg[(size_t)(h + 2) * E_ + tid], a2);
        a3 = fmaf(xr[h + 3], Wg[(size_t)(h + 3) * E_ + tid], a3);
    }
    float logit = (a0 + a1) + (a2 + a3);
    __shared__ float red[64];
    __shared__ float gv[64];
    red[tid] = logit; __syncthreads();
    for (int o = 32; o > 0; o >>= 1) { if (tid < o) red[tid] = fmaxf(red[tid], red[tid + o]); __syncthreads(); }
    float mx = red[0]; __syncthreads();
    float ex = __expf(logit - mx);
    red[tid] = ex; __syncthreads();
    for (int o = 32; o > 0; o >>= 1) { if (tid < o) red[tid] += red[tid + o]; __syncthreads(); }
    float sum = red[0];
    gv[tid] = ex / sum; __syncthreads();
    if (tid == 0) {
        bool used[E_];
        for (int e = 0; e < E_; e++) used[e] = false;
        float wv[TOPK_]; int id[TOPK_]; float wsum = 0.f;
        for (int r = 0; r < TOPK_; r++) {
            int best = 0; float bv = -1e30f;
            for (int e = 0; e < E_; e++)
                if (!used[e] && gv[e] > bv) { bv = gv[e]; best = e; }
            used[best] = true; wv[r] = bv; id[r] = best; wsum += bv;
        }
        wsum = fmaxf(wsum, 1.1920929e-07f);
        for (int r = 0; r < TOPK_; r++) {
            w8[tt * TOPK_ + r] = wv[r] / wsum;
            idx8[tt * TOPK_ + r] = id[r];
        }
    }
}

// ---------------- routing ----------------
__global__ void route_kernel(const int* __restrict__ idx8, const float* __restrict__ w8,
                             int* __restrict__ etok, float* __restrict__ ew, int* __restrict__ ecnt) {
    int e = blockIdx.x, lane = threadIdx.x;
    int cnt = 0;
    for (int base = 0; base < S_ * TOPK_; base += 32) {
        int j = base + lane;
        int ee = idx8[j];
        bool match = (ee == e);
        unsigned bal = __ballot_sync(0xffffffffu, match);
        int pre = __popc(bal & ((1u << lane) - 1u));
        if (match) {
            int p = cnt + pre;
            if (p < CAP_) {
                etok[e * CAP_ + p] = j >> 3;
                ew[e * CAP_ + p] = w8[j];
            }
        }
        cnt += __popc(bal);
    }
    if (lane == 0) ecnt[e] = (cnt < CAP_) ? cnt : CAP_;
}

// ---------------- launch ----------------
extern "C" void kernel_launch(void* const* d_in, const int* in_sizes, int n_in,
                              void* d_out, int out_size) {
    (void)in_sizes; (void)n_in; (void)out_size;
    const float* hidden = (const float*)d_in[0];
    const float* cosb   = (const float*)d_in[1];
    const float* sinb   = (const float*)d_in[2];
    const float* ln1    = (const float*)d_in[3];
    const float* ln2    = (const float*)d_in[4];
    const float* Wqkv   = (const float*)d_in[5];
    const float* Wo     = (const float*)d_in[6];
    const float* qnw    = (const float*)d_in[7];
    const float* knw    = (const float*)d_in[8];
    const float* Wgu_sh = (const float*)d_in[9];
    const float* Wd_sh  = (const float*)d_in[10];
    const float* Wgate  = (const float*)d_in[11];
    const float* Wgu_e  = (const float*)d_in[12];
    const float* Wd_e   = (const float*)d_in[13];
    float* out = (float*)d_out;

    float* fb = nullptr; int* ib = nullptr;
    cudaGetSymbolAddress((void**)&fb, g_fbuf);
    cudaGetSymbolAddress((void**)&ib, g_ibuf);

    float* x      = fb + OFF_X;
    float* qkv    = fb + OFF_QKV;
    float* q      = fb + OFF_Q;
    float* k      = fb + OFF_K;
    float* v      = fb + OFF_V;
    float* attn   = fb + OFF_ATTN;
    float* h1     = fb + OFF_H1;
    float* x2     = fb + OFF_X2;
    float* actsh  = fb + OFF_ACTSH;
    float* w8     = fb + OFF_W8;
    float* expw   = fb + OFF_EXPW;
    float* actexp = fb + OFF_ACTEXP;
    int* idx8   = ib + IOFF_IDX8;
    int* exptok = ib + IOFF_EXPTOK;
    int* expcnt = ib + IOFF_EXPCNT;

    // 1. x = rmsnorm(hidden, ln1)
    rmsnorm_kernel<<<S_, 256>>>(hidden, ln1, x);
    // 2. qkv = x @ Wqkv
    mma_gemm<0><<<dim3(QKVN_ / 128, S_ / 128), 256>>>(
        x, H_, Wqkv, QKVN_, nullptr, qkv, QKVN_, H_, nullptr, nullptr, nullptr);
    // 3. RoPE + QK-norm
    qkvproc_kernel<<<S_, 256>>>(qkv, cosb, sinb, qnw, knw, q, k, v);
    // 4. attention
    attn_kernel<<<dim3(S_ / 64, NH_), 256>>>(q, k, v, attn);
    // 5. h1 = attn @ Wo + hidden
    mma_gemm<1><<<dim3(H_ / 128, S_ / 128), 256>>>(
        attn, H_, Wo, H_, hidden, h1, H_, H_, nullptr, nullptr, nullptr);
    // 6. x2 = rmsnorm(h1, ln2)
    rmsnorm_kernel<<<S_, 256>>>(h1, ln2, x2);
    // 7. shared swiglu activation
    mma_gemm<2><<<dim3(I_ / 64, S_ / 128), 256>>>(
        x2, H_, Wgu_sh, 2 * I_, nullptr, actsh, I_, H_, nullptr, nullptr, nullptr);
    // 8. out = actsh @ Wd_sh + h1
    mma_gemm<1><<<dim3(H_ / 128, S_ / 128), 256>>>(
        actsh, I_, Wd_sh, H_, h1, out, H_, I_, nullptr, nullptr, nullptr);
    // 9. gate + top-8
    gate_topk_kernel<<<S_, 64>>>(x2, Wgate, w8, idx8);
    // 10. routing
    route_kernel<<<E_, 32>>>(idx8, w8, exptok, expw, expcnt);
    // 11a. expert swiglu, slots 0-127 (128-row mma)
    mma_gemm<3><<<dim3(I_ / 64, 1, E_), 256>>>(
        x2, H_, Wgu_e, 2 * I_, nullptr, actexp, I_, H_, exptok, nullptr, expcnt);
    // 11b. expert swiglu overflow slots 128..511 (32-row mma, early-exit)
    mma_gemm_s<3><<<dim3(I_ / 64, 12, E_), 256>>>(
        x2, H_, Wgu_e, 2 * I_, actexp, H_, exptok, nullptr, expcnt);
    // 12a. expert down + scatter, slots 0-127 (128-row mma)
    mma_gemm<4><<<dim3(H_ / 128, 1, E_), 256>>>(
        actexp, I_, Wd_e, H_, nullptr, out, H_, I_, exptok, expw, expcnt);
    // 12b. expert down overflow slots 128..511 (32-row mma, early-exit)
    mma_gemm_s<4><<<dim3(H_ / 128, 12, E_), 256>>>(
        actexp, I_, Wd_e, H_, out, I_, exptok, expw, expcnt);
}

// round 13
// speedup vs baseline: 1.9730x; 1.0468x over previous
#include <cuda_runtime.h>
#include <cstddef>
#include <cstdint>

#define S_    1024
#define H_    1024
#define HD_   64
#define NH_   16
#define KVH_  8
#define E_    64
#define TOPK_ 8
#define CAP_  512
#define I_    3072
#define QKVN_ 2048

// ---------------- static scratch ----------------
static const size_t OFF_X      = 0;
static const size_t OFF_QKV    = 1048576;
static const size_t OFF_Q      = 3145728;
static const size_t OFF_K      = 4194304;
static const size_t OFF_V      = 4718592;
static const size_t OFF_ATTN   = 5242880;
static const size_t OFF_H1     = 6291456;
static const size_t OFF_X2     = 7340032;
static const size_t OFF_ACTSH  = 8388608;
static const size_t OFF_W8     = 11599872;
static const size_t OFF_EXPW   = 11608064;
static const size_t OFF_ACTEXP = 11640832;
static const size_t FBUF_TOT   = 112304128;

static const size_t IOFF_IDX8   = 0;
static const size_t IOFF_EXPTOK = 8192;
static const size_t IOFF_EXPCNT = 40960;

__device__ float g_fbuf[FBUF_TOT];
__device__ int   g_ibuf[41028];

// pack two fp32 -> f16x2 word, round-to-nearest-even; lo = first arg
__device__ __forceinline__ uint32_t pack_f16(float lo, float hi) {
    uint32_t r;
    asm("cvt.rn.f16x2.f32 %0, %1, %2;" : "=r"(r) : "f"(hi), "f"(lo));
    return r;
}

__device__ __forceinline__ void mma_f16(float* c, const uint32_t* a, const uint32_t* b) {
    asm volatile(
        "mma.sync.aligned.m16n8k16.row.col.f32.f16.f16.f32 "
        "{%0,%1,%2,%3}, {%4,%5,%6,%7}, {%8,%9}, {%0,%1,%2,%3};"
        : "+f"(c[0]), "+f"(c[1]), "+f"(c[2]), "+f"(c[3])
        : "r"(a[0]), "r"(a[1]), "r"(a[2]), "r"(a[3]), "r"(b[0]), "r"(b[1]));
}

// ---------------- fp16 mma.sync GEMM (128x128, 2x4 warps, 2 CTA/SM) ----------------
#define AWS 12
#define BWS 132

template<int MODE>
__global__ void __launch_bounds__(256, 2) mma_gemm(
    const float* __restrict__ A, int lda,
    const float* __restrict__ B, int ldb,
    const float* __restrict__ Dadd,
    float* __restrict__ out, int ldc, int Kdim,
    const int* __restrict__ etok, const float* __restrict__ ew,
    const int* __restrict__ ecnt) {
    constexpr bool IS_SWI = (MODE == 2 || MODE == 3);
    constexpr bool IS_EXP = (MODE == 3 || MODE == 4);

    int e = IS_EXP ? blockIdx.z : 0;
    int cnt = IS_EXP ? ecnt[e] : S_;
    if (IS_EXP) { int mx = 128 * gridDim.y; cnt = (cnt < mx) ? cnt : mx; }
    int row0 = blockIdx.y * 128;
    if (IS_EXP && row0 >= cnt) return;
    int bx = blockIdx.x;

    __shared__ uint32_t Aw[2][128 * AWS];
    __shared__ uint32_t Bw[2][8 * BWS];
    __shared__ int   toks_s[128];
    __shared__ float ws_s[128];

    int tid = threadIdx.x;
    int wid = tid >> 5;
    int lane = tid & 31;
    int g = lane >> 2, t = lane & 3;
    int wm = wid & 1, wn = wid >> 1;

    const float* Ab = A;
    const float* Bb = B;
    float* outp = out;
    if (MODE == 3) { Bb = B + (size_t)e * H_ * 2 * I_; outp = out + (size_t)e * CAP_ * I_; }
    if (MODE == 4) { Ab = A + (size_t)e * CAP_ * I_; Bb = B + (size_t)e * I_ * H_; }

    if (IS_EXP && tid < 128) {
        int rr = row0 + tid;
        bool v = rr < cnt;
        toks_s[tid] = v ? etok[e * CAP_ + rr] : 0;
        ws_s[tid]   = v ? ew[e * CAP_ + rr] : 0.f;
    }
    if (IS_EXP) __syncthreads();

    const float* arow_ptr[2];
    int aq[2];
#pragma unroll
    for (int s = 0; s < 2; s++) {
        int f4 = tid + 256 * s;
        int r = f4 >> 2; aq[s] = (f4 & 3) * 4;
        if (MODE == 3) arow_ptr[s] = A + (size_t)toks_s[r] * lda;
        else           arow_ptr[s] = Ab + (size_t)(row0 + r) * lda;
    }
    int kp = tid >> 5, nq = tid & 31;
    int bcol;
    if (IS_SWI) bcol = (nq < 16) ? (bx * 64 + nq * 4) : (I_ + bx * 64 + (nq - 16) * 4);
    else        bcol = bx * 128 + nq * 4;
    const float* b_even = Bb + (size_t)(2 * kp) * ldb + bcol;
    const float* b_odd  = Bb + (size_t)(2 * kp + 1) * ldb + bcol;

    float4 aR[2], bE, bO;
    auto ldg = [&](int kt) {
#pragma unroll
        for (int s = 0; s < 2; s++) aR[s] = *(const float4*)(arow_ptr[s] + kt + aq[s]);
        bE = *(const float4*)(b_even + (size_t)kt * ldb);
        bO = *(const float4*)(b_odd  + (size_t)kt * ldb);
    };
    auto sts = [&](int buf) {
#pragma unroll
        for (int s = 0; s < 2; s++) {
            int f4 = tid + 256 * s;
            int r = f4 >> 2, q = f4 & 3;
            uint2 w;
            w.x = pack_f16(aR[s].x, aR[s].y);
            w.y = pack_f16(aR[s].z, aR[s].w);
            *(uint2*)&Aw[buf][r * AWS + 2 * q] = w;
        }
        uint4 wb;
        wb.x = pack_f16(bE.x, bO.x);
        wb.y = pack_f16(bE.y, bO.y);
        wb.z = pack_f16(bE.z, bO.z);
        wb.w = pack_f16(bE.w, bO.w);
        *(uint4*)&Bw[buf][kp * BWS + nq * 4] = wb;
    };

    float acc[4][4][4];
#pragma unroll
    for (int mi = 0; mi < 4; mi++)
#pragma unroll
        for (int ni = 0; ni < 4; ni++)
#pragma unroll
            for (int p = 0; p < 4; p++) acc[mi][ni][p] = 0.f;

    ldg(0); sts(0);
    __syncthreads();

    int NC = Kdim / 16;
    for (int c = 0; c < NC; c++) {
        int cur = c & 1;
        if (c + 1 < NC) ldg((c + 1) * 16);
        {
            uint32_t af[4][4], bf[4][2];
#pragma unroll
            for (int mi = 0; mi < 4; mi++) {
                int base = (wm * 64 + mi * 16 + g) * AWS;
                af[mi][0] = Aw[cur][base + t];
                af[mi][1] = Aw[cur][base + 8 * AWS + t];
                af[mi][2] = Aw[cur][base + t + 4];
                af[mi][3] = Aw[cur][base + 8 * AWS + t + 4];
            }
#pragma unroll
            for (int ni = 0; ni < 4; ni++) {
                int n0;
                if (IS_SWI) n0 = (ni < 2) ? (wn * 16 + ni * 8) : (64 + wn * 16 + (ni - 2) * 8);
                else        n0 = wn * 32 + ni * 8;
                bf[ni][0] = Bw[cur][t * BWS + n0 + g];
                bf[ni][1] = Bw[cur][(t + 4) * BWS + n0 + g];
            }
#pragma unroll
            for (int mi = 0; mi < 4; mi++)
#pragma unroll
                for (int ni = 0; ni < 4; ni++)
                    mma_f16(acc[mi][ni], af[mi], bf[ni]);
        }
        if (c + 1 < NC) sts(cur ^ 1);
        __syncthreads();
    }

    if (MODE == 0 || MODE == 1) {
#pragma unroll
        for (int mi = 0; mi < 4; mi++) {
            int r = row0 + wm * 64 + mi * 16 + g;
#pragma unroll
            for (int ni = 0; ni < 4; ni++) {
                int col = bx * 128 + wn * 32 + ni * 8 + 2 * t;
                float2 v0 = make_float2(acc[mi][ni][0], acc[mi][ni][1]);
                float2 v1 = make_float2(acc[mi][ni][2], acc[mi][ni][3]);
                if (MODE == 1) {
                    float2 d0 = *(const float2*)(Dadd + (size_t)r * ldc + col);
                    float2 d1 = *(const float2*)(Dadd + (size_t)(r + 8) * ldc + col);
                    v0.x += d0.x; v0.y += d0.y; v1.x += d1.x; v1.y += d1.y;
                }
                *(float2*)(outp + (size_t)r * ldc + col) = v0;
                *(float2*)(outp + (size_t)(r + 8) * ldc + col) = v1;
            }
        }
    } else if (IS_SWI) {
#pragma unroll
        for (int mi = 0; mi < 4; mi++) {
            int r = row0 + wm * 64 + mi * 16 + g;
#pragma unroll
            for (int ni = 0; ni < 2; ni++) {
                int col = bx * 64 + wn * 16 + ni * 8 + 2 * t;
#pragma unroll
                for (int h = 0; h < 2; h++) {
                    int rg = r + 8 * h;
                    if (MODE == 3 && rg >= cnt) continue;
                    float gg0 = acc[mi][ni][2 * h + 0], gg1 = acc[mi][ni][2 * h + 1];
                    float uu0 = acc[mi][ni + 2][2 * h + 0], uu1 = acc[mi][ni + 2][2 * h + 1];
                    float s0 = 1.f / (1.f + __expf(-uu0));
                    float s1 = 1.f / (1.f + __expf(-uu1));
                    float2 v = make_float2(gg0 * uu0 * s0, gg1 * uu1 * s1);
                    *(float2*)(outp + (size_t)rg * I_ + col) = v;
                }
            }
        }
    } else {  // MODE 4
#pragma unroll
        for (int mi = 0; mi < 4; mi++) {
            int rl = wm * 64 + mi * 16 + g;
#pragma unroll
            for (int h = 0; h < 2; h++) {
                int rr = rl + 8 * h;
                if (row0 + rr >= cnt) continue;
                int tok = toks_s[rr];
                float wv = ws_s[rr];
#pragma unroll
                for (int ni = 0; ni < 4; ni++) {
                    int col = bx * 128 + wn * 32 + ni * 8 + 2 * t;
                    atomicAdd(out + (size_t)tok * H_ + col,     acc[mi][ni][2 * h + 0] * wv);
                    atomicAdd(out + (size_t)tok * H_ + col + 1, acc[mi][ni][2 * h + 1] * wv);
                }
            }
        }
    }
}

// ---------------- small-M (32-row) fp16 expert mma kernel for overflow slots ----------
template<int MODE>
__global__ void __launch_bounds__(256, 2) mma_gemm_s(
    const float* __restrict__ A, int lda,
    const float* __restrict__ B, int ldb,
    float* __restrict__ out, int Kdim,
    const int* __restrict__ etok, const float* __restrict__ ew,
    const int* __restrict__ ecnt) {
    constexpr bool IS_SWI = (MODE == 3);

    int e = blockIdx.z;
    int cnt = ecnt[e];
    int row0 = 128 + blockIdx.y * 32;
    if (row0 >= cnt) return;
    int bx = blockIdx.x;

    __shared__ uint32_t Aw[2][32 * AWS];
    __shared__ uint32_t Bw[2][8 * BWS];
    __shared__ int   toks_s[32];
    __shared__ float ws_s[32];

    int tid = threadIdx.x;
    int wid = tid >> 5;
    int lane = tid & 31;
    int g = lane >> 2, t = lane & 3;
    int wn = wid;

    const float* Ab = A;
    const float* Bb = B;
    float* outp = out;
    if (MODE == 3) { Bb = B + (size_t)e * H_ * 2 * I_; outp = out + (size_t)e * CAP_ * I_; }
    if (MODE == 4) { Ab = A + (size_t)e * CAP_ * I_; Bb = B + (size_t)e * I_ * H_; }

    if (tid < 32) {
        int rr = row0 + tid;
        bool v = rr < cnt;
        toks_s[tid] = v ? etok[e * CAP_ + rr] : 0;
        ws_s[tid]   = v ? ew[e * CAP_ + rr] : 0.f;
    }
    __syncthreads();

    const float* arow_ptr = nullptr;
    int aq = 0;
    if (tid < 128) {
        int r = tid >> 2; aq = (tid & 3) * 4;
        if (MODE == 3) arow_ptr = A + (size_t)toks_s[r] * lda;
        else           arow_ptr = Ab + (size_t)(row0 + r) * lda;
    }
    int kp = tid >> 5, nq = tid & 31;
    int bcol;
    if (IS_SWI) bcol = (nq < 16) ? (bx * 64 + nq * 4) : (I_ + bx * 64 + (nq - 16) * 4);
    else        bcol = bx * 128 + nq * 4;
    const float* b_even = Bb + (size_t)(2 * kp) * ldb + bcol;
    const float* b_odd  = Bb + (size_t)(2 * kp + 1) * ldb + bcol;

    float4 aR, bE, bO;
    auto ldg = [&](int kt) {
        if (tid < 128) aR = *(const float4*)(arow_ptr + kt + aq);
        bE = *(const float4*)(b_even + (size_t)kt * ldb);
        bO = *(const float4*)(b_odd  + (size_t)kt * ldb);
    };
    auto sts = [&](int buf) {
        if (tid < 128) {
            int r = tid >> 2, q = tid & 3;
            uint2 w;
            w.x = pack_f16(aR.x, aR.y);
            w.y = pack_f16(aR.z, aR.w);
            *(uint2*)&Aw[buf][r * AWS + 2 * q] = w;
        }
        uint4 wb;
        wb.x = pack_f16(bE.x, bO.x);
        wb.y = pack_f16(bE.y, bO.y);
        wb.z = pack_f16(bE.z, bO.z);
        wb.w = pack_f16(bE.w, bO.w);
        *(uint4*)&Bw[buf][kp * BWS + nq * 4] = wb;
    };

    float acc[2][2][4];
#pragma unroll
    for (int mi = 0; mi < 2; mi++)
#pragma unroll
        for (int ni = 0; ni < 2; ni++)
#pragma unroll
            for (int p = 0; p < 4; p++) acc[mi][ni][p] = 0.f;

    ldg(0); sts(0);
    __syncthreads();

    int NC = Kdim / 16;
    for (int c = 0; c < NC; c++) {
        int cur = c & 1;
        if (c + 1 < NC) ldg((c + 1) * 16);
        {
            uint32_t af[2][4], bf[2][2];
#pragma unroll
            for (int mi = 0; mi < 2; mi++) {
                int base = (mi * 16 + g) * AWS;
                af[mi][0] = Aw[cur][base + t];
                af[mi][1] = Aw[cur][base + 8 * AWS + t];
                af[mi][2] = Aw[cur][base + t + 4];
                af[mi][3] = Aw[cur][base + 8 * AWS + t + 4];
            }
#pragma unroll
            for (int ni = 0; ni < 2; ni++) {
                int n0;
                if (IS_SWI) n0 = (ni == 0) ? (wn * 8) : (64 + wn * 8);
                else        n0 = wn * 16 + ni * 8;
                bf[ni][0] = Bw[cur][t * BWS + n0 + g];
                bf[ni][1] = Bw[cur][(t + 4) * BWS + n0 + g];
            }
#pragma unroll
            for (int mi = 0; mi < 2; mi++)
#pragma unroll
                for (int ni = 0; ni < 2; ni++)
                    mma_f16(acc[mi][ni], af[mi], bf[ni]);
        }
        if (c + 1 < NC) sts(cur ^ 1);
        __syncthreads();
    }

    if (MODE == 3) {
#pragma unroll
        for (int mi = 0; mi < 2; mi++) {
            int col = bx * 64 + wn * 8 + 2 * t;
#pragma unroll
            for (int h = 0; h < 2; h++) {
                int rl = mi * 16 + g + 8 * h;
                int rg = row0 + rl;
                if (rg >= cnt) continue;
                float gg0 = acc[mi][0][2 * h + 0], gg1 = acc[mi][0][2 * h + 1];
                float uu0 = acc[mi][1][2 * h + 0], uu1 = acc[mi][1][2 * h + 1];
                float s0 = 1.f / (1.f + __expf(-uu0));
                float s1 = 1.f / (1.f + __expf(-uu1));
                float2 v = make_float2(gg0 * uu0 * s0, gg1 * uu1 * s1);
                *(float2*)(outp + (size_t)rg * I_ + col) = v;
            }
        }
    } else {
#pragma unroll
        for (int mi = 0; mi < 2; mi++) {
#pragma unroll
            for (int h = 0; h < 2; h++) {
                int rl = mi * 16 + g + 8 * h;
                if (row0 + rl >= cnt) continue;
                int tok = toks_s[rl];
                float wv = ws_s[rl];
#pragma unroll
                for (int ni = 0; ni < 2; ni++) {
                    int col = bx * 128 + wn * 16 + ni * 8 + 2 * t;
                    atomicAdd(out + (size_t)tok * H_ + col,     acc[mi][ni][2 * h + 0] * wv);
                    atomicAdd(out + (size_t)tok * H_ + col + 1, acc[mi][ni][2 * h + 1] * wv);
                }
            }
        }
    }
}

// ---------------- RMSNorm ----------------
__global__ void rmsnorm_kernel(const float* __restrict__ in, const float* __restrict__ w,
                               float* __restrict__ out) {
    int row = blockIdx.x, tid = threadIdx.x;
    const float* x = in + (size_t)row * H_;
    float s = 0.f;
    for (int i = tid; i < H_; i += 256) { float v = x[i]; s += v * v; }
    __shared__ float red[256];
    red[tid] = s; __syncthreads();
    for (int o = 128; o > 0; o >>= 1) { if (tid < o) red[tid] += red[tid + o]; __syncthreads(); }
    float sc = rsqrtf(red[0] * (1.f / H_) + 1e-6f);
    for (int i = tid; i < H_; i += 256) out[(size_t)row * H_ + i] = x[i] * sc * w[i];
}

// ---------------- QKV postprocess ----------------
__global__ void qkvproc_kernel(const float* __restrict__ qkv, const float* __restrict__ cosb,
                               const float* __restrict__ sinb, const float* __restrict__ qnw,
                               const float* __restrict__ knw, float* __restrict__ q,
                               float* __restrict__ k, float* __restrict__ v) {
    int s = blockIdx.x, tid = threadIdx.x;
    int w = tid >> 5, lane = tid & 31;
#pragma unroll
    for (int p = 0; p < 4; p++) {
        int r = w + 8 * p;
        int kv = r >> 2, slot = r & 3;
        int base = s * QKVN_ + kv * 256 + slot * 64;
        int d0 = lane * 2, d1 = d0 + 1;
        float x0 = qkv[base + d0], x1 = qkv[base + d1];
        float y0, y1;
        if (slot == 3) { y0 = x0; y1 = x1; }
        else {
            float p0 = __shfl_xor_sync(0xffffffffu, x0, 16);
            float p1 = __shfl_xor_sync(0xffffffffu, x1, 16);
            float rh0 = (lane < 16) ? -p0 : p0;
            float rh1 = (lane < 16) ? -p1 : p1;
            float c0 = cosb[s * HD_ + d0], s0 = sinb[s * HD_ + d0];
            float c1 = cosb[s * HD_ + d1], s1 = sinb[s * HD_ + d1];
            y0 = x0 * c0 + rh0 * s0;
            y1 = x1 * c1 + rh1 * s1;
            float ss = y0 * y0 + y1 * y1;
            for (int off = 16; off > 0; off >>= 1) ss += __shfl_xor_sync(0xffffffffu, ss, off);
            float scn = rsqrtf(ss * (1.f / HD_) + 1e-6f);
            const float* wn = (slot < 2) ? qnw : knw;
            y0 = y0 * scn * wn[d0];
            y1 = y1 * scn * wn[d1];
        }
        if (slot < 2) {
            int hh = kv * 2 + slot;
            size_t off = ((size_t)hh * S_ + s) * HD_;
            q[off + d0] = y0; q[off + d1] = y1;
        } else if (slot == 2) {
            size_t off = ((size_t)kv * S_ + s) * HD_;
            k[off + d0] = y0; k[off + d1] = y1;
        } else {
            size_t off = ((size_t)kv * S_ + s) * HD_;
            v[off + d0] = y0; v[off + d1] = y1;
        }
    }
}

// ---------------- flash attention, fp16 mma (BQ=64, BK=32, 128 threads) ----------------
// Strides: AQW/KWS = 36 (even -> uint2 aligned; frag-load bank = 4g+t, conflict-free)
//          VWS = 72 (mult of 4 -> uint4 aligned; frag-load bank = 8t+g, conflict-free)
#define AQW 36
#define KWS 36
#define VWS 72

__global__ void __launch_bounds__(128) attn_kernel(const float* __restrict__ qg,
                                                   const float* __restrict__ kg,
                                                   const float* __restrict__ vg,
                                                   float* __restrict__ attn) {
    int qt = blockIdx.x, h = blockIdx.y;
    int q0 = qt * 64;
    const float* Q = qg + ((size_t)h * S_ + q0) * HD_;
    const float* Kp = kg + ((size_t)(h >> 1) * S_) * HD_;
    const float* Vp = vg + ((size_t)(h >> 1) * S_) * HD_;

    __shared__ uint32_t Qw[64 * AQW];
    __shared__ uint32_t Kw[32 * KWS];
    __shared__ uint32_t Vw[16 * VWS];

    int tid = threadIdx.x;
    int wid = tid >> 5;          // 0..3 -> 16 q-rows each
    int lane = tid & 31;
    int g = lane >> 2, t = lane & 3;
    int m0 = wid * 16;

    // load Q tile (fp32 -> fp16): 1024 float4 over 128 threads
    for (int i = tid; i < 1024; i += 128) {
        int row = i >> 4, qq = i & 15;
        float4 v = *(const float4*)(Q + (size_t)row * HD_ + qq * 4);
        uint2 w;
        w.x = pack_f16(v.x, v.y);
        w.y = pack_f16(v.z, v.w);
        *(uint2*)&Qw[row * AQW + qq * 2] = w;
    }

    float acc_o[8][4];
#pragma unroll
    for (int i = 0; i < 8; i++)
#pragma unroll
        for (int p = 0; p < 4; p++) acc_o[i][p] = 0.f;
    float m[2] = {-1e30f, -1e30f};
    float l[2] = {0.f, 0.f};

    int nkt = (q0 + 64) / 32;
    for (int kt = 0; kt < nkt; kt++) {
        int k0 = kt * 32;
        __syncthreads();   // previous iteration's Kw/Vw reads done (also covers Qw fill)
        // fill K: 512 float4
        for (int i = tid; i < 512; i += 128) {
            int key = i >> 4, qq = i & 15;
            float4 v = *(const float4*)(Kp + (size_t)(k0 + key) * HD_ + qq * 4);
            uint2 w;
            w.x = pack_f16(v.x, v.y);
            w.y = pack_f16(v.z, v.w);
            *(uint2*)&Kw[key * KWS + qq * 2] = w;
        }
        // fill V key-pair packed: 256 tasks (kp 0..15, d-group 0..15)
        for (int i = tid; i < 256; i += 128) {
            int kp = i >> 4, qq = i & 15;
            float4 ve = *(const float4*)(Vp + (size_t)(k0 + 2 * kp) * HD_ + qq * 4);
            float4 vo = *(const float4*)(Vp + (size_t)(k0 + 2 * kp + 1) * HD_ + qq * 4);
            uint4 w;
            w.x = pack_f16(ve.x, vo.x);
            w.y = pack_f16(ve.y, vo.y);
            w.z = pack_f16(ve.z, vo.z);
            w.w = pack_f16(ve.w, vo.w);
            *(uint4*)&Vw[kp * VWS + qq * 4] = w;
        }
        __syncthreads();

        // S = Q K^T : warp tile 16 x 32 (4 n8 tiles), k = d = 64 (4 chunks)
        float sc[4][4];
#pragma unroll
        for (int ni = 0; ni < 4; ni++)
#pragma unroll
            for (int p = 0; p < 4; p++) sc[ni][p] = 0.f;
#pragma unroll
        for (int ck = 0; ck < 4; ck++) {
            uint32_t a[4];
            a[0] = Qw[(m0 + g) * AQW + ck * 8 + t];
            a[1] = Qw[(m0 + g + 8) * AQW + ck * 8 + t];
            a[2] = Qw[(m0 + g) * AQW + ck * 8 + t + 4];
            a[3] = Qw[(m0 + g + 8) * AQW + ck * 8 + t + 4];
#pragma unroll
            for (int ni = 0; ni < 4; ni++) {
                uint32_t b[2];
                b[0] = Kw[(ni * 8 + g) * KWS + ck * 8 + t];
                b[1] = Kw[(ni * 8 + g) * KWS + ck * 8 + t + 4];
                mma_f16(sc[ni], a, b);
            }
        }

        // online softmax (per 2 rows owned by this thread: g and g+8)
#pragma unroll
        for (int h2 = 0; h2 < 2; h2++) {
            int row = q0 + m0 + g + 8 * h2;
            float mloc = -1e30f;
#pragma unroll
            for (int ni = 0; ni < 4; ni++)
#pragma unroll
                for (int p2 = 0; p2 < 2; p2++) {
                    int col = k0 + ni * 8 + 2 * t + p2;
                    float v = (col > row) ? -1e30f : sc[ni][2 * h2 + p2] * 0.125f;
                    sc[ni][2 * h2 + p2] = v;
                    mloc = fmaxf(mloc, v);
                }
            mloc = fmaxf(mloc, __shfl_xor_sync(0xffffffffu, mloc, 1));
            mloc = fmaxf(mloc, __shfl_xor_sync(0xffffffffu, mloc, 2));
            float mn = fmaxf(m[h2], mloc);
            float corr = __expf(m[h2] - mn);
            float rs = 0.f;
#pragma unroll
            for (int ni = 0; ni < 4; ni++)
#pragma unroll
                for (int p2 = 0; p2 < 2; p2++) {
                    float v = sc[ni][2 * h2 + p2];
                    float pv = (v <= -1e29f) ? 0.f : __expf(v - mn);
                    sc[ni][2 * h2 + p2] = pv;
                    rs += pv;
                }
            rs += __shfl_xor_sync(0xffffffffu, rs, 1);
            rs += __shfl_xor_sync(0xffffffffu, rs, 2);
            l[h2] = l[h2] * corr + rs;
            m[h2] = mn;
#pragma unroll
            for (int ni = 0; ni < 8; ni++) {
                acc_o[ni][2 * h2 + 0] *= corr;
                acc_o[ni][2 * h2 + 1] *= corr;
            }
        }

        // pack P fragments: kchunk c covers keys c*16..c*16+15 = tiles 2c, 2c+1
        uint32_t pa[2][4];
#pragma unroll
        for (int c = 0; c < 2; c++) {
            pa[c][0] = pack_f16(sc[2 * c][0], sc[2 * c][1]);
            pa[c][1] = pack_f16(sc[2 * c][2], sc[2 * c][3]);
            pa[c][2] = pack_f16(sc[2 * c + 1][0], sc[2 * c + 1][1]);
            pa[c][3] = pack_f16(sc[2 * c + 1][2], sc[2 * c + 1][3]);
        }
        // O += P V : 8 d-tiles x 2 k-chunks
#pragma unroll
        for (int no = 0; no < 8; no++) {
#pragma unroll
            for (int c = 0; c < 2; c++) {
                uint32_t b[2];
                b[0] = Vw[(c * 8 + t) * VWS + no * 8 + g];
                b[1] = Vw[(c * 8 + t + 4) * VWS + no * 8 + g];
                mma_f16(acc_o[no], pa[c], b);
            }
        }
    }

    // epilogue
#pragma unroll
    for (int h2 = 0; h2 < 2; h2++) {
        float inv = 1.f / l[h2];
        int row = q0 + m0 + g + 8 * h2;
#pragma unroll
        for (int no = 0; no < 8; no++) {
            float2 v = make_float2(acc_o[no][2 * h2 + 0] * inv, acc_o[no][2 * h2 + 1] * inv);
            *(float2*)(attn + (size_t)row * H_ + h * HD_ + no * 8 + 2 * t) = v;
        }
    }
}

// ---------------- gate + top-8 ----------------
__global__ void gate_topk_kernel(const float* __restrict__ x2, const float* __restrict__ Wg,
                                 float* __restrict__ w8, int* __restrict__ idx8) {
    int tt = blockIdx.x, tid = threadIdx.x;
    const float* xr = x2 + (size_t)tt * H_;
    float a0 = 0.f, a1 = 0.f, a2 = 0.f, a3 = 0.f;
    for (int h = 0; h < H_; h += 4) {
        a0 = fmaf(xr[h],     Wg[(size_t)h * E_ + tid],       a0);
        a1 = fmaf(xr[h + 1], Wg[(size_t)(h + 1) * E_ + tid], a1);
        a2 = fmaf(xr[h + 2], Wg[(size_t)(h + 2) * E_ + tid], a2);
        a3 = fmaf(xr[h + 3], Wg[(size_t)(h + 3) * E_ + tid], a3);
    }
    float logit = (a0 + a1) + (a2 + a3);
    __shared__ float red[64];
    __shared__ float gv[64];
    red[tid] = logit; __syncthreads();
    for (int o = 32; o > 0; o >>= 1) { if (tid < o) red[tid] = fmaxf(red[tid], red[tid + o]); __syncthreads(); }
    float mx = red[0]; __syncthreads();
    float ex = __expf(logit - mx);
    red[tid] = ex; __syncthreads();
    for (int o = 32; o > 0; o >>= 1) { if (tid < o) red[tid] += red[tid + o]; __syncthreads(); }
    float sum = red[0];
    gv[tid] = ex / sum; __syncthreads();
    if (tid == 0) {
        bool used[E_];
        for (int e = 0; e < E_; e++) used[e] = false;
        float wv[TOPK_]; int id[TOPK_]; float wsum = 0.f;
        for (int r = 0; r < TOPK_; r++) {
            int best = 0; float bv = -1e30f;
            for (int e = 0; e < E_; e++)
                if (!used[e] && gv[e] > bv) { bv = gv[e]; best = e; }
            used[best] = true; wv[r] = bv; id[r] = best; wsum += bv;
        }
        wsum = fmaxf(wsum, 1.1920929e-07f);
        for (int r = 0; r < TOPK_; r++) {
            w8[tt * TOPK_ + r] = wv[r] / wsum;
            idx8[tt * TOPK_ + r] = id[r];
        }
    }
}

// ---------------- routing ----------------
__global__ void route_kernel(const int* __restrict__ idx8, const float* __restrict__ w8,
                             int* __restrict__ etok, float* __restrict__ ew, int* __restrict__ ecnt) {
    int e = blockIdx.x, lane = threadIdx.x;
    int cnt = 0;
    for (int base = 0; base < S_ * TOPK_; base += 32) {
        int j = base + lane;
        int ee = idx8[j];
        bool match = (ee == e);
        unsigned bal = __ballot_sync(0xffffffffu, match);
        int pre = __popc(bal & ((1u << lane) - 1u));
        if (match) {
            int p = cnt + pre;
            if (p < CAP_) {
                etok[e * CAP_ + p] = j >> 3;
                ew[e * CAP_ + p] = w8[j];
            }
        }
        cnt += __popc(bal);
    }
    if (lane == 0) ecnt[e] = (cnt < CAP_) ? cnt : CAP_;
}

// ---------------- launch ----------------
extern "C" void kernel_launch(void* const* d_in, const int* in_sizes, int n_in,
                              void* d_out, int out_size) {
    (void)in_sizes; (void)n_in; (void)out_size;
    const float* hidden = (const float*)d_in[0];
    const float* cosb   = (const float*)d_in[1];
    const float* sinb   = (const float*)d_in[2];
    const float* ln1    = (const float*)d_in[3];
    const float* ln2    = (const float*)d_in[4];
    const float* Wqkv   = (const float*)d_in[5];
    const float* Wo     = (const float*)d_in[6];
    const float* qnw    = (const float*)d_in[7];
    const float* knw    = (const float*)d_in[8];
    const float* Wgu_sh = (const float*)d_in[9];
    const float* Wd_sh  = (const float*)d_in[10];
    const float* Wgate  = (const float*)d_in[11];
    const float* Wgu_e  = (const float*)d_in[12];
    const float* Wd_e   = (const float*)d_in[13];
    float* out = (float*)d_out;

    float* fb = nullptr; int* ib = nullptr;
    cudaGetSymbolAddress((void**)&fb, g_fbuf);
    cudaGetSymbolAddress((void**)&ib, g_ibuf);

    float* x      = fb + OFF_X;
    float* qkv    = fb + OFF_QKV;
    float* q      = fb + OFF_Q;
    float* k      = fb + OFF_K;
    float* v      = fb + OFF_V;
    float* attn   = fb + OFF_ATTN;
    float* h1     = fb + OFF_H1;
    float* x2     = fb + OFF_X2;
    float* actsh  = fb + OFF_ACTSH;
    float* w8     = fb + OFF_W8;
    float* expw   = fb + OFF_EXPW;
    float* actexp = fb + OFF_ACTEXP;
    int* idx8   = ib + IOFF_IDX8;
    int* exptok = ib + IOFF_EXPTOK;
    int* expcnt = ib + IOFF_EXPCNT;

    // 1. x = rmsnorm(hidden, ln1)
    rmsnorm_kernel<<<S_, 256>>>(hidden, ln1, x);
    // 2. qkv = x @ Wqkv
    mma_gemm<0><<<dim3(QKVN_ / 128, S_ / 128), 256>>>(
        x, H_, Wqkv, QKVN_, nullptr, qkv, QKVN_, H_, nullptr, nullptr, nullptr);
    // 3. RoPE + QK-norm
    qkvproc_kernel<<<S_, 256>>>(qkv, cosb, sinb, qnw, knw, q, k, v);
    // 4. attention (fp16 mma)
    attn_kernel<<<dim3(S_ / 64, NH_), 128>>>(q, k, v, attn);
    // 5. h1 = attn @ Wo + hidden
    mma_gemm<1><<<dim3(H_ / 128, S_ / 128), 256>>>(
        attn, H_, Wo, H_, hidden, h1, H_, H_, nullptr, nullptr, nullptr);
    // 6. x2 = rmsnorm(h1, ln2)
    rmsnorm_kernel<<<S_, 256>>>(h1, ln2, x2);
    // 7. shared swiglu activation
    mma_gemm<2><<<dim3(I_ / 64, S_ / 128), 256>>>(
        x2, H_, Wgu_sh, 2 * I_, nullptr, actsh, I_, H_, nullptr, nullptr, nullptr);
    // 8. out = actsh @ Wd_sh + h1
    mma_gemm<1><<<dim3(H_ / 128, S_ / 128), 256>>>(
        actsh, I_, Wd_sh, H_, h1, out, H_, I_, nullptr, nullptr, nullptr);
    // 9. gate + top-8
    gate_topk_kernel<<<S_, 64>>>(x2, Wgate, w8, idx8);
    // 10. routing
    route_kernel<<<E_, 32>>>(idx8, w8, exptok, expw, expcnt);
    // 11a. expert swiglu, slots 0-127 (128-row mma)
    mma_gemm<3><<<dim3(I_ / 64, 1, E_), 256>>>(
        x2, H_, Wgu_e, 2 * I_, nullptr, actexp, I_, H_, exptok, nullptr, expcnt);
    // 11b. expert swiglu overflow slots 128..511 (32-row mma, early-exit)
    mma_gemm_s<3><<<dim3(I_ / 64, 12, E_), 256>>>(
        x2, H_, Wgu_e, 2 * I_, actexp, H_, exptok, nullptr, expcnt);
    // 12a. expert down + scatter, slots 0-127 (128-row mma)
    mma_gemm<4><<<dim3(H_ / 128, 1, E_), 256>>>(
        actexp, I_, Wd_e, H_, nullptr, out, H_, I_, exptok, expw, expcnt);
    // 12b. expert down overflow slots 128..511 (32-row mma, early-exit)
    mma_gemm_s<4><<<dim3(H_ / 128, 12, E_), 256>>>(
        actexp, I_, Wd_e, H_, out, I_, exptok, expw, expcnt);
}

// round 14
// speedup vs baseline: 2.0496x; 1.0388x over previous
#include <cuda_runtime.h>
#include <cstddef>
#include <cstdint>

#define S_    1024
#define H_    1024
#define HD_   64
#define NH_   16
#define KVH_  8
#define E_    64
#define TOPK_ 8
#define CAP_  512
#define I_    3072
#define QKVN_ 2048

// ---------------- static scratch ----------------
static const size_t OFF_X      = 0;
static const size_t OFF_QKV    = 1048576;
static const size_t OFF_Q      = 3145728;
static const size_t OFF_K      = 4194304;
static const size_t OFF_V      = 4718592;
static const size_t OFF_ATTN   = 5242880;
static const size_t OFF_H1     = 6291456;
static const size_t OFF_X2     = 7340032;
static const size_t OFF_ACTSH  = 8388608;
static const size_t OFF_W8     = 11599872;
static const size_t OFF_EXPW   = 11608064;
static const size_t OFF_ACTEXP = 11640832;
static const size_t FBUF_TOT   = 112304128;

static const size_t IOFF_IDX8   = 0;
static const size_t IOFF_EXPTOK = 8192;
static const size_t IOFF_EXPCNT = 40960;

__device__ float g_fbuf[FBUF_TOT];
__device__ int   g_ibuf[41028];

// pack two fp32 -> f16x2 word, round-to-nearest-even; lo = first arg
__device__ __forceinline__ uint32_t pack_f16(float lo, float hi) {
    uint32_t r;
    asm("cvt.rn.f16x2.f32 %0, %1, %2;" : "=r"(r) : "f"(hi), "f"(lo));
    return r;
}

__device__ __forceinline__ void mma_f16(float* c, const uint32_t* a, const uint32_t* b) {
    asm volatile(
        "mma.sync.aligned.m16n8k16.row.col.f32.f16.f16.f32 "
        "{%0,%1,%2,%3}, {%4,%5,%6,%7}, {%8,%9}, {%0,%1,%2,%3};"
        : "+f"(c[0]), "+f"(c[1]), "+f"(c[2]), "+f"(c[3])
        : "r"(a[0]), "r"(a[1]), "r"(a[2]), "r"(a[3]), "r"(b[0]), "r"(b[1]));
}

__device__ __forceinline__ void ldsm_x4(uint32_t* r, uint32_t addr) {
    asm volatile("ldmatrix.sync.aligned.m8n8.x4.shared.b16 {%0,%1,%2,%3}, [%4];"
        : "=r"(r[0]), "=r"(r[1]), "=r"(r[2]), "=r"(r[3]) : "r"(addr));
}

// ---------------- fp16 mma.sync GEMM (128x128, 2x4 warps, 2 CTA/SM) ----------------
#define AWS 12
#define BWS 132

template<int MODE>
__global__ void __launch_bounds__(256, 2) mma_gemm(
    const float* __restrict__ A, int lda,
    const float* __restrict__ B, int ldb,
    const float* __restrict__ Dadd,
    float* __restrict__ out, int ldc, int Kdim,
    const int* __restrict__ etok, const float* __restrict__ ew,
    const int* __restrict__ ecnt) {
    constexpr bool IS_SWI = (MODE == 2 || MODE == 3);
    constexpr bool IS_EXP = (MODE == 3 || MODE == 4);

    int e = IS_EXP ? blockIdx.z : 0;
    int cnt = IS_EXP ? ecnt[e] : S_;
    if (IS_EXP) { int mx = 128 * gridDim.y; cnt = (cnt < mx) ? cnt : mx; }
    int row0 = blockIdx.y * 128;
    if (IS_EXP && row0 >= cnt) return;
    int bx = blockIdx.x;

    __shared__ uint32_t Aw[2][128 * AWS];
    __shared__ uint32_t Bw[2][8 * BWS];
    __shared__ int   toks_s[128];
    __shared__ float ws_s[128];

    int tid = threadIdx.x;
    int wid = tid >> 5;
    int lane = tid & 31;
    int g = lane >> 2, t = lane & 3;
    int wm = wid & 1, wn = wid >> 1;

    const float* Ab = A;
    const float* Bb = B;
    float* outp = out;
    if (MODE == 3) { Bb = B + (size_t)e * H_ * 2 * I_; outp = out + (size_t)e * CAP_ * I_; }
    if (MODE == 4) { Ab = A + (size_t)e * CAP_ * I_; Bb = B + (size_t)e * I_ * H_; }

    if (IS_EXP && tid < 128) {
        int rr = row0 + tid;
        bool v = rr < cnt;
        toks_s[tid] = v ? etok[e * CAP_ + rr] : 0;
        ws_s[tid]   = v ? ew[e * CAP_ + rr] : 0.f;
    }
    if (IS_EXP) __syncthreads();

    const float* arow_ptr[2];
    int aq[2];
#pragma unroll
    for (int s = 0; s < 2; s++) {
        int f4 = tid + 256 * s;
        int r = f4 >> 2; aq[s] = (f4 & 3) * 4;
        if (MODE == 3) arow_ptr[s] = A + (size_t)toks_s[r] * lda;
        else           arow_ptr[s] = Ab + (size_t)(row0 + r) * lda;
    }
    int kp = tid >> 5, nq = tid & 31;
    int bcol;
    if (IS_SWI) bcol = (nq < 16) ? (bx * 64 + nq * 4) : (I_ + bx * 64 + (nq - 16) * 4);
    else        bcol = bx * 128 + nq * 4;
    const float* b_even = Bb + (size_t)(2 * kp) * ldb + bcol;
    const float* b_odd  = Bb + (size_t)(2 * kp + 1) * ldb + bcol;

    float4 aR[2], bE, bO;
    auto ldg = [&](int kt) {
#pragma unroll
        for (int s = 0; s < 2; s++) aR[s] = *(const float4*)(arow_ptr[s] + kt + aq[s]);
        bE = *(const float4*)(b_even + (size_t)kt * ldb);
        bO = *(const float4*)(b_odd  + (size_t)kt * ldb);
    };
    auto sts = [&](int buf) {
#pragma unroll
        for (int s = 0; s < 2; s++) {
            int f4 = tid + 256 * s;
            int r = f4 >> 2, q = f4 & 3;
            uint2 w;
            w.x = pack_f16(aR[s].x, aR[s].y);
            w.y = pack_f16(aR[s].z, aR[s].w);
            *(uint2*)&Aw[buf][r * AWS + 2 * q] = w;
        }
        uint4 wb;
        wb.x = pack_f16(bE.x, bO.x);
        wb.y = pack_f16(bE.y, bO.y);
        wb.z = pack_f16(bE.z, bO.z);
        wb.w = pack_f16(bE.w, bO.w);
        *(uint4*)&Bw[buf][kp * BWS + nq * 4] = wb;
    };

    // ldmatrix lane addressing for A fragments
    uint32_t asmb[2];
    asmb[0] = (uint32_t)__cvta_generic_to_shared(&Aw[0][0]);
    asmb[1] = (uint32_t)__cvta_generic_to_shared(&Aw[1][0]);
    int rowoff = (lane & 7) + ((lane >> 3) & 1) * 8;
    int wordoff = (lane >> 4) * 4;
    uint32_t laneoff = (uint32_t)(rowoff * AWS + wordoff) * 4u;

    float acc[4][4][4];
#pragma unroll
    for (int mi = 0; mi < 4; mi++)
#pragma unroll
        for (int ni = 0; ni < 4; ni++)
#pragma unroll
            for (int p = 0; p < 4; p++) acc[mi][ni][p] = 0.f;

    ldg(0); sts(0);
    __syncthreads();

    int NC = Kdim / 16;
    for (int c = 0; c < NC; c++) {
        int cur = c & 1;
        if (c + 1 < NC) ldg((c + 1) * 16);
        {
            uint32_t af[4][4], bf[4][2];
#pragma unroll
            for (int mi = 0; mi < 4; mi++) {
                uint32_t addr = asmb[cur] + (uint32_t)((wm * 64 + mi * 16) * AWS) * 4u + laneoff;
                ldsm_x4(af[mi], addr);
            }
#pragma unroll
            for (int ni = 0; ni < 4; ni++) {
                int n0;
                if (IS_SWI) n0 = (ni < 2) ? (wn * 16 + ni * 8) : (64 + wn * 16 + (ni - 2) * 8);
                else        n0 = wn * 32 + ni * 8;
                bf[ni][0] = Bw[cur][t * BWS + n0 + g];
                bf[ni][1] = Bw[cur][(t + 4) * BWS + n0 + g];
            }
#pragma unroll
            for (int mi = 0; mi < 4; mi++)
#pragma unroll
                for (int ni = 0; ni < 4; ni++)
                    mma_f16(acc[mi][ni], af[mi], bf[ni]);
        }
        if (c + 1 < NC) sts(cur ^ 1);
        __syncthreads();
    }

    if (MODE == 0 || MODE == 1) {
#pragma unroll
        for (int mi = 0; mi < 4; mi++) {
            int r = row0 + wm * 64 + mi * 16 + g;
#pragma unroll
            for (int ni = 0; ni < 4; ni++) {
                int col = bx * 128 + wn * 32 + ni * 8 + 2 * t;
                float2 v0 = make_float2(acc[mi][ni][0], acc[mi][ni][1]);
                float2 v1 = make_float2(acc[mi][ni][2], acc[mi][ni][3]);
                if (MODE == 1) {
                    float2 d0 = *(const float2*)(Dadd + (size_t)r * ldc + col);
                    float2 d1 = *(const float2*)(Dadd + (size_t)(r + 8) * ldc + col);
                    v0.x += d0.x; v0.y += d0.y; v1.x += d1.x; v1.y += d1.y;
                }
                *(float2*)(outp + (size_t)r * ldc + col) = v0;
                *(float2*)(outp + (size_t)(r + 8) * ldc + col) = v1;
            }
        }
    } else if (IS_SWI) {
#pragma unroll
        for (int mi = 0; mi < 4; mi++) {
            int r = row0 + wm * 64 + mi * 16 + g;
#pragma unroll
            for (int ni = 0; ni < 2; ni++) {
                int col = bx * 64 + wn * 16 + ni * 8 + 2 * t;
#pragma unroll
                for (int h = 0; h < 2; h++) {
                    int rg = r + 8 * h;
                    if (MODE == 3 && rg >= cnt) continue;
                    float gg0 = acc[mi][ni][2 * h + 0], gg1 = acc[mi][ni][2 * h + 1];
                    float uu0 = acc[mi][ni + 2][2 * h + 0], uu1 = acc[mi][ni + 2][2 * h + 1];
                    float s0 = 1.f / (1.f + __expf(-uu0));
                    float s1 = 1.f / (1.f + __expf(-uu1));
                    float2 v = make_float2(gg0 * uu0 * s0, gg1 * uu1 * s1);
                    *(float2*)(outp + (size_t)rg * I_ + col) = v;
                }
            }
        }
    } else {  // MODE 4
#pragma unroll
        for (int mi = 0; mi < 4; mi++) {
            int rl = wm * 64 + mi * 16 + g;
#pragma unroll
            for (int h = 0; h < 2; h++) {
                int rr = rl + 8 * h;
                if (row0 + rr >= cnt) continue;
                int tok = toks_s[rr];
                float wv = ws_s[rr];
#pragma unroll
                for (int ni = 0; ni < 4; ni++) {
                    int col = bx * 128 + wn * 32 + ni * 8 + 2 * t;
                    atomicAdd(out + (size_t)tok * H_ + col,     acc[mi][ni][2 * h + 0] * wv);
                    atomicAdd(out + (size_t)tok * H_ + col + 1, acc[mi][ni][2 * h + 1] * wv);
                }
            }
        }
    }
}

// ---------------- small-M (32-row) fp16 expert mma kernel for overflow slots ----------
template<int MODE>
__global__ void __launch_bounds__(256, 2) mma_gemm_s(
    const float* __restrict__ A, int lda,
    const float* __restrict__ B, int ldb,
    float* __restrict__ out, int Kdim,
    const int* __restrict__ etok, const float* __restrict__ ew,
    const int* __restrict__ ecnt) {
    constexpr bool IS_SWI = (MODE == 3);

    int e = blockIdx.z;
    int cnt = ecnt[e];
    int row0 = 128 + blockIdx.y * 32;
    if (row0 >= cnt) return;
    int bx = blockIdx.x;

    __shared__ uint32_t Aw[2][32 * AWS];
    __shared__ uint32_t Bw[2][8 * BWS];
    __shared__ int   toks_s[32];
    __shared__ float ws_s[32];

    int tid = threadIdx.x;
    int wid = tid >> 5;
    int lane = tid & 31;
    int g = lane >> 2, t = lane & 3;
    int wn = wid;

    const float* Ab = A;
    const float* Bb = B;
    float* outp = out;
    if (MODE == 3) { Bb = B + (size_t)e * H_ * 2 * I_; outp = out + (size_t)e * CAP_ * I_; }
    if (MODE == 4) { Ab = A + (size_t)e * CAP_ * I_; Bb = B + (size_t)e * I_ * H_; }

    if (tid < 32) {
        int rr = row0 + tid;
        bool v = rr < cnt;
        toks_s[tid] = v ? etok[e * CAP_ + rr] : 0;
        ws_s[tid]   = v ? ew[e * CAP_ + rr] : 0.f;
    }
    __syncthreads();

    const float* arow_ptr = nullptr;
    int aq = 0;
    if (tid < 128) {
        int r = tid >> 2; aq = (tid & 3) * 4;
        if (MODE == 3) arow_ptr = A + (size_t)toks_s[r] * lda;
        else           arow_ptr = Ab + (size_t)(row0 + r) * lda;
    }
    int kp = tid >> 5, nq = tid & 31;
    int bcol;
    if (IS_SWI) bcol = (nq < 16) ? (bx * 64 + nq * 4) : (I_ + bx * 64 + (nq - 16) * 4);
    else        bcol = bx * 128 + nq * 4;
    const float* b_even = Bb + (size_t)(2 * kp) * ldb + bcol;
    const float* b_odd  = Bb + (size_t)(2 * kp + 1) * ldb + bcol;

    float4 aR, bE, bO;
    auto ldg = [&](int kt) {
        if (tid < 128) aR = *(const float4*)(arow_ptr + kt + aq);
        bE = *(const float4*)(b_even + (size_t)kt * ldb);
        bO = *(const float4*)(b_odd  + (size_t)kt * ldb);
    };
    auto sts = [&](int buf) {
        if (tid < 128) {
            int r = tid >> 2, q = tid & 3;
            uint2 w;
            w.x = pack_f16(aR.x, aR.y);
            w.y = pack_f16(aR.z, aR.w);
            *(uint2*)&Aw[buf][r * AWS + 2 * q] = w;
        }
        uint4 wb;
        wb.x = pack_f16(bE.x, bO.x);
        wb.y = pack_f16(bE.y, bO.y);
        wb.z = pack_f16(bE.z, bO.z);
        wb.w = pack_f16(bE.w, bO.w);
        *(uint4*)&Bw[buf][kp * BWS + nq * 4] = wb;
    };

    uint32_t asmb[2];
    asmb[0] = (uint32_t)__cvta_generic_to_shared(&Aw[0][0]);
    asmb[1] = (uint32_t)__cvta_generic_to_shared(&Aw[1][0]);
    int rowoff = (lane & 7) + ((lane >> 3) & 1) * 8;
    int wordoff = (lane >> 4) * 4;
    uint32_t laneoff = (uint32_t)(rowoff * AWS + wordoff) * 4u;

    float acc[2][2][4];
#pragma unroll
    for (int mi = 0; mi < 2; mi++)
#pragma unroll
        for (int ni = 0; ni < 2; ni++)
#pragma unroll
            for (int p = 0; p < 4; p++) acc[mi][ni][p] = 0.f;

    ldg(0); sts(0);
    __syncthreads();

    int NC = Kdim / 16;
    for (int c = 0; c < NC; c++) {
        int cur = c & 1;
        if (c + 1 < NC) ldg((c + 1) * 16);
        {
            uint32_t af[2][4], bf[2][2];
#pragma unroll
            for (int mi = 0; mi < 2; mi++) {
                uint32_t addr = asmb[cur] + (uint32_t)((mi * 16) * AWS) * 4u + laneoff;
                ldsm_x4(af[mi], addr);
            }
#pragma unroll
            for (int ni = 0; ni < 2; ni++) {
                int n0;
                if (IS_SWI) n0 = (ni == 0) ? (wn * 8) : (64 + wn * 8);
                else        n0 = wn * 16 + ni * 8;
                bf[ni][0] = Bw[cur][t * BWS + n0 + g];
                bf[ni][1] = Bw[cur][(t + 4) * BWS + n0 + g];
            }
#pragma unroll
            for (int mi = 0; mi < 2; mi++)
#pragma unroll
                for (int ni = 0; ni < 2; ni++)
                    mma_f16(acc[mi][ni], af[mi], bf[ni]);
        }
        if (c + 1 < NC) sts(cur ^ 1);
        __syncthreads();
    }

    if (MODE == 3) {
#pragma unroll
        for (int mi = 0; mi < 2; mi++) {
            int col = bx * 64 + wn * 8 + 2 * t;
#pragma unroll
            for (int h = 0; h < 2; h++) {
                int rl = mi * 16 + g + 8 * h;
                int rg = row0 + rl;
                if (rg >= cnt) continue;
                float gg0 = acc[mi][0][2 * h + 0], gg1 = acc[mi][0][2 * h + 1];
                float uu0 = acc[mi][1][2 * h + 0], uu1 = acc[mi][1][2 * h + 1];
                float s0 = 1.f / (1.f + __expf(-uu0));
                float s1 = 1.f / (1.f + __expf(-uu1));
                float2 v = make_float2(gg0 * uu0 * s0, gg1 * uu1 * s1);
                *(float2*)(outp + (size_t)rg * I_ + col) = v;
            }
        }
    } else {
#pragma unroll
        for (int mi = 0; mi < 2; mi++) {
#pragma unroll
            for (int h = 0; h < 2; h++) {
                int rl = mi * 16 + g + 8 * h;
                if (row0 + rl >= cnt) continue;
                int tok = toks_s[rl];
                float wv = ws_s[rl];
#pragma unroll
                for (int ni = 0; ni < 2; ni++) {
                    int col = bx * 128 + wn * 16 + ni * 8 + 2 * t;
                    atomicAdd(out + (size_t)tok * H_ + col,     acc[mi][ni][2 * h + 0] * wv);
                    atomicAdd(out + (size_t)tok * H_ + col + 1, acc[mi][ni][2 * h + 1] * wv);
                }
            }
        }
    }
}

// ---------------- RMSNorm ----------------
__global__ void rmsnorm_kernel(const float* __restrict__ in, const float* __restrict__ w,
                               float* __restrict__ out) {
    int row = blockIdx.x, tid = threadIdx.x;
    const float* x = in + (size_t)row * H_;
    float s = 0.f;
    for (int i = tid; i < H_; i += 256) { float v = x[i]; s += v * v; }
    __shared__ float red[256];
    red[tid] = s; __syncthreads();
    for (int o = 128; o > 0; o >>= 1) { if (tid < o) red[tid] += red[tid + o]; __syncthreads(); }
    float sc = rsqrtf(red[0] * (1.f / H_) + 1e-6f);
    for (int i = tid; i < H_; i += 256) out[(size_t)row * H_ + i] = x[i] * sc * w[i];
}

// ---------------- QKV postprocess ----------------
__global__ void qkvproc_kernel(const float* __restrict__ qkv, const float* __restrict__ cosb,
                               const float* __restrict__ sinb, const float* __restrict__ qnw,
                               const float* __restrict__ knw, float* __restrict__ q,
                               float* __restrict__ k, float* __restrict__ v) {
    int s = blockIdx.x, tid = threadIdx.x;
    int w = tid >> 5, lane = tid & 31;
#pragma unroll
    for (int p = 0; p < 4; p++) {
        int r = w + 8 * p;
        int kv = r >> 2, slot = r & 3;
        int base = s * QKVN_ + kv * 256 + slot * 64;
        int d0 = lane * 2, d1 = d0 + 1;
        float x0 = qkv[base + d0], x1 = qkv[base + d1];
        float y0, y1;
        if (slot == 3) { y0 = x0; y1 = x1; }
        else {
            float p0 = __shfl_xor_sync(0xffffffffu, x0, 16);
            float p1 = __shfl_xor_sync(0xffffffffu, x1, 16);
            float rh0 = (lane < 16) ? -p0 : p0;
            float rh1 = (lane < 16) ? -p1 : p1;
            float c0 = cosb[s * HD_ + d0], s0 = sinb[s * HD_ + d0];
            float c1 = cosb[s * HD_ + d1], s1 = sinb[s * HD_ + d1];
            y0 = x0 * c0 + rh0 * s0;
            y1 = x1 * c1 + rh1 * s1;
            float ss = y0 * y0 + y1 * y1;
            for (int off = 16; off > 0; off >>= 1) ss += __shfl_xor_sync(0xffffffffu, ss, off);
            float scn = rsqrtf(ss * (1.f / HD_) + 1e-6f);
            const float* wn = (slot < 2) ? qnw : knw;
            y0 = y0 * scn * wn[d0];
            y1 = y1 * scn * wn[d1];
        }
        if (slot < 2) {
            int hh = kv * 2 + slot;
            size_t off = ((size_t)hh * S_ + s) * HD_;
            q[off + d0] = y0; q[off + d1] = y1;
        } else if (slot == 2) {
            size_t off = ((size_t)kv * S_ + s) * HD_;
            k[off + d0] = y0; k[off + d1] = y1;
        } else {
            size_t off = ((size_t)kv * S_ + s) * HD_;
            v[off + d0] = y0; v[off + d1] = y1;
        }
    }
}

// ---------------- flash attention, fp16 mma (BQ=64, BK=32, 128 threads) ----------------
#define AQW 36
#define KWS 36
#define VWS 72

__global__ void __launch_bounds__(128) attn_kernel(const float* __restrict__ qg,
                                                   const float* __restrict__ kg,
                                                   const float* __restrict__ vg,
                                                   float* __restrict__ attn) {
    int qt = blockIdx.x, h = blockIdx.y;
    int q0 = qt * 64;
    const float* Q = qg + ((size_t)h * S_ + q0) * HD_;
    const float* Kp = kg + ((size_t)(h >> 1) * S_) * HD_;
    const float* Vp = vg + ((size_t)(h >> 1) * S_) * HD_;

    __shared__ uint32_t Qw[64 * AQW];
    __shared__ uint32_t Kw[32 * KWS];
    __shared__ uint32_t Vw[16 * VWS];

    int tid = threadIdx.x;
    int wid = tid >> 5;
    int lane = tid & 31;
    int g = lane >> 2, t = lane & 3;
    int m0 = wid * 16;

    for (int i = tid; i < 1024; i += 128) {
        int row = i >> 4, qq = i & 15;
        float4 v = *(const float4*)(Q + (size_t)row * HD_ + qq * 4);
        uint2 w;
        w.x = pack_f16(v.x, v.y);
        w.y = pack_f16(v.z, v.w);
        *(uint2*)&Qw[row * AQW + qq * 2] = w;
    }

    float acc_o[8][4];
#pragma unroll
    for (int i = 0; i < 8; i++)
#pragma unroll
        for (int p = 0; p < 4; p++) acc_o[i][p] = 0.f;
    float m[2] = {-1e30f, -1e30f};
    float l[2] = {0.f, 0.f};

    int nkt = (q0 + 64) / 32;
    for (int kt = 0; kt < nkt; kt++) {
        int k0 = kt * 32;
        __syncthreads();
        for (int i = tid; i < 512; i += 128) {
            int key = i >> 4, qq = i & 15;
            float4 v = *(const float4*)(Kp + (size_t)(k0 + key) * HD_ + qq * 4);
            uint2 w;
            w.x = pack_f16(v.x, v.y);
            w.y = pack_f16(v.z, v.w);
            *(uint2*)&Kw[key * KWS + qq * 2] = w;
        }
        for (int i = tid; i < 256; i += 128) {
            int kp = i >> 4, qq = i & 15;
            float4 ve = *(const float4*)(Vp + (size_t)(k0 + 2 * kp) * HD_ + qq * 4);
            float4 vo = *(const float4*)(Vp + (size_t)(k0 + 2 * kp + 1) * HD_ + qq * 4);
            uint4 w;
            w.x = pack_f16(ve.x, vo.x);
            w.y = pack_f16(ve.y, vo.y);
            w.z = pack_f16(ve.z, vo.z);
            w.w = pack_f16(ve.w, vo.w);
            *(uint4*)&Vw[kp * VWS + qq * 4] = w;
        }
        __syncthreads();

        float sc[4][4];
#pragma unroll
        for (int ni = 0; ni < 4; ni++)
#pragma unroll
            for (int p = 0; p < 4; p++) sc[ni][p] = 0.f;
#pragma unroll
        for (int ck = 0; ck < 4; ck++) {
            uint32_t a[4];
            a[0] = Qw[(m0 + g) * AQW + ck * 8 + t];
            a[1] = Qw[(m0 + g + 8) * AQW + ck * 8 + t];
            a[2] = Qw[(m0 + g) * AQW + ck * 8 + t + 4];
            a[3] = Qw[(m0 + g + 8) * AQW + ck * 8 + t + 4];
#pragma unroll
            for (int ni = 0; ni < 4; ni++) {
                uint32_t b[2];
                b[0] = Kw[(ni * 8 + g) * KWS + ck * 8 + t];
                b[1] = Kw[(ni * 8 + g) * KWS + ck * 8 + t + 4];
                mma_f16(sc[ni], a, b);
            }
        }

#pragma unroll
        for (int h2 = 0; h2 < 2; h2++) {
            int row = q0 + m0 + g + 8 * h2;
            float mloc = -1e30f;
#pragma unroll
            for (int ni = 0; ni < 4; ni++)
#pragma unroll
                for (int p2 = 0; p2 < 2; p2++) {
                    int col = k0 + ni * 8 + 2 * t + p2;
                    float v = (col > row) ? -1e30f : sc[ni][2 * h2 + p2] * 0.125f;
                    sc[ni][2 * h2 + p2] = v;
                    mloc = fmaxf(mloc, v);
                }
            mloc = fmaxf(mloc, __shfl_xor_sync(0xffffffffu, mloc, 1));
            mloc = fmaxf(mloc, __shfl_xor_sync(0xffffffffu, mloc, 2));
            float mn = fmaxf(m[h2], mloc);
            float corr = __expf(m[h2] - mn);
            float rs = 0.f;
#pragma unroll
            for (int ni = 0; ni < 4; ni++)
#pragma unroll
                for (int p2 = 0; p2 < 2; p2++) {
                    float v = sc[ni][2 * h2 + p2];
                    float pv = (v <= -1e29f) ? 0.f : __expf(v - mn);
                    sc[ni][2 * h2 + p2] = pv;
                    rs += pv;
                }
            rs += __shfl_xor_sync(0xffffffffu, rs, 1);
            rs += __shfl_xor_sync(0xffffffffu, rs, 2);
            l[h2] = l[h2] * corr + rs;
            m[h2] = mn;
#pragma unroll
            for (int ni = 0; ni < 8; ni++) {
                acc_o[ni][2 * h2 + 0] *= corr;
                acc_o[ni][2 * h2 + 1] *= corr;
            }
        }

        uint32_t pa[2][4];
#pragma unroll
        for (int c = 0; c < 2; c++) {
            pa[c][0] = pack_f16(sc[2 * c][0], sc[2 * c][1]);
            pa[c][1] = pack_f16(sc[2 * c][2], sc[2 * c][3]);
            pa[c][2] = pack_f16(sc[2 * c + 1][0], sc[2 * c + 1][1]);
            pa[c][3] = pack_f16(sc[2 * c + 1][2], sc[2 * c + 1][3]);
        }
#pragma unroll
        for (int no = 0; no < 8; no++) {
#pragma unroll
            for (int c = 0; c < 2; c++) {
                uint32_t b[2];
                b[0] = Vw[(c * 8 + t) * VWS + no * 8 + g];
                b[1] = Vw[(c * 8 + t + 4) * VWS + no * 8 + g];
                mma_f16(acc_o[no], pa[c], b);
            }
        }
    }

#pragma unroll
    for (int h2 = 0; h2 < 2; h2++) {
        float inv = 1.f / l[h2];
        int row = q0 + m0 + g + 8 * h2;
#pragma unroll
        for (int no = 0; no < 8; no++) {
            float2 v = make_float2(acc_o[no][2 * h2 + 0] * inv, acc_o[no][2 * h2 + 1] * inv);
            *(float2*)(attn + (size_t)row * H_ + h * HD_ + no * 8 + 2 * t) = v;
        }
    }
}

// ---------------- gate + top-8 ----------------
__global__ void gate_topk_kernel(const float* __restrict__ x2, const float* __restrict__ Wg,
                                 float* __restrict__ w8, int* __restrict__ idx8) {
    int tt = blockIdx.x, tid = threadIdx.x;
    const float* xr = x2 + (size_t)tt * H_;
    float a0 = 0.f, a1 = 0.f, a2 = 0.f, a3 = 0.f;
    for (int h = 0; h < H_; h += 4) {
        a0 = fmaf(xr[h],     Wg[(size_t)h * E_ + tid],       a0);
        a1 = fmaf(xr[h + 1], Wg[(size_t)(h + 1) * E_ + tid], a1);
        a2 = fmaf(xr[h + 2], Wg[(size_t)(h + 2) * E_ + tid], a2);
        a3 = fmaf(xr[h + 3], Wg[(size_t)(h + 3) * E_ + tid], a3);
    }
    float logit = (a0 + a1) + (a2 + a3);
    __shared__ float red[64];
    __shared__ float gv[64];
    red[tid] = logit; __syncthreads();
    for (int o = 32; o > 0; o >>= 1) { if (tid < o) red[tid] = fmaxf(red[tid], red[tid + o]); __syncthreads(); }
    float mx = red[0]; __syncthreads();
    float ex = __expf(logit - mx);
    red[tid] = ex; __syncthreads();
    for (int o = 32; o > 0; o >>= 1) { if (tid < o) red[tid] += red[tid + o]; __syncthreads(); }
    float sum = red[0];
    gv[tid] = ex / sum; __syncthreads();
    if (tid == 0) {
        bool used[E_];
        for (int e = 0; e < E_; e++) used[e] = false;
        float wv[TOPK_]; int id[TOPK_]; float wsum = 0.f;
        for (int r = 0; r < TOPK_; r++) {
            int best = 0; float bv = -1e30f;
            for (int e = 0; e < E_; e++)
                if (!used[e] && gv[e] > bv) { bv = gv[e]; best = e; }
            used[best] = true; wv[r] = bv; id[r] = best; wsum += bv;
        }
        wsum = fmaxf(wsum, 1.1920929e-07f);
        for (int r = 0; r < TOPK_; r++) {
            w8[tt * TOPK_ + r] = wv[r] / wsum;
            idx8[tt * TOPK_ + r] = id[r];
        }
    }
}

// ---------------- routing ----------------
__global__ void route_kernel(const int* __restrict__ idx8, const float* __restrict__ w8,
                             int* __restrict__ etok, float* __restrict__ ew, int* __restrict__ ecnt) {
    int e = blockIdx.x, lane = threadIdx.x;
    int cnt = 0;
    for (int base = 0; base < S_ * TOPK_; base += 32) {
        int j = base + lane;
        int ee = idx8[j];
        bool match = (ee == e);
        unsigned bal = __ballot_sync(0xffffffffu, match);
        int pre = __popc(bal & ((1u << lane) - 1u));
        if (match) {
            int p = cnt + pre;
            if (p < CAP_) {
                etok[e * CAP_ + p] = j >> 3;
                ew[e * CAP_ + p] = w8[j];
            }
        }
        cnt += __popc(bal);
    }
    if (lane == 0) ecnt[e] = (cnt < CAP_) ? cnt : CAP_;
}

// ---------------- launch ----------------
extern "C" void kernel_launch(void* const* d_in, const int* in_sizes, int n_in,
                              void* d_out, int out_size) {
    (void)in_sizes; (void)n_in; (void)out_size;
    const float* hidden = (const float*)d_in[0];
    const float* cosb   = (const float*)d_in[1];
    const float* sinb   = (const float*)d_in[2];
    const float* ln1    = (const float*)d_in[3];
    const float* ln2    = (const float*)d_in[4];
    const float* Wqkv   = (const float*)d_in[5];
    const float* Wo     = (const float*)d_in[6];
    const float* qnw    = (const float*)d_in[7];
    const float* knw    = (const float*)d_in[8];
    const float* Wgu_sh = (const float*)d_in[9];
    const float* Wd_sh  = (const float*)d_in[10];
    const float* Wgate  = (const float*)d_in[11];
    const float* Wgu_e  = (const float*)d_in[12];
    const float* Wd_e   = (const float*)d_in[13];
    float* out = (float*)d_out;

    float* fb = nullptr; int* ib = nullptr;
    cudaGetSymbolAddress((void**)&fb, g_fbuf);
    cudaGetSymbolAddress((void**)&ib, g_ibuf);

    float* x      = fb + OFF_X;
    float* qkv    = fb + OFF_QKV;
    float* q      = fb + OFF_Q;
    float* k      = fb + OFF_K;
    float* v      = fb + OFF_V;
    float* attn   = fb + OFF_ATTN;
    float* h1     = fb + OFF_H1;
    float* x2     = fb + OFF_X2;
    float* actsh  = fb + OFF_ACTSH;
    float* w8     = fb + OFF_W8;
    float* expw   = fb + OFF_EXPW;
    float* actexp = fb + OFF_ACTEXP;
    int* idx8   = ib + IOFF_IDX8;
    int* exptok = ib + IOFF_EXPTOK;
    int* expcnt = ib + IOFF_EXPCNT;

    // 1. x = rmsnorm(hidden, ln1)
    rmsnorm_kernel<<<S_, 256>>>(hidden, ln1, x);
    // 2. qkv = x @ Wqkv
    mma_gemm<0><<<dim3(QKVN_ / 128, S_ / 128), 256>>>(
        x, H_, Wqkv, QKVN_, nullptr, qkv, QKVN_, H_, nullptr, nullptr, nullptr);
    // 3. RoPE + QK-norm
    qkvproc_kernel<<<S_, 256>>>(qkv, cosb, sinb, qnw, knw, q, k, v);
    // 4. attention (fp16 mma)
    attn_kernel<<<dim3(S_ / 64, NH_), 128>>>(q, k, v, attn);
    // 5. h1 = attn @ Wo + hidden
    mma_gemm<1><<<dim3(H_ / 128, S_ / 128), 256>>>(
        attn, H_, Wo, H_, hidden, h1, H_, H_, nullptr, nullptr, nullptr);
    // 6. x2 = rmsnorm(h1, ln2)
    rmsnorm_kernel<<<S_, 256>>>(h1, ln2, x2);
    // 7. shared swiglu activation
    mma_gemm<2><<<dim3(I_ / 64, S_ / 128), 256>>>(
        x2, H_, Wgu_sh, 2 * I_, nullptr, actsh, I_, H_, nullptr, nullptr, nullptr);
    // 8. out = actsh @ Wd_sh + h1
    mma_gemm<1><<<dim3(H_ / 128, S_ / 128), 256>>>(
        actsh, I_, Wd_sh, H_, h1, out, H_, I_, nullptr, nullptr, nullptr);
    // 9. gate + top-8
    gate_topk_kernel<<<S_, 64>>>(x2, Wgate, w8, idx8);
    // 10. routing
    route_kernel<<<E_, 32>>>(idx8, w8, exptok, expw, expcnt);
    // 11a. expert swiglu, slots 0-127 (128-row mma)
    mma_gemm<3><<<dim3(I_ / 64, 1, E_), 256>>>(
        x2, H_, Wgu_e, 2 * I_, nullptr, actexp, I_, H_, exptok, nullptr, expcnt);
    // 11b. expert swiglu overflow slots 128..511 (32-row mma, early-exit)
    mma_gemm_s<3><<<dim3(I_ / 64, 12, E_), 256>>>(
        x2, H_, Wgu_e, 2 * I_, actexp, H_, exptok, nullptr, expcnt);
    // 12a. expert down + scatter, slots 0-127 (128-row mma)
    mma_gemm<4><<<dim3(H_ / 128, 1, E_), 256>>>(
        actexp, I_, Wd_e, H_, nullptr, out, H_, I_, exptok, expw, expcnt);
    // 12b. expert down overflow slots 128..511 (32-row mma, early-exit)
    mma_gemm_s<4><<<dim3(H_ / 128, 12, E_), 256>>>(
        actexp, I_, Wd_e, H_, out, I_, exptok, expw, expcnt);
}

// round 15
// speedup vs baseline: 2.2127x; 1.0796x over previous
#include <cuda_runtime.h>
#include <cstddef>
#include <cstdint>

#define S_    1024
#define H_    1024
#define HD_   64
#define NH_   16
#define KVH_  8
#define E_    64
#define TOPK_ 8
#define CAP_  512
#define I_    3072
#define QKVN_ 2048

// ---------------- static scratch ----------------
static const size_t OFF_X      = 0;
static const size_t OFF_QKV    = 1048576;
static const size_t OFF_Q      = 3145728;
static const size_t OFF_K      = 4194304;
static const size_t OFF_V      = 4718592;
static const size_t OFF_ATTN   = 5242880;
static const size_t OFF_H1     = 6291456;
static const size_t OFF_X2     = 7340032;
static const size_t OFF_ACTSH  = 8388608;
static const size_t OFF_W8     = 11599872;
static const size_t OFF_EXPW   = 11608064;
static const size_t OFF_ACTEXP = 11640832;
static const size_t FBUF_TOT   = 112304128;

static const size_t IOFF_IDX8   = 0;
static const size_t IOFF_EXPTOK = 8192;
static const size_t IOFF_EXPCNT = 40960;

__device__ float g_fbuf[FBUF_TOT];
__device__ int   g_ibuf[41028];

// pack two fp32 -> f16x2 word, round-to-nearest-even; lo = first arg
__device__ __forceinline__ uint32_t pack_f16(float lo, float hi) {
    uint32_t r;
    asm("cvt.rn.f16x2.f32 %0, %1, %2;" : "=r"(r) : "f"(hi), "f"(lo));
    return r;
}

__device__ __forceinline__ void mma_f16(float* c, const uint32_t* a, const uint32_t* b) {
    asm volatile(
        "mma.sync.aligned.m16n8k16.row.col.f32.f16.f16.f32 "
        "{%0,%1,%2,%3}, {%4,%5,%6,%7}, {%8,%9}, {%0,%1,%2,%3};"
        : "+f"(c[0]), "+f"(c[1]), "+f"(c[2]), "+f"(c[3])
        : "r"(a[0]), "r"(a[1]), "r"(a[2]), "r"(a[3]), "r"(b[0]), "r"(b[1]));
}

__device__ __forceinline__ void ldsm_x4(uint32_t* r, uint32_t addr) {
    asm volatile("ldmatrix.sync.aligned.m8n8.x4.shared.b16 {%0,%1,%2,%3}, [%4];"
        : "=r"(r[0]), "=r"(r[1]), "=r"(r[2]), "=r"(r[3]) : "r"(addr));
}

// ---------------- fp16 mma.sync GEMM (128x128, K-chunk 32, 2x4 warps, 2 CTA/SM) ------
// A smem: [2][128 rows][A2WS=28 words] (16 data words = 32 f16 per row)
// B smem: [2][16 kp][BWS=132 words]
#define A2WS 28
#define AWS  12
#define BWS  132

template<int MODE>
__global__ void __launch_bounds__(256, 2) mma_gemm(
    const float* __restrict__ A, int lda,
    const float* __restrict__ B, int ldb,
    const float* __restrict__ Dadd,
    float* __restrict__ out, int ldc, int Kdim,
    const int* __restrict__ etok, const float* __restrict__ ew,
    const int* __restrict__ ecnt) {
    constexpr bool IS_SWI = (MODE == 2 || MODE == 3);
    constexpr bool IS_EXP = (MODE == 3 || MODE == 4);

    int e = IS_EXP ? blockIdx.z : 0;
    int cnt = IS_EXP ? ecnt[e] : S_;
    if (IS_EXP) { int mx = 128 * gridDim.y; cnt = (cnt < mx) ? cnt : mx; }
    int row0 = blockIdx.y * 128;
    if (IS_EXP && row0 >= cnt) return;
    int bx = blockIdx.x;

    __shared__ uint32_t Aw[2][128 * A2WS];
    __shared__ uint32_t Bw[2][16 * BWS];
    __shared__ int   toks_s[128];
    __shared__ float ws_s[128];

    int tid = threadIdx.x;
    int wid = tid >> 5;
    int lane = tid & 31;
    int g = lane >> 2, t = lane & 3;
    int wm = wid & 1, wn = wid >> 1;

    const float* Ab = A;
    const float* Bb = B;
    float* outp = out;
    if (MODE == 3) { Bb = B + (size_t)e * H_ * 2 * I_; outp = out + (size_t)e * CAP_ * I_; }
    if (MODE == 4) { Ab = A + (size_t)e * CAP_ * I_; Bb = B + (size_t)e * I_ * H_; }

    if (IS_EXP && tid < 128) {
        int rr = row0 + tid;
        bool v = rr < cnt;
        toks_s[tid] = v ? etok[e * CAP_ + rr] : 0;
        ws_s[tid]   = v ? ew[e * CAP_ + rr] : 0.f;
    }
    if (IS_EXP) __syncthreads();

    // A: 4 float4 tasks/thread (2 per half): f4 = tid + 256*s, r = f4>>3, q = f4&7
    const float* arow_ptr[4];
    int aq[4];
#pragma unroll
    for (int s = 0; s < 4; s++) {
        int f4 = tid + 256 * s;
        int r = f4 >> 3; aq[s] = (f4 & 7) * 4;
        if (MODE == 3) arow_ptr[s] = A + (size_t)toks_s[r] * lda;
        else           arow_ptr[s] = Ab + (size_t)(row0 + r) * lda;
    }
    // B: 2 pack tasks/thread (1 per half): kp = tid>>5 (+8 for half 1), nq = tid&31
    int kp0 = tid >> 5, nq = tid & 31;
    int bcol;
    if (IS_SWI) bcol = (nq < 16) ? (bx * 64 + nq * 4) : (I_ + bx * 64 + (nq - 16) * 4);
    else        bcol = bx * 128 + nq * 4;
    const float* b_even0 = Bb + (size_t)(2 * kp0) * ldb + bcol;
    const float* b_odd0  = Bb + (size_t)(2 * kp0 + 1) * ldb + bcol;

    float4 aR[2], bE, bO;
    auto ldg = [&](int kt, int h) {
#pragma unroll
        for (int j = 0; j < 2; j++)
            aR[j] = *(const float4*)(arow_ptr[2 * h + j] + kt + aq[2 * h + j]);
        size_t roff = (size_t)(kt + 16 * h) * ldb;
        bE = *(const float4*)(b_even0 + roff);
        bO = *(const float4*)(b_odd0  + roff);
    };
    auto sts = [&](int buf, int h) {
#pragma unroll
        for (int j = 0; j < 2; j++) {
            int f4 = tid + 256 * (2 * h + j);
            int r = f4 >> 3, q = f4 & 7;
            uint2 w;
            w.x = pack_f16(aR[j].x, aR[j].y);
            w.y = pack_f16(aR[j].z, aR[j].w);
            *(uint2*)&Aw[buf][r * A2WS + 2 * q] = w;
        }
        uint4 wb;
        wb.x = pack_f16(bE.x, bO.x);
        wb.y = pack_f16(bE.y, bO.y);
        wb.z = pack_f16(bE.z, bO.z);
        wb.w = pack_f16(bE.w, bO.w);
        *(uint4*)&Bw[buf][(kp0 + 8 * h) * BWS + nq * 4] = wb;
    };

    // ldmatrix lane addressing
    uint32_t asmb[2];
    asmb[0] = (uint32_t)__cvta_generic_to_shared(&Aw[0][0]);
    asmb[1] = (uint32_t)__cvta_generic_to_shared(&Aw[1][0]);
    int rowoff = (lane & 7) + ((lane >> 3) & 1) * 8;
    int wordoff = (lane >> 4) * 4;
    uint32_t laneoff = (uint32_t)(rowoff * A2WS + wordoff) * 4u;

    float acc[4][4][4];
#pragma unroll
    for (int mi = 0; mi < 4; mi++)
#pragma unroll
        for (int ni = 0; ni < 4; ni++)
#pragma unroll
            for (int p = 0; p < 4; p++) acc[mi][ni][p] = 0.f;

    ldg(0, 0); sts(0, 0);
    ldg(0, 1); sts(0, 1);
    __syncthreads();

    int NC = Kdim / 32;
    for (int c = 0; c < NC; c++) {
        int cur = c & 1;
        int nxt = cur ^ 1;
        bool more = (c + 1 < NC);
        int ktn = (c + 1) * 32;

        if (more) ldg(ktn, 0);
        // sub-chunk kk = 0
        {
            uint32_t af[4][4], bf[4][2];
#pragma unroll
            for (int mi = 0; mi < 4; mi++)
                ldsm_x4(af[mi], asmb[cur] + (uint32_t)((wm * 64 + mi * 16) * A2WS) * 4u + laneoff);
#pragma unroll
            for (int ni = 0; ni < 4; ni++) {
                int n0;
                if (IS_SWI) n0 = (ni < 2) ? (wn * 16 + ni * 8) : (64 + wn * 16 + (ni - 2) * 8);
                else        n0 = wn * 32 + ni * 8;
                bf[ni][0] = Bw[cur][t * BWS + n0 + g];
                bf[ni][1] = Bw[cur][(t + 4) * BWS + n0 + g];
            }
#pragma unroll
            for (int mi = 0; mi < 4; mi++)
#pragma unroll
                for (int ni = 0; ni < 4; ni++)
                    mma_f16(acc[mi][ni], af[mi], bf[ni]);
        }
        if (more) { sts(nxt, 0); ldg(ktn, 1); }
        // sub-chunk kk = 1
        {
            uint32_t af[4][4], bf[4][2];
#pragma unroll
            for (int mi = 0; mi < 4; mi++)
                ldsm_x4(af[mi], asmb[cur] + (uint32_t)((wm * 64 + mi * 16) * A2WS) * 4u + laneoff + 32u);
#pragma unroll
            for (int ni = 0; ni < 4; ni++) {
                int n0;
                if (IS_SWI) n0 = (ni < 2) ? (wn * 16 + ni * 8) : (64 + wn * 16 + (ni - 2) * 8);
                else        n0 = wn * 32 + ni * 8;
                bf[ni][0] = Bw[cur][(8 + t) * BWS + n0 + g];
                bf[ni][1] = Bw[cur][(8 + t + 4) * BWS + n0 + g];
            }
#pragma unroll
            for (int mi = 0; mi < 4; mi++)
#pragma unroll
                for (int ni = 0; ni < 4; ni++)
                    mma_f16(acc[mi][ni], af[mi], bf[ni]);
        }
        if (more) sts(nxt, 1);
        __syncthreads();
    }

    // ---------------- epilogue ----------------
    if (MODE == 0 || MODE == 1) {
#pragma unroll
        for (int mi = 0; mi < 4; mi++) {
            int r = row0 + wm * 64 + mi * 16 + g;
#pragma unroll
            for (int ni = 0; ni < 4; ni++) {
                int col = bx * 128 + wn * 32 + ni * 8 + 2 * t;
                float2 v0 = make_float2(acc[mi][ni][0], acc[mi][ni][1]);
                float2 v1 = make_float2(acc[mi][ni][2], acc[mi][ni][3]);
                if (MODE == 1) {
                    float2 d0 = *(const float2*)(Dadd + (size_t)r * ldc + col);
                    float2 d1 = *(const float2*)(Dadd + (size_t)(r + 8) * ldc + col);
                    v0.x += d0.x; v0.y += d0.y; v1.x += d1.x; v1.y += d1.y;
                }
                *(float2*)(outp + (size_t)r * ldc + col) = v0;
                *(float2*)(outp + (size_t)(r + 8) * ldc + col) = v1;
            }
        }
    } else if (IS_SWI) {
#pragma unroll
        for (int mi = 0; mi < 4; mi++) {
            int r = row0 + wm * 64 + mi * 16 + g;
#pragma unroll
            for (int ni = 0; ni < 2; ni++) {
                int col = bx * 64 + wn * 16 + ni * 8 + 2 * t;
#pragma unroll
                for (int h = 0; h < 2; h++) {
                    int rg = r + 8 * h;
                    if (MODE == 3 && rg >= cnt) continue;
                    float gg0 = acc[mi][ni][2 * h + 0], gg1 = acc[mi][ni][2 * h + 1];
                    float uu0 = acc[mi][ni + 2][2 * h + 0], uu1 = acc[mi][ni + 2][2 * h + 1];
                    float s0 = 1.f / (1.f + __expf(-uu0));
                    float s1 = 1.f / (1.f + __expf(-uu1));
                    float2 v = make_float2(gg0 * uu0 * s0, gg1 * uu1 * s1);
                    *(float2*)(outp + (size_t)rg * I_ + col) = v;
                }
            }
        }
    } else {  // MODE 4
#pragma unroll
        for (int mi = 0; mi < 4; mi++) {
            int rl = wm * 64 + mi * 16 + g;
#pragma unroll
            for (int h = 0; h < 2; h++) {
                int rr = rl + 8 * h;
                if (row0 + rr >= cnt) continue;
                int tok = toks_s[rr];
                float wv = ws_s[rr];
#pragma unroll
                for (int ni = 0; ni < 4; ni++) {
                    int col = bx * 128 + wn * 32 + ni * 8 + 2 * t;
                    atomicAdd(out + (size_t)tok * H_ + col,     acc[mi][ni][2 * h + 0] * wv);
                    atomicAdd(out + (size_t)tok * H_ + col + 1, acc[mi][ni][2 * h + 1] * wv);
                }
            }
        }
    }
}

// ---------------- small-M (32-row) fp16 expert mma kernel for overflow slots ----------
template<int MODE>
__global__ void __launch_bounds__(256, 2) mma_gemm_s(
    const float* __restrict__ A, int lda,
    const float* __restrict__ B, int ldb,
    float* __restrict__ out, int Kdim,
    const int* __restrict__ etok, const float* __restrict__ ew,
    const int* __restrict__ ecnt) {
    constexpr bool IS_SWI = (MODE == 3);

    int e = blockIdx.z;
    int cnt = ecnt[e];
    int row0 = 128 + blockIdx.y * 32;
    if (row0 >= cnt) return;
    int bx = blockIdx.x;

    __shared__ uint32_t Aw[2][32 * AWS];
    __shared__ uint32_t Bw[2][8 * BWS];
    __shared__ int   toks_s[32];
    __shared__ float ws_s[32];

    int tid = threadIdx.x;
    int wid = tid >> 5;
    int lane = tid & 31;
    int g = lane >> 2, t = lane & 3;
    int wn = wid;

    const float* Ab = A;
    const float* Bb = B;
    float* outp = out;
    if (MODE == 3) { Bb = B + (size_t)e * H_ * 2 * I_; outp = out + (size_t)e * CAP_ * I_; }
    if (MODE == 4) { Ab = A + (size_t)e * CAP_ * I_; Bb = B + (size_t)e * I_ * H_; }

    if (tid < 32) {
        int rr = row0 + tid;
        bool v = rr < cnt;
        toks_s[tid] = v ? etok[e * CAP_ + rr] : 0;
        ws_s[tid]   = v ? ew[e * CAP_ + rr] : 0.f;
    }
    __syncthreads();

    const float* arow_ptr = nullptr;
    int aq = 0;
    if (tid < 128) {
        int r = tid >> 2; aq = (tid & 3) * 4;
        if (MODE == 3) arow_ptr = A + (size_t)toks_s[r] * lda;
        else           arow_ptr = Ab + (size_t)(row0 + r) * lda;
    }
    int kp = tid >> 5, nq = tid & 31;
    int bcol;
    if (IS_SWI) bcol = (nq < 16) ? (bx * 64 + nq * 4) : (I_ + bx * 64 + (nq - 16) * 4);
    else        bcol = bx * 128 + nq * 4;
    const float* b_even = Bb + (size_t)(2 * kp) * ldb + bcol;
    const float* b_odd  = Bb + (size_t)(2 * kp + 1) * ldb + bcol;

    float4 aR, bE, bO;
    auto ldg = [&](int kt) {
        if (tid < 128) aR = *(const float4*)(arow_ptr + kt + aq);
        bE = *(const float4*)(b_even + (size_t)kt * ldb);
        bO = *(const float4*)(b_odd  + (size_t)kt * ldb);
    };
    auto sts = [&](int buf) {
        if (tid < 128) {
            int r = tid >> 2, q = tid & 3;
            uint2 w;
            w.x = pack_f16(aR.x, aR.y);
            w.y = pack_f16(aR.z, aR.w);
            *(uint2*)&Aw[buf][r * AWS + 2 * q] = w;
        }
        uint4 wb;
        wb.x = pack_f16(bE.x, bO.x);
        wb.y = pack_f16(bE.y, bO.y);
        wb.z = pack_f16(bE.z, bO.z);
        wb.w = pack_f16(bE.w, bO.w);
        *(uint4*)&Bw[buf][kp * BWS + nq * 4] = wb;
    };

    uint32_t asmb[2];
    asmb[0] = (uint32_t)__cvta_generic_to_shared(&Aw[0][0]);
    asmb[1] = (uint32_t)__cvta_generic_to_shared(&Aw[1][0]);
    int rowoff = (lane & 7) + ((lane >> 3) & 1) * 8;
    int wordoff = (lane >> 4) * 4;
    uint32_t laneoff = (uint32_t)(rowoff * AWS + wordoff) * 4u;

    float acc[2][2][4];
#pragma unroll
    for (int mi = 0; mi < 2; mi++)
#pragma unroll
        for (int ni = 0; ni < 2; ni++)
#pragma unroll
            for (int p = 0; p < 4; p++) acc[mi][ni][p] = 0.f;

    ldg(0); sts(0);
    __syncthreads();

    int NC = Kdim / 16;
    for (int c = 0; c < NC; c++) {
        int cur = c & 1;
        if (c + 1 < NC) ldg((c + 1) * 16);
        {
            uint32_t af[2][4], bf[2][2];
#pragma unroll
            for (int mi = 0; mi < 2; mi++)
                ldsm_x4(af[mi], asmb[cur] + (uint32_t)((mi * 16) * AWS) * 4u + laneoff);
#pragma unroll
            for (int ni = 0; ni < 2; ni++) {
                int n0;
                if (IS_SWI) n0 = (ni == 0) ? (wn * 8) : (64 + wn * 8);
                else        n0 = wn * 16 + ni * 8;
                bf[ni][0] = Bw[cur][t * BWS + n0 + g];
                bf[ni][1] = Bw[cur][(t + 4) * BWS + n0 + g];
            }
#pragma unroll
            for (int mi = 0; mi < 2; mi++)
#pragma unroll
                for (int ni = 0; ni < 2; ni++)
                    mma_f16(acc[mi][ni], af[mi], bf[ni]);
        }
        if (c + 1 < NC) sts(cur ^ 1);
        __syncthreads();
    }

    if (MODE == 3) {
#pragma unroll
        for (int mi = 0; mi < 2; mi++) {
            int col = bx * 64 + wn * 8 + 2 * t;
#pragma unroll
            for (int h = 0; h < 2; h++) {
                int rl = mi * 16 + g + 8 * h;
                int rg = row0 + rl;
                if (rg >= cnt) continue;
                float gg0 = acc[mi][0][2 * h + 0], gg1 = acc[mi][0][2 * h + 1];
                float uu0 = acc[mi][1][2 * h + 0], uu1 = acc[mi][1][2 * h + 1];
                float s0 = 1.f / (1.f + __expf(-uu0));
                float s1 = 1.f / (1.f + __expf(-uu1));
                float2 v = make_float2(gg0 * uu0 * s0, gg1 * uu1 * s1);
                *(float2*)(outp + (size_t)rg * I_ + col) = v;
            }
        }
    } else {
#pragma unroll
        for (int mi = 0; mi < 2; mi++) {
#pragma unroll
            for (int h = 0; h < 2; h++) {
                int rl = mi * 16 + g + 8 * h;
                if (row0 + rl >= cnt) continue;
                int tok = toks_s[rl];
                float wv = ws_s[rl];
#pragma unroll
                for (int ni = 0; ni < 2; ni++) {
                    int col = bx * 128 + wn * 16 + ni * 8 + 2 * t;
                    atomicAdd(out + (size_t)tok * H_ + col,     acc[mi][ni][2 * h + 0] * wv);
                    atomicAdd(out + (size_t)tok * H_ + col + 1, acc[mi][ni][2 * h + 1] * wv);
                }
            }
        }
    }
}

// ---------------- RMSNorm ----------------
__global__ void rmsnorm_kernel(const float* __restrict__ in, const float* __restrict__ w,
                               float* __restrict__ out) {
    int row = blockIdx.x, tid = threadIdx.x;
    const float* x = in + (size_t)row * H_;
    float s = 0.f;
    for (int i = tid; i < H_; i += 256) { float v = x[i]; s += v * v; }
    __shared__ float red[256];
    red[tid] = s; __syncthreads();
    for (int o = 128; o > 0; o >>= 1) { if (tid < o) red[tid] += red[tid + o]; __syncthreads(); }
    float sc = rsqrtf(red[0] * (1.f / H_) + 1e-6f);
    for (int i = tid; i < H_; i += 256) out[(size_t)row * H_ + i] = x[i] * sc * w[i];
}

// ---------------- QKV postprocess ----------------
__global__ void qkvproc_kernel(const float* __restrict__ qkv, const float* __restrict__ cosb,
                               const float* __restrict__ sinb, const float* __restrict__ qnw,
                               const float* __restrict__ knw, float* __restrict__ q,
                               float* __restrict__ k, float* __restrict__ v) {
    int s = blockIdx.x, tid = threadIdx.x;
    int w = tid >> 5, lane = tid & 31;
#pragma unroll
    for (int p = 0; p < 4; p++) {
        int r = w + 8 * p;
        int kv = r >> 2, slot = r & 3;
        int base = s * QKVN_ + kv * 256 + slot * 64;
        int d0 = lane * 2, d1 = d0 + 1;
        float x0 = qkv[base + d0], x1 = qkv[base + d1];
        float y0, y1;
        if (slot == 3) { y0 = x0; y1 = x1; }
        else {
            float p0 = __shfl_xor_sync(0xffffffffu, x0, 16);
            float p1 = __shfl_xor_sync(0xffffffffu, x1, 16);
            float rh0 = (lane < 16) ? -p0 : p0;
            float rh1 = (lane < 16) ? -p1 : p1;
            float c0 = cosb[s * HD_ + d0], s0 = sinb[s * HD_ + d0];
            float c1 = cosb[s * HD_ + d1], s1 = sinb[s * HD_ + d1];
            y0 = x0 * c0 + rh0 * s0;
            y1 = x1 * c1 + rh1 * s1;
            float ss = y0 * y0 + y1 * y1;
            for (int off = 16; off > 0; off >>= 1) ss += __shfl_xor_sync(0xffffffffu, ss, off);
            float scn = rsqrtf(ss * (1.f / HD_) + 1e-6f);
            const float* wn = (slot < 2) ? qnw : knw;
            y0 = y0 * scn * wn[d0];
            y1 = y1 * scn * wn[d1];
        }
        if (slot < 2) {
            int hh = kv * 2 + slot;
            size_t off = ((size_t)hh * S_ + s) * HD_;
            q[off + d0] = y0; q[off + d1] = y1;
        } else if (slot == 2) {
            size_t off = ((size_t)kv * S_ + s) * HD_;
            k[off + d0] = y0; k[off + d1] = y1;
        } else {
            size_t off = ((size_t)kv * S_ + s) * HD_;
            v[off + d0] = y0; v[off + d1] = y1;
        }
    }
}

// ---------------- flash attention, fp16 mma (BQ=64, BK=32, 128 threads) ----------------
#define AQW 36
#define KWS 36
#define VWS 72

__global__ void __launch_bounds__(128) attn_kernel(const float* __restrict__ qg,
                                                   const float* __restrict__ kg,
                                                   const float* __restrict__ vg,
                                                   float* __restrict__ attn) {
    int qt = blockIdx.x, h = blockIdx.y;
    int q0 = qt * 64;
    const float* Q = qg + ((size_t)h * S_ + q0) * HD_;
    const float* Kp = kg + ((size_t)(h >> 1) * S_) * HD_;
    const float* Vp = vg + ((size_t)(h >> 1) * S_) * HD_;

    __shared__ uint32_t Qw[64 * AQW];
    __shared__ uint32_t Kw[32 * KWS];
    __shared__ uint32_t Vw[16 * VWS];

    int tid = threadIdx.x;
    int wid = tid >> 5;
    int lane = tid & 31;
    int g = lane >> 2, t = lane & 3;
    int m0 = wid * 16;

    for (int i = tid; i < 1024; i += 128) {
        int row = i >> 4, qq = i & 15;
        float4 v = *(const float4*)(Q + (size_t)row * HD_ + qq * 4);
        uint2 w;
        w.x = pack_f16(v.x, v.y);
        w.y = pack_f16(v.z, v.w);
        *(uint2*)&Qw[row * AQW + qq * 2] = w;
    }

    float acc_o[8][4];
#pragma unroll
    for (int i = 0; i < 8; i++)
#pragma unroll
        for (int p = 0; p < 4; p++) acc_o[i][p] = 0.f;
    float m[2] = {-1e30f, -1e30f};
    float l[2] = {0.f, 0.f};

    int nkt = (q0 + 64) / 32;
    for (int kt = 0; kt < nkt; kt++) {
        int k0 = kt * 32;
        __syncthreads();
        for (int i = tid; i < 512; i += 128) {
            int key = i >> 4, qq = i & 15;
            float4 v = *(const float4*)(Kp + (size_t)(k0 + key) * HD_ + qq * 4);
            uint2 w;
            w.x = pack_f16(v.x, v.y);
            w.y = pack_f16(v.z, v.w);
            *(uint2*)&Kw[key * KWS + qq * 2] = w;
        }
        for (int i = tid; i < 256; i += 128) {
            int kp = i >> 4, qq = i & 15;
            float4 ve = *(const float4*)(Vp + (size_t)(k0 + 2 * kp) * HD_ + qq * 4);
            float4 vo = *(const float4*)(Vp + (size_t)(k0 + 2 * kp + 1) * HD_ + qq * 4);
            uint4 w;
            w.x = pack_f16(ve.x, vo.x);
            w.y = pack_f16(ve.y, vo.y);
            w.z = pack_f16(ve.z, vo.z);
            w.w = pack_f16(ve.w, vo.w);
            *(uint4*)&Vw[kp * VWS + qq * 4] = w;
        }
        __syncthreads();

        float sc[4][4];
#pragma unroll
        for (int ni = 0; ni < 4; ni++)
#pragma unroll
            for (int p = 0; p < 4; p++) sc[ni][p] = 0.f;
#pragma unroll
        for (int ck = 0; ck < 4; ck++) {
            uint32_t a[4];
            a[0] = Qw[(m0 + g) * AQW + ck * 8 + t];
            a[1] = Qw[(m0 + g + 8) * AQW + ck * 8 + t];
            a[2] = Qw[(m0 + g) * AQW + ck * 8 + t + 4];
            a[3] = Qw[(m0 + g + 8) * AQW + ck * 8 + t + 4];
#pragma unroll
            for (int ni = 0; ni < 4; ni++) {
                uint32_t b[2];
                b[0] = Kw[(ni * 8 + g) * KWS + ck * 8 + t];
                b[1] = Kw[(ni * 8 + g) * KWS + ck * 8 + t + 4];
                mma_f16(sc[ni], a, b);
            }
        }

#pragma unroll
        for (int h2 = 0; h2 < 2; h2++) {
            int row = q0 + m0 + g + 8 * h2;
            float mloc = -1e30f;
#pragma unroll
            for (int ni = 0; ni < 4; ni++)
#pragma unroll
                for (int p2 = 0; p2 < 2; p2++) {
                    int col = k0 + ni * 8 + 2 * t + p2;
                    float v = (col > row) ? -1e30f : sc[ni][2 * h2 + p2] * 0.125f;
                    sc[ni][2 * h2 + p2] = v;
                    mloc = fmaxf(mloc, v);
                }
            mloc = fmaxf(mloc, __shfl_xor_sync(0xffffffffu, mloc, 1));
            mloc = fmaxf(mloc, __shfl_xor_sync(0xffffffffu, mloc, 2));
            float mn = fmaxf(m[h2], mloc);
            float corr = __expf(m[h2] - mn);
            float rs = 0.f;
#pragma unroll
            for (int ni = 0; ni < 4; ni++)
#pragma unroll
                for (int p2 = 0; p2 < 2; p2++) {
                    float v = sc[ni][2 * h2 + p2];
                    float pv = (v <= -1e29f) ? 0.f : __expf(v - mn);
                    sc[ni][2 * h2 + p2] = pv;
                    rs += pv;
                }
            rs += __shfl_xor_sync(0xffffffffu, rs, 1);
            rs += __shfl_xor_sync(0xffffffffu, rs, 2);
            l[h2] = l[h2] * corr + rs;
            m[h2] = mn;
#pragma unroll
            for (int ni = 0; ni < 8; ni++) {
                acc_o[ni][2 * h2 + 0] *= corr;
                acc_o[ni][2 * h2 + 1] *= corr;
            }
        }

        uint32_t pa[2][4];
#pragma unroll
        for (int c = 0; c < 2; c++) {
            pa[c][0] = pack_f16(sc[2 * c][0], sc[2 * c][1]);
            pa[c][1] = pack_f16(sc[2 * c][2], sc[2 * c][3]);
            pa[c][2] = pack_f16(sc[2 * c + 1][0], sc[2 * c + 1][1]);
            pa[c][3] = pack_f16(sc[2 * c + 1][2], sc[2 * c + 1][3]);
        }
#pragma unroll
        for (int no = 0; no < 8; no++) {
#pragma unroll
            for (int c = 0; c < 2; c++) {
                uint32_t b[2];
                b[0] = Vw[(c * 8 + t) * VWS + no * 8 + g];
                b[1] = Vw[(c * 8 + t + 4) * VWS + no * 8 + g];
                mma_f16(acc_o[no], pa[c], b);
            }
        }
    }

#pragma unroll
    for (int h2 = 0; h2 < 2; h2++) {
        float inv = 1.f / l[h2];
        int row = q0 + m0 + g + 8 * h2;
#pragma unroll
        for (int no = 0; no < 8; no++) {
            float2 v = make_float2(acc_o[no][2 * h2 + 0] * inv, acc_o[no][2 * h2 + 1] * inv);
            *(float2*)(attn + (size_t)row * H_ + h * HD_ + no * 8 + 2 * t) = v;
        }
    }
}

// ---------------- gate + top-8 ----------------
__global__ void gate_topk_kernel(const float* __restrict__ x2, const float* __restrict__ Wg,
                                 float* __restrict__ w8, int* __restrict__ idx8) {
    int tt = blockIdx.x, tid = threadIdx.x;
    const float* xr = x2 + (size_t)tt * H_;
    float a0 = 0.f, a1 = 0.f, a2 = 0.f, a3 = 0.f;
    for (int h = 0; h < H_; h += 4) {
        a0 = fmaf(xr[h],     Wg[(size_t)h * E_ + tid],       a0);
        a1 = fmaf(xr[h + 1], Wg[(size_t)(h + 1) * E_ + tid], a1);
        a2 = fmaf(xr[h + 2], Wg[(size_t)(h + 2) * E_ + tid], a2);
        a3 = fmaf(xr[h + 3], Wg[(size_t)(h + 3) * E_ + tid], a3);
    }
    float logit = (a0 + a1) + (a2 + a3);
    __shared__ float red[64];
    __shared__ float gv[64];
    red[tid] = logit; __syncthreads();
    for (int o = 32; o > 0; o >>= 1) { if (tid < o) red[tid] = fmaxf(red[tid], red[tid + o]); __syncthreads(); }
    float mx = red[0]; __syncthreads();
    float ex = __expf(logit - mx);
    red[tid] = ex; __syncthreads();
    for (int o = 32; o > 0; o >>= 1) { if (tid < o) red[tid] += red[tid + o]; __syncthreads(); }
    float sum = red[0];
    gv[tid] = ex / sum; __syncthreads();
    if (tid == 0) {
        bool used[E_];
        for (int e = 0; e < E_; e++) used[e] = false;
        float wv[TOPK_]; int id[TOPK_]; float wsum = 0.f;
        for (int r = 0; r < TOPK_; r++) {
            int best = 0; float bv = -1e30f;
            for (int e = 0; e < E_; e++)
                if (!used[e] && gv[e] > bv) { bv = gv[e]; best = e; }
            used[best] = true; wv[r] = bv; id[r] = best; wsum += bv;
        }
        wsum = fmaxf(wsum, 1.1920929e-07f);
        for (int r = 0; r < TOPK_; r++) {
            w8[tt * TOPK_ + r] = wv[r] / wsum;
            idx8[tt * TOPK_ + r] = id[r];
        }
    }
}

// ---------------- routing ----------------
__global__ void route_kernel(const int* __restrict__ idx8, const float* __restrict__ w8,
                             int* __restrict__ etok, float* __restrict__ ew, int* __restrict__ ecnt) {
    int e = blockIdx.x, lane = threadIdx.x;
    int cnt = 0;
    for (int base = 0; base < S_ * TOPK_; base += 32) {
        int j = base + lane;
        int ee = idx8[j];
        bool match = (ee == e);
        unsigned bal = __ballot_sync(0xffffffffu, match);
        int pre = __popc(bal & ((1u << lane) - 1u));
        if (match) {
            int p = cnt + pre;
            if (p < CAP_) {
                etok[e * CAP_ + p] = j >> 3;
                ew[e * CAP_ + p] = w8[j];
            }
        }
        cnt += __popc(bal);
    }
    if (lane == 0) ecnt[e] = (cnt < CAP_) ? cnt : CAP_;
}

// ---------------- launch ----------------
extern "C" void kernel_launch(void* const* d_in, const int* in_sizes, int n_in,
                              void* d_out, int out_size) {
    (void)in_sizes; (void)n_in; (void)out_size;
    const float* hidden = (const float*)d_in[0];
    const float* cosb   = (const float*)d_in[1];
    const float* sinb   = (const float*)d_in[2];
    const float* ln1    = (const float*)d_in[3];
    const float* ln2    = (const float*)d_in[4];
    const float* Wqkv   = (const float*)d_in[5];
    const float* Wo     = (const float*)d_in[6];
    const float* qnw    = (const float*)d_in[7];
    const float* knw    = (const float*)d_in[8];
    const float* Wgu_sh = (const float*)d_in[9];
    const float* Wd_sh  = (const float*)d_in[10];
    const float* Wgate  = (const float*)d_in[11];
    const float* Wgu_e  = (const float*)d_in[12];
    const float* Wd_e   = (const float*)d_in[13];
    float* out = (float*)d_out;

    float* fb = nullptr; int* ib = nullptr;
    cudaGetSymbolAddress((void**)&fb, g_fbuf);
    cudaGetSymbolAddress((void**)&ib, g_ibuf);

    float* x      = fb + OFF_X;
    float* qkv    = fb + OFF_QKV;
    float* q      = fb + OFF_Q;
    float* k      = fb + OFF_K;
    float* v      = fb + OFF_V;
    float* attn   = fb + OFF_ATTN;
    float* h1     = fb + OFF_H1;
    float* x2     = fb + OFF_X2;
    float* actsh  = fb + OFF_ACTSH;
    float* w8     = fb + OFF_W8;
    float* expw   = fb + OFF_EXPW;
    float* actexp = fb + OFF_ACTEXP;
    int* idx8   = ib + IOFF_IDX8;
    int* exptok = ib + IOFF_EXPTOK;
    int* expcnt = ib + IOFF_EXPCNT;

    // 1. x = rmsnorm(hidden, ln1)
    rmsnorm_kernel<<<S_, 256>>>(hidden, ln1, x);
    // 2. qkv = x @ Wqkv
    mma_gemm<0><<<dim3(QKVN_ / 128, S_ / 128), 256>>>(
        x, H_, Wqkv, QKVN_, nullptr, qkv, QKVN_, H_, nullptr, nullptr, nullptr);
    // 3. RoPE + QK-norm
    qkvproc_kernel<<<S_, 256>>>(qkv, cosb, sinb, qnw, knw, q, k, v);
    // 4. attention (fp16 mma)
    attn_kernel<<<dim3(S_ / 64, NH_), 128>>>(q, k, v, attn);
    // 5. h1 = attn @ Wo + hidden
    mma_gemm<1><<<dim3(H_ / 128, S_ / 128), 256>>>(
        attn, H_, Wo, H_, hidden, h1, H_, H_, nullptr, nullptr, nullptr);
    // 6. x2 = rmsnorm(h1, ln2)
    rmsnorm_kernel<<<S_, 256>>>(h1, ln2, x2);
    // 7. shared swiglu activation
    mma_gemm<2><<<dim3(I_ / 64, S_ / 128), 256>>>(
        x2, H_, Wgu_sh, 2 * I_, nullptr, actsh, I_, H_, nullptr, nullptr, nullptr);
    // 8. out = actsh @ Wd_sh + h1
    mma_gemm<1><<<dim3(H_ / 128, S_ / 128), 256>>>(
        actsh, I_, Wd_sh, H_, h1, out, H_, I_, nullptr, nullptr, nullptr);
    // 9. gate + top-8
    gate_topk_kernel<<<S_, 64>>>(x2, Wgate, w8, idx8);
    // 10. routing
    route_kernel<<<E_, 32>>>(idx8, w8, exptok, expw, expcnt);
    // 11a. expert swiglu, slots 0-127 (128-row mma)
    mma_gemm<3><<<dim3(I_ / 64, 1, E_), 256>>>(
        x2, H_, Wgu_e, 2 * I_, nullptr, actexp, I_, H_, exptok, nullptr, expcnt);
    // 11b. expert swiglu overflow slots 128..511 (32-row mma, early-exit)
    mma_gemm_s<3><<<dim3(I_ / 64, 12, E_), 256>>>(
        x2, H_, Wgu_e, 2 * I_, actexp, H_, exptok, nullptr, expcnt);
    // 12a. expert down + scatter, slots 0-127 (128-row mma)
    mma_gemm<4><<<dim3(H_ / 128, 1, E_), 256>>>(
        actexp, I_, Wd_e, H_, nullptr, out, H_, I_, exptok, expw, expcnt);
    // 12b. expert down overflow slots 128..511 (32-row mma, early-exit)
    mma_gemm_s<4><<<dim3(H_ / 128, 12, E_), 256>>>(
        actexp, I_, Wd_e, H_, out, I_, exptok, expw, expcnt);
}

// round 16
// speedup vs baseline: 2.2460x; 1.0151x over previous
#include <cuda_runtime.h>
#include <cstddef>
#include <cstdint>

#define S_    1024
#define H_    1024
#define HD_   64
#define NH_   16
#define KVH_  8
#define E_    64
#define TOPK_ 8
#define CAP_  512
#define I_    3072
#define QKVN_ 2048

// ---------------- static scratch ----------------
static const size_t OFF_X      = 0;
static const size_t OFF_QKV    = 1048576;
static const size_t OFF_Q      = 3145728;
static const size_t OFF_K      = 4194304;
static const size_t OFF_V      = 4718592;
static const size_t OFF_ATTN   = 5242880;
static const size_t OFF_H1     = 6291456;
static const size_t OFF_X2     = 7340032;
static const size_t OFF_ACTSH  = 8388608;
static const size_t OFF_W8     = 11599872;
static const size_t OFF_EXPW   = 11608064;
static const size_t OFF_ACTEXP = 11640832;   // attn partials reuse head of this region
static const size_t FBUF_TOT   = 112304128;

static const size_t IOFF_IDX8   = 0;
static const size_t IOFF_EXPTOK = 8192;
static const size_t IOFF_EXPCNT = 40960;

__device__ float g_fbuf[FBUF_TOT];
__device__ int   g_ibuf[41028];

// pack two fp32 -> f16x2 word, round-to-nearest-even; lo = first arg
__device__ __forceinline__ uint32_t pack_f16(float lo, float hi) {
    uint32_t r;
    asm("cvt.rn.f16x2.f32 %0, %1, %2;" : "=r"(r) : "f"(hi), "f"(lo));
    return r;
}

__device__ __forceinline__ void mma_f16(float* c, const uint32_t* a, const uint32_t* b) {
    asm volatile(
        "mma.sync.aligned.m16n8k16.row.col.f32.f16.f16.f32 "
        "{%0,%1,%2,%3}, {%4,%5,%6,%7}, {%8,%9}, {%0,%1,%2,%3};"
        : "+f"(c[0]), "+f"(c[1]), "+f"(c[2]), "+f"(c[3])
        : "r"(a[0]), "r"(a[1]), "r"(a[2]), "r"(a[3]), "r"(b[0]), "r"(b[1]));
}

__device__ __forceinline__ void ldsm_x4(uint32_t* r, uint32_t addr) {
    asm volatile("ldmatrix.sync.aligned.m8n8.x4.shared.b16 {%0,%1,%2,%3}, [%4];"
        : "=r"(r[0]), "=r"(r[1]), "=r"(r[2]), "=r"(r[3]) : "r"(addr));
}

// ---------------- fp16 mma.sync GEMM (128x128, K-chunk 32, 2x4 warps, 2 CTA/SM) ------
#define A2WS 28
#define AWS  12
#define BWS  132

template<int MODE>
__global__ void __launch_bounds__(256, 2) mma_gemm(
    const float* __restrict__ A, int lda,
    const float* __restrict__ B, int ldb,
    const float* __restrict__ Dadd,
    float* __restrict__ out, int ldc, int Kdim,
    const int* __restrict__ etok, const float* __restrict__ ew,
    const int* __restrict__ ecnt) {
    constexpr bool IS_SWI = (MODE == 2 || MODE == 3);
    constexpr bool IS_EXP = (MODE == 3 || MODE == 4);

    int e = IS_EXP ? blockIdx.z : 0;
    int cnt = IS_EXP ? ecnt[e] : S_;
    if (IS_EXP) { int mx = 128 * gridDim.y; cnt = (cnt < mx) ? cnt : mx; }
    int row0 = blockIdx.y * 128;
    if (IS_EXP && row0 >= cnt) return;
    int bx = blockIdx.x;

    __shared__ uint32_t Aw[2][128 * A2WS];
    __shared__ uint32_t Bw[2][16 * BWS];
    __shared__ int   toks_s[128];
    __shared__ float ws_s[128];

    int tid = threadIdx.x;
    int wid = tid >> 5;
    int lane = tid & 31;
    int g = lane >> 2, t = lane & 3;
    int wm = wid & 1, wn = wid >> 1;

    const float* Ab = A;
    const float* Bb = B;
    float* outp = out;
    if (MODE == 3) { Bb = B + (size_t)e * H_ * 2 * I_; outp = out + (size_t)e * CAP_ * I_; }
    if (MODE == 4) { Ab = A + (size_t)e * CAP_ * I_; Bb = B + (size_t)e * I_ * H_; }

    if (IS_EXP && tid < 128) {
        int rr = row0 + tid;
        bool v = rr < cnt;
        toks_s[tid] = v ? etok[e * CAP_ + rr] : 0;
        ws_s[tid]   = v ? ew[e * CAP_ + rr] : 0.f;
    }
    if (IS_EXP) __syncthreads();

    const float* arow_ptr[4];
    int aq[4];
#pragma unroll
    for (int s = 0; s < 4; s++) {
        int f4 = tid + 256 * s;
        int r = f4 >> 3; aq[s] = (f4 & 7) * 4;
        if (MODE == 3) arow_ptr[s] = A + (size_t)toks_s[r] * lda;
        else           arow_ptr[s] = Ab + (size_t)(row0 + r) * lda;
    }
    int kp0 = tid >> 5, nq = tid & 31;
    int bcol;
    if (IS_SWI) bcol = (nq < 16) ? (bx * 64 + nq * 4) : (I_ + bx * 64 + (nq - 16) * 4);
    else        bcol = bx * 128 + nq * 4;
    const float* b_even0 = Bb + (size_t)(2 * kp0) * ldb + bcol;
    const float* b_odd0  = Bb + (size_t)(2 * kp0 + 1) * ldb + bcol;

    float4 aR[2], bE, bO;
    auto ldg = [&](int kt, int h) {
#pragma unroll
        for (int j = 0; j < 2; j++)
            aR[j] = *(const float4*)(arow_ptr[2 * h + j] + kt + aq[2 * h + j]);
        size_t roff = (size_t)(kt + 16 * h) * ldb;
        bE = *(const float4*)(b_even0 + roff);
        bO = *(const float4*)(b_odd0  + roff);
    };
    auto sts = [&](int buf, int h) {
#pragma unroll
        for (int j = 0; j < 2; j++) {
            int f4 = tid + 256 * (2 * h + j);
            int r = f4 >> 3, q = f4 & 7;
            uint2 w;
            w.x = pack_f16(aR[j].x, aR[j].y);
            w.y = pack_f16(aR[j].z, aR[j].w);
            *(uint2*)&Aw[buf][r * A2WS + 2 * q] = w;
        }
        uint4 wb;
        wb.x = pack_f16(bE.x, bO.x);
        wb.y = pack_f16(bE.y, bO.y);
        wb.z = pack_f16(bE.z, bO.z);
        wb.w = pack_f16(bE.w, bO.w);
        *(uint4*)&Bw[buf][(kp0 + 8 * h) * BWS + nq * 4] = wb;
    };

    uint32_t asmb[2];
    asmb[0] = (uint32_t)__cvta_generic_to_shared(&Aw[0][0]);
    asmb[1] = (uint32_t)__cvta_generic_to_shared(&Aw[1][0]);
    int rowoff = (lane & 7) + ((lane >> 3) & 1) * 8;
    int wordoff = (lane >> 4) * 4;
    uint32_t laneoff = (uint32_t)(rowoff * A2WS + wordoff) * 4u;

    float acc[4][4][4];
#pragma unroll
    for (int mi = 0; mi < 4; mi++)
#pragma unroll
        for (int ni = 0; ni < 4; ni++)
#pragma unroll
            for (int p = 0; p < 4; p++) acc[mi][ni][p] = 0.f;

    ldg(0, 0); sts(0, 0);
    ldg(0, 1); sts(0, 1);
    __syncthreads();

    int NC = Kdim / 32;
    for (int c = 0; c < NC; c++) {
        int cur = c & 1;
        int nxt = cur ^ 1;
        bool more = (c + 1 < NC);
        int ktn = (c + 1) * 32;

        if (more) ldg(ktn, 0);
        {
            uint32_t af[4][4], bf[4][2];
#pragma unroll
            for (int mi = 0; mi < 4; mi++)
                ldsm_x4(af[mi], asmb[cur] + (uint32_t)((wm * 64 + mi * 16) * A2WS) * 4u + laneoff);
#pragma unroll
            for (int ni = 0; ni < 4; ni++) {
                int n0;
                if (IS_SWI) n0 = (ni < 2) ? (wn * 16 + ni * 8) : (64 + wn * 16 + (ni - 2) * 8);
                else        n0 = wn * 32 + ni * 8;
                bf[ni][0] = Bw[cur][t * BWS + n0 + g];
                bf[ni][1] = Bw[cur][(t + 4) * BWS + n0 + g];
            }
#pragma unroll
            for (int mi = 0; mi < 4; mi++)
#pragma unroll
                for (int ni = 0; ni < 4; ni++)
                    mma_f16(acc[mi][ni], af[mi], bf[ni]);
        }
        if (more) { sts(nxt, 0); ldg(ktn, 1); }
        {
            uint32_t af[4][4], bf[4][2];
#pragma unroll
            for (int mi = 0; mi < 4; mi++)
                ldsm_x4(af[mi], asmb[cur] + (uint32_t)((wm * 64 + mi * 16) * A2WS) * 4u + laneoff + 32u);
#pragma unroll
            for (int ni = 0; ni < 4; ni++) {
                int n0;
                if (IS_SWI) n0 = (ni < 2) ? (wn * 16 + ni * 8) : (64 + wn * 16 + (ni - 2) * 8);
                else        n0 = wn * 32 + ni * 8;
                bf[ni][0] = Bw[cur][(8 + t) * BWS + n0 + g];
                bf[ni][1] = Bw[cur][(8 + t + 4) * BWS + n0 + g];
            }
#pragma unroll
            for (int mi = 0; mi < 4; mi++)
#pragma unroll
                for (int ni = 0; ni < 4; ni++)
                    mma_f16(acc[mi][ni], af[mi], bf[ni]);
        }
        if (more) sts(nxt, 1);
        __syncthreads();
    }

    if (MODE == 0 || MODE == 1) {
#pragma unroll
        for (int mi = 0; mi < 4; mi++) {
            int r = row0 + wm * 64 + mi * 16 + g;
#pragma unroll
            for (int ni = 0; ni < 4; ni++) {
                int col = bx * 128 + wn * 32 + ni * 8 + 2 * t;
                float2 v0 = make_float2(acc[mi][ni][0], acc[mi][ni][1]);
                float2 v1 = make_float2(acc[mi][ni][2], acc[mi][ni][3]);
                if (MODE == 1) {
                    float2 d0 = *(const float2*)(Dadd + (size_t)r * ldc + col);
                    float2 d1 = *(const float2*)(Dadd + (size_t)(r + 8) * ldc + col);
                    v0.x += d0.x; v0.y += d0.y; v1.x += d1.x; v1.y += d1.y;
                }
                *(float2*)(outp + (size_t)r * ldc + col) = v0;
                *(float2*)(outp + (size_t)(r + 8) * ldc + col) = v1;
            }
        }
    } else if (IS_SWI) {
#pragma unroll
        for (int mi = 0; mi < 4; mi++) {
            int r = row0 + wm * 64 + mi * 16 + g;
#pragma unroll
            for (int ni = 0; ni < 2; ni++) {
                int col = bx * 64 + wn * 16 + ni * 8 + 2 * t;
#pragma unroll
                for (int h = 0; h < 2; h++) {
                    int rg = r + 8 * h;
                    if (MODE == 3 && rg >= cnt) continue;
                    float gg0 = acc[mi][ni][2 * h + 0], gg1 = acc[mi][ni][2 * h + 1];
                    float uu0 = acc[mi][ni + 2][2 * h + 0], uu1 = acc[mi][ni + 2][2 * h + 1];
                    float s0 = 1.f / (1.f + __expf(-uu0));
                    float s1 = 1.f / (1.f + __expf(-uu1));
                    float2 v = make_float2(gg0 * uu0 * s0, gg1 * uu1 * s1);
                    *(float2*)(outp + (size_t)rg * I_ + col) = v;
                }
            }
        }
    } else {  // MODE 4
#pragma unroll
        for (int mi = 0; mi < 4; mi++) {
            int rl = wm * 64 + mi * 16 + g;
#pragma unroll
            for (int h = 0; h < 2; h++) {
                int rr = rl + 8 * h;
                if (row0 + rr >= cnt) continue;
                int tok = toks_s[rr];
                float wv = ws_s[rr];
#pragma unroll
                for (int ni = 0; ni < 4; ni++) {
                    int col = bx * 128 + wn * 32 + ni * 8 + 2 * t;
                    atomicAdd(out + (size_t)tok * H_ + col,     acc[mi][ni][2 * h + 0] * wv);
                    atomicAdd(out + (size_t)tok * H_ + col + 1, acc[mi][ni][2 * h + 1] * wv);
                }
            }
        }
    }
}

// ---------------- small-M (32-row) fp16 expert mma kernel for overflow slots ----------
template<int MODE>
__global__ void __launch_bounds__(256, 2) mma_gemm_s(
    const float* __restrict__ A, int lda,
    const float* __restrict__ B, int ldb,
    float* __restrict__ out, int Kdim,
    const int* __restrict__ etok, const float* __restrict__ ew,
    const int* __restrict__ ecnt) {
    constexpr bool IS_SWI = (MODE == 3);

    int e = blockIdx.z;
    int cnt = ecnt[e];
    int row0 = 128 + blockIdx.y * 32;
    if (row0 >= cnt) return;
    int bx = blockIdx.x;

    __shared__ uint32_t Aw[2][32 * AWS];
    __shared__ uint32_t Bw[2][8 * BWS];
    __shared__ int   toks_s[32];
    __shared__ float ws_s[32];

    int tid = threadIdx.x;
    int wid = tid >> 5;
    int lane = tid & 31;
    int g = lane >> 2, t = lane & 3;
    int wn = wid;

    const float* Ab = A;
    const float* Bb = B;
    float* outp = out;
    if (MODE == 3) { Bb = B + (size_t)e * H_ * 2 * I_; outp = out + (size_t)e * CAP_ * I_; }
    if (MODE == 4) { Ab = A + (size_t)e * CAP_ * I_; Bb = B + (size_t)e * I_ * H_; }

    if (tid < 32) {
        int rr = row0 + tid;
        bool v = rr < cnt;
        toks_s[tid] = v ? etok[e * CAP_ + rr] : 0;
        ws_s[tid]   = v ? ew[e * CAP_ + rr] : 0.f;
    }
    __syncthreads();

    const float* arow_ptr = nullptr;
    int aq = 0;
    if (tid < 128) {
        int r = tid >> 2; aq = (tid & 3) * 4;
        if (MODE == 3) arow_ptr = A + (size_t)toks_s[r] * lda;
        else           arow_ptr = Ab + (size_t)(row0 + r) * lda;
    }
    int kp = tid >> 5, nq = tid & 31;
    int bcol;
    if (IS_SWI) bcol = (nq < 16) ? (bx * 64 + nq * 4) : (I_ + bx * 64 + (nq - 16) * 4);
    else        bcol = bx * 128 + nq * 4;
    const float* b_even = Bb + (size_t)(2 * kp) * ldb + bcol;
    const float* b_odd  = Bb + (size_t)(2 * kp + 1) * ldb + bcol;

    float4 aR, bE, bO;
    auto ldg = [&](int kt) {
        if (tid < 128) aR = *(const float4*)(arow_ptr + kt + aq);
        bE = *(const float4*)(b_even + (size_t)kt * ldb);
        bO = *(const float4*)(b_odd  + (size_t)kt * ldb);
    };
    auto sts = [&](int buf) {
        if (tid < 128) {
            int r = tid >> 2, q = tid & 3;
            uint2 w;
            w.x = pack_f16(aR.x, aR.y);
            w.y = pack_f16(aR.z, aR.w);
            *(uint2*)&Aw[buf][r * AWS + 2 * q] = w;
        }
        uint4 wb;
        wb.x = pack_f16(bE.x, bO.x);
        wb.y = pack_f16(bE.y, bO.y);
        wb.z = pack_f16(bE.z, bO.z);
        wb.w = pack_f16(bE.w, bO.w);
        *(uint4*)&Bw[buf][kp * BWS + nq * 4] = wb;
    };

    uint32_t asmb[2];
    asmb[0] = (uint32_t)__cvta_generic_to_shared(&Aw[0][0]);
    asmb[1] = (uint32_t)__cvta_generic_to_shared(&Aw[1][0]);
    int rowoff = (lane & 7) + ((lane >> 3) & 1) * 8;
    int wordoff = (lane >> 4) * 4;
    uint32_t laneoff = (uint32_t)(rowoff * AWS + wordoff) * 4u;

    float acc[2][2][4];
#pragma unroll
    for (int mi = 0; mi < 2; mi++)
#pragma unroll
        for (int ni = 0; ni < 2; ni++)
#pragma unroll
            for (int p = 0; p < 4; p++) acc[mi][ni][p] = 0.f;

    ldg(0); sts(0);
    __syncthreads();

    int NC = Kdim / 16;
    for (int c = 0; c < NC; c++) {
        int cur = c & 1;
        if (c + 1 < NC) ldg((c + 1) * 16);
        {
            uint32_t af[2][4], bf[2][2];
#pragma unroll
            for (int mi = 0; mi < 2; mi++)
                ldsm_x4(af[mi], asmb[cur] + (uint32_t)((mi * 16) * AWS) * 4u + laneoff);
#pragma unroll
            for (int ni = 0; ni < 2; ni++) {
                int n0;
                if (IS_SWI) n0 = (ni == 0) ? (wn * 8) : (64 + wn * 8);
                else        n0 = wn * 16 + ni * 8;
                bf[ni][0] = Bw[cur][t * BWS + n0 + g];
                bf[ni][1] = Bw[cur][(t + 4) * BWS + n0 + g];
            }
#pragma unroll
            for (int mi = 0; mi < 2; mi++)
#pragma unroll
                for (int ni = 0; ni < 2; ni++)
                    mma_f16(acc[mi][ni], af[mi], bf[ni]);
        }
        if (c + 1 < NC) sts(cur ^ 1);
        __syncthreads();
    }

    if (MODE == 3) {
#pragma unroll
        for (int mi = 0; mi < 2; mi++) {
            int col = bx * 64 + wn * 8 + 2 * t;
#pragma unroll
            for (int h = 0; h < 2; h++) {
                int rl = mi * 16 + g + 8 * h;
                int rg = row0 + rl;
                if (rg >= cnt) continue;
                float gg0 = acc[mi][0][2 * h + 0], gg1 = acc[mi][0][2 * h + 1];
                float uu0 = acc[mi][1][2 * h + 0], uu1 = acc[mi][1][2 * h + 1];
                float s0 = 1.f / (1.f + __expf(-uu0));
                float s1 = 1.f / (1.f + __expf(-uu1));
                float2 v = make_float2(gg0 * uu0 * s0, gg1 * uu1 * s1);
                *(float2*)(outp + (size_t)rg * I_ + col) = v;
            }
        }
    } else {
#pragma unroll
        for (int mi = 0; mi < 2; mi++) {
#pragma unroll
            for (int h = 0; h < 2; h++) {
                int rl = mi * 16 + g + 8 * h;
                if (row0 + rl >= cnt) continue;
                int tok = toks_s[rl];
                float wv = ws_s[rl];
#pragma unroll
                for (int ni = 0; ni < 2; ni++) {
                    int col = bx * 128 + wn * 16 + ni * 8 + 2 * t;
                    atomicAdd(out + (size_t)tok * H_ + col,     acc[mi][ni][2 * h + 0] * wv);
                    atomicAdd(out + (size_t)tok * H_ + col + 1, acc[mi][ni][2 * h + 1] * wv);
                }
            }
        }
    }
}

// ---------------- RMSNorm ----------------
__global__ void rmsnorm_kernel(const float* __restrict__ in, const float* __restrict__ w,
                               float* __restrict__ out) {
    int row = blockIdx.x, tid = threadIdx.x;
    const float* x = in + (size_t)row * H_;
    float s = 0.f;
    for (int i = tid; i < H_; i += 256) { float v = x[i]; s += v * v; }
    __shared__ float red[256];
    red[tid] = s; __syncthreads();
    for (int o = 128; o > 0; o >>= 1) { if (tid < o) red[tid] += red[tid + o]; __syncthreads(); }
    float sc = rsqrtf(red[0] * (1.f / H_) + 1e-6f);
    for (int i = tid; i < H_; i += 256) out[(size_t)row * H_ + i] = x[i] * sc * w[i];
}

// ---------------- QKV postprocess ----------------
__global__ void qkvproc_kernel(const float* __restrict__ qkv, const float* __restrict__ cosb,
                               const float* __restrict__ sinb, const float* __restrict__ qnw,
                               const float* __restrict__ knw, float* __restrict__ q,
                               float* __restrict__ k, float* __restrict__ v) {
    int s = blockIdx.x, tid = threadIdx.x;
    int w = tid >> 5, lane = tid & 31;
#pragma unroll
    for (int p = 0; p < 4; p++) {
        int r = w + 8 * p;
        int kv = r >> 2, slot = r & 3;
        int base = s * QKVN_ + kv * 256 + slot * 64;
        int d0 = lane * 2, d1 = d0 + 1;
        float x0 = qkv[base + d0], x1 = qkv[base + d1];
        float y0, y1;
        if (slot == 3) { y0 = x0; y1 = x1; }
        else {
            float p0 = __shfl_xor_sync(0xffffffffu, x0, 16);
            float p1 = __shfl_xor_sync(0xffffffffu, x1, 16);
            float rh0 = (lane < 16) ? -p0 : p0;
            float rh1 = (lane < 16) ? -p1 : p1;
            float c0 = cosb[s * HD_ + d0], s0 = sinb[s * HD_ + d0];
            float c1 = cosb[s * HD_ + d1], s1 = sinb[s * HD_ + d1];
            y0 = x0 * c0 + rh0 * s0;
            y1 = x1 * c1 + rh1 * s1;
            float ss = y0 * y0 + y1 * y1;
            for (int off = 16; off > 0; off >>= 1) ss += __shfl_xor_sync(0xffffffffu, ss, off);
            float scn = rsqrtf(ss * (1.f / HD_) + 1e-6f);
            const float* wn = (slot < 2) ? qnw : knw;
            y0 = y0 * scn * wn[d0];
            y1 = y1 * scn * wn[d1];
        }
        if (slot < 2) {
            int hh = kv * 2 + slot;
            size_t off = ((size_t)hh * S_ + s) * HD_;
            q[off + d0] = y0; q[off + d1] = y1;
        } else if (slot == 2) {
            size_t off = ((size_t)kv * S_ + s) * HD_;
            k[off + d0] = y0; k[off + d1] = y1;
        } else {
            size_t off = ((size_t)kv * S_ + s) * HD_;
            v[off + d0] = y0; v[off + d1] = y1;
        }
    }
}

// ---------------- flash attention partial, KV-split=2 (BQ=64, BK=32, 128 threads) -----
#define AQW 36
#define KWS 36
#define VWS 72

__global__ void __launch_bounds__(128) attn_part_kernel(const float* __restrict__ qg,
                                                        const float* __restrict__ kg,
                                                        const float* __restrict__ vg,
                                                        float* __restrict__ opart,
                                                        float* __restrict__ mlpart) {
    int qt = blockIdx.x, h = blockIdx.y, z = blockIdx.z;
    int q0 = qt * 64;
    const float* Q = qg + ((size_t)h * S_ + q0) * HD_;
    const float* Kp = kg + ((size_t)(h >> 1) * S_) * HD_;
    const float* Vp = vg + ((size_t)(h >> 1) * S_) * HD_;

    __shared__ uint32_t Qw[64 * AQW];
    __shared__ uint32_t Kw[32 * KWS];
    __shared__ uint32_t Vw[16 * VWS];

    int tid = threadIdx.x;
    int wid = tid >> 5;
    int lane = tid & 31;
    int g = lane >> 2, t = lane & 3;
    int m0w = wid * 16;

    for (int i = tid; i < 1024; i += 128) {
        int row = i >> 4, qq = i & 15;
        float4 v = *(const float4*)(Q + (size_t)row * HD_ + qq * 4);
        uint2 w;
        w.x = pack_f16(v.x, v.y);
        w.y = pack_f16(v.z, v.w);
        *(uint2*)&Qw[row * AQW + qq * 2] = w;
    }

    float acc_o[8][4];
#pragma unroll
    for (int i = 0; i < 8; i++)
#pragma unroll
        for (int p = 0; p < 4; p++) acc_o[i][p] = 0.f;
    float m[2] = {-1e30f, -1e30f};
    float l[2] = {0.f, 0.f};

    int nkt = (q0 + 64) / 32;          // 2*(qt+1) key tiles
    int half = nkt >> 1;               // = qt+1
    int kt_lo = z ? half : 0;
    int kt_hi = z ? nkt : half;
    for (int kt = kt_lo; kt < kt_hi; kt++) {
        int k0 = kt * 32;
        __syncthreads();
        for (int i = tid; i < 512; i += 128) {
            int key = i >> 4, qq = i & 15;
            float4 v = *(const float4*)(Kp + (size_t)(k0 + key) * HD_ + qq * 4);
            uint2 w;
            w.x = pack_f16(v.x, v.y);
            w.y = pack_f16(v.z, v.w);
            *(uint2*)&Kw[key * KWS + qq * 2] = w;
        }
        for (int i = tid; i < 256; i += 128) {
            int kp = i >> 4, qq = i & 15;
            float4 ve = *(const float4*)(Vp + (size_t)(k0 + 2 * kp) * HD_ + qq * 4);
            float4 vo = *(const float4*)(Vp + (size_t)(k0 + 2 * kp + 1) * HD_ + qq * 4);
            uint4 w;
            w.x = pack_f16(ve.x, vo.x);
            w.y = pack_f16(ve.y, vo.y);
            w.z = pack_f16(ve.z, vo.z);
            w.w = pack_f16(ve.w, vo.w);
            *(uint4*)&Vw[kp * VWS + qq * 4] = w;
        }
        __syncthreads();

        float sc[4][4];
#pragma unroll
        for (int ni = 0; ni < 4; ni++)
#pragma unroll
            for (int p = 0; p < 4; p++) sc[ni][p] = 0.f;
#pragma unroll
        for (int ck = 0; ck < 4; ck++) {
            uint32_t a[4];
            a[0] = Qw[(m0w + g) * AQW + ck * 8 + t];
            a[1] = Qw[(m0w + g + 8) * AQW + ck * 8 + t];
            a[2] = Qw[(m0w + g) * AQW + ck * 8 + t + 4];
            a[3] = Qw[(m0w + g + 8) * AQW + ck * 8 + t + 4];
#pragma unroll
            for (int ni = 0; ni < 4; ni++) {
                uint32_t b[2];
                b[0] = Kw[(ni * 8 + g) * KWS + ck * 8 + t];
                b[1] = Kw[(ni * 8 + g) * KWS + ck * 8 + t + 4];
                mma_f16(sc[ni], a, b);
            }
        }

#pragma unroll
        for (int h2 = 0; h2 < 2; h2++) {
            int row = q0 + m0w + g + 8 * h2;
            float mloc = -1e30f;
#pragma unroll
            for (int ni = 0; ni < 4; ni++)
#pragma unroll
                for (int p2 = 0; p2 < 2; p2++) {
                    int col = k0 + ni * 8 + 2 * t + p2;
                    float v = (col > row) ? -1e30f : sc[ni][2 * h2 + p2] * 0.125f;
                    sc[ni][2 * h2 + p2] = v;
                    mloc = fmaxf(mloc, v);
                }
            mloc = fmaxf(mloc, __shfl_xor_sync(0xffffffffu, mloc, 1));
            mloc = fmaxf(mloc, __shfl_xor_sync(0xffffffffu, mloc, 2));
            float mn = fmaxf(m[h2], mloc);
            float corr = __expf(m[h2] - mn);
            float rs = 0.f;
#pragma unroll
            for (int ni = 0; ni < 4; ni++)
#pragma unroll
                for (int p2 = 0; p2 < 2; p2++) {
                    float v = sc[ni][2 * h2 + p2];
                    float pv = (v <= -1e29f) ? 0.f : __expf(v - mn);
                    sc[ni][2 * h2 + p2] = pv;
                    rs += pv;
                }
            rs += __shfl_xor_sync(0xffffffffu, rs, 1);
            rs += __shfl_xor_sync(0xffffffffu, rs, 2);
            l[h2] = l[h2] * corr + rs;
            m[h2] = mn;
#pragma unroll
            for (int ni = 0; ni < 8; ni++) {
                acc_o[ni][2 * h2 + 0] *= corr;
                acc_o[ni][2 * h2 + 1] *= corr;
            }
        }

        uint32_t pa[2][4];
#pragma unroll
        for (int c = 0; c < 2; c++) {
            pa[c][0] = pack_f16(sc[2 * c][0], sc[2 * c][1]);
            pa[c][1] = pack_f16(sc[2 * c][2], sc[2 * c][3]);
            pa[c][2] = pack_f16(sc[2 * c + 1][0], sc[2 * c + 1][1]);
            pa[c][3] = pack_f16(sc[2 * c + 1][2], sc[2 * c + 1][3]);
        }
#pragma unroll
        for (int no = 0; no < 8; no++) {
#pragma unroll
            for (int c = 0; c < 2; c++) {
                uint32_t b[2];
                b[0] = Vw[(c * 8 + t) * VWS + no * 8 + g];
                b[1] = Vw[(c * 8 + t + 4) * VWS + no * 8 + g];
                mma_f16(acc_o[no], pa[c], b);
            }
        }
    }

    // epilogue: un-normalized O + (m, l)
    float* Op = opart + (size_t)z * (S_ * H_);
#pragma unroll
    for (int h2 = 0; h2 < 2; h2++) {
        int row = q0 + m0w + g + 8 * h2;
#pragma unroll
        for (int no = 0; no < 8; no++) {
            float2 v = make_float2(acc_o[no][2 * h2 + 0], acc_o[no][2 * h2 + 1]);
            *(float2*)(Op + (size_t)row * H_ + h * HD_ + no * 8 + 2 * t) = v;
        }
        if (t == 0) {
            mlpart[z * 16384 + h * 1024 + row] = m[h2];
            mlpart[32768 + z * 16384 + h * 1024 + row] = l[h2];
        }
    }
}

// merge the two KV-split partials
__global__ void __launch_bounds__(256) attn_merge_kernel(const float* __restrict__ opart,
                                                         const float* __restrict__ mlpart,
                                                         float* __restrict__ attn) {
    int row = blockIdx.x;
    int tid = threadIdx.x;
    int h = tid >> 4, d4 = (tid & 15) * 4;
    float m0 = mlpart[h * 1024 + row];
    float m1 = mlpart[16384 + h * 1024 + row];
    float l0 = mlpart[32768 + h * 1024 + row];
    float l1 = mlpart[32768 + 16384 + h * 1024 + row];
    float ms = fmaxf(m0, m1);
    float e0 = __expf(m0 - ms), e1 = __expf(m1 - ms);
    float li = 1.f / (l0 * e0 + l1 * e1);
    size_t off = (size_t)row * H_ + h * HD_ + d4;
    float4 o0 = *(const float4*)(opart + off);
    float4 o1 = *(const float4*)(opart + (size_t)(S_ * H_) + off);
    float4 r;
    r.x = (o0.x * e0 + o1.x * e1) * li;
    r.y = (o0.y * e0 + o1.y * e1) * li;
    r.z = (o0.z * e0 + o1.z * e1) * li;
    r.w = (o0.w * e0 + o1.w * e1) * li;
    *(float4*)(attn + off) = r;
}

// ---------------- gate + top-8 (parallel warp-argmax topk) ----------------
__global__ void gate_topk_kernel(const float* __restrict__ x2, const float* __restrict__ Wg,
                                 float* __restrict__ w8, int* __restrict__ idx8) {
    int tt = blockIdx.x, tid = threadIdx.x;
    const float* xr = x2 + (size_t)tt * H_;
    float a0 = 0.f, a1 = 0.f, a2 = 0.f, a3 = 0.f;
    for (int h = 0; h < H_; h += 4) {
        a0 = fmaf(xr[h],     Wg[(size_t)h * E_ + tid],       a0);
        a1 = fmaf(xr[h + 1], Wg[(size_t)(h + 1) * E_ + tid], a1);
        a2 = fmaf(xr[h + 2], Wg[(size_t)(h + 2) * E_ + tid], a2);
        a3 = fmaf(xr[h + 3], Wg[(size_t)(h + 3) * E_ + tid], a3);
    }
    float logit = (a0 + a1) + (a2 + a3);
    __shared__ float red[64];
    __shared__ float gv[64];
    red[tid] = logit; __syncthreads();
    for (int o = 32; o > 0; o >>= 1) { if (tid < o) red[tid] = fmaxf(red[tid], red[tid + o]); __syncthreads(); }
    float mx = red[0]; __syncthreads();
    float ex = __expf(logit - mx);
    red[tid] = ex; __syncthreads();
    for (int o = 32; o > 0; o >>= 1) { if (tid < o) red[tid] += red[tid + o]; __syncthreads(); }
    float sum = red[0];
    gv[tid] = ex / sum; __syncthreads();

    if (tid < 32) {
        float v0 = gv[tid], v1 = gv[tid + 32];
        float wsum = 0.f;
#pragma unroll
        for (int r = 0; r < TOPK_; r++) {
            float best; int bi;
            if (v1 > v0) { best = v1; bi = tid + 32; }
            else         { best = v0; bi = tid; }
#pragma unroll
            for (int off = 16; off > 0; off >>= 1) {
                float ov = __shfl_down_sync(0xffffffffu, best, off);
                int   oi = __shfl_down_sync(0xffffffffu, bi, off);
                if (ov > best) { best = ov; bi = oi; }
            }
            bi = __shfl_sync(0xffffffffu, bi, 0);
            best = __shfl_sync(0xffffffffu, best, 0);
            if (tid == 0) {
                w8[tt * TOPK_ + r] = best;   // temporarily unnormalized
                idx8[tt * TOPK_ + r] = bi;
            }
            wsum += (tid == 0) ? best : 0.f;
            if (bi == tid) v0 = -1e30f;
            if (bi == tid + 32) v1 = -1e30f;
        }
        if (tid == 0) {
            wsum = fmaxf(wsum, 1.1920929e-07f);
            float inv = 1.f / wsum;
#pragma unroll
            for (int r = 0; r < TOPK_; r++) w8[tt * TOPK_ + r] *= inv;
        }
    }
}

// ---------------- routing ----------------
__global__ void route_kernel(const int* __restrict__ idx8, const float* __restrict__ w8,
                             int* __restrict__ etok, float* __restrict__ ew, int* __restrict__ ecnt) {
    int e = blockIdx.x, lane = threadIdx.x;
    int cnt = 0;
    for (int base = 0; base < S_ * TOPK_; base += 32) {
        int j = base + lane;
        int ee = idx8[j];
        bool match = (ee == e);
        unsigned bal = __ballot_sync(0xffffffffu, match);
        int pre = __popc(bal & ((1u << lane) - 1u));
        if (match) {
            int p = cnt + pre;
            if (p < CAP_) {
                etok[e * CAP_ + p] = j >> 3;
                ew[e * CAP_ + p] = w8[j];
            }
        }
        cnt += __popc(bal);
    }
    if (lane == 0) ecnt[e] = (cnt < CAP_) ? cnt : CAP_;
}

// ---------------- launch ----------------
extern "C" void kernel_launch(void* const* d_in, const int* in_sizes, int n_in,
                              void* d_out, int out_size) {
    (void)in_sizes; (void)n_in; (void)out_size;
    const float* hidden = (const float*)d_in[0];
    const float* cosb   = (const float*)d_in[1];
    const float* sinb   = (const float*)d_in[2];
    const float* ln1    = (const float*)d_in[3];
    const float* ln2    = (const float*)d_in[4];
    const float* Wqkv   = (const float*)d_in[5];
    const float* Wo     = (const float*)d_in[6];
    const float* qnw    = (const float*)d_in[7];
    const float* knw    = (const float*)d_in[8];
    const float* Wgu_sh = (const float*)d_in[9];
    const float* Wd_sh  = (const float*)d_in[10];
    const float* Wgate  = (const float*)d_in[11];
    const float* Wgu_e  = (const float*)d_in[12];
    const float* Wd_e   = (const float*)d_in[13];
    float* out = (float*)d_out;

    float* fb = nullptr; int* ib = nullptr;
    cudaGetSymbolAddress((void**)&fb, g_fbuf);
    cudaGetSymbolAddress((void**)&ib, g_ibuf);

    float* x      = fb + OFF_X;
    float* qkv    = fb + OFF_QKV;
    float* q      = fb + OFF_Q;
    float* k      = fb + OFF_K;
    float* v      = fb + OFF_V;
    float* attn   = fb + OFF_ATTN;
    float* h1     = fb + OFF_H1;
    float* x2     = fb + OFF_X2;
    float* actsh  = fb + OFF_ACTSH;
    float* w8     = fb + OFF_W8;
    float* expw   = fb + OFF_EXPW;
    float* actexp = fb + OFF_ACTEXP;
    float* opart  = fb + OFF_ACTEXP;            // reuse (attn precedes experts)
    float* mlpart = opart + 2 * (size_t)S_ * H_;
    int* idx8   = ib + IOFF_IDX8;
    int* exptok = ib + IOFF_EXPTOK;
    int* expcnt = ib + IOFF_EXPCNT;

    // 1. x = rmsnorm(hidden, ln1)
    rmsnorm_kernel<<<S_, 256>>>(hidden, ln1, x);
    // 2. qkv = x @ Wqkv
    mma_gemm<0><<<dim3(QKVN_ / 128, S_ / 128), 256>>>(
        x, H_, Wqkv, QKVN_, nullptr, qkv, QKVN_, H_, nullptr, nullptr, nullptr);
    // 3. RoPE + QK-norm
    qkvproc_kernel<<<S_, 256>>>(qkv, cosb, sinb, qnw, knw, q, k, v);
    // 4. attention: KV-split partials + merge
    attn_part_kernel<<<dim3(S_ / 64, NH_, 2), 128>>>(q, k, v, opart, mlpart);
    attn_merge_kernel<<<S_, 256>>>(opart, mlpart, attn);
    // 5. h1 = attn @ Wo + hidden
    mma_gemm<1><<<dim3(H_ / 128, S_ / 128), 256>>>(
        attn, H_, Wo, H_, hidden, h1, H_, H_, nullptr, nullptr, nullptr);
    // 6. x2 = rmsnorm(h1, ln2)
    rmsnorm_kernel<<<S_, 256>>>(h1, ln2, x2);
    // 7. shared swiglu activation
    mma_gemm<2><<<dim3(I_ / 64, S_ / 128), 256>>>(
        x2, H_, Wgu_sh, 2 * I_, nullptr, actsh, I_, H_, nullptr, nullptr, nullptr);
    // 8. out = actsh @ Wd_sh + h1
    mma_gemm<1><<<dim3(H_ / 128, S_ / 128), 256>>>(
        actsh, I_, Wd_sh, H_, h1, out, H_, I_, nullptr, nullptr, nullptr);
    // 9. gate + top-8
    gate_topk_kernel<<<S_, 64>>>(x2, Wgate, w8, idx8);
    // 10. routing
    route_kernel<<<E_, 32>>>(idx8, w8, exptok, expw, expcnt);
    // 11a. expert swiglu, slots 0-127 (128-row mma)
    mma_gemm<3><<<dim3(I_ / 64, 1, E_), 256>>>(
        x2, H_, Wgu_e, 2 * I_, nullptr, actexp, I_, H_, exptok, nullptr, expcnt);
    // 11b. expert swiglu overflow slots 128..511 (32-row mma, early-exit)
    mma_gemm_s<3><<<dim3(I_ / 64, 12, E_), 256>>>(
        x2, H_, Wgu_e, 2 * I_, actexp, H_, exptok, nullptr, expcnt);
    // 12a. expert down + scatter, slots 0-127 (128-row mma)
    mma_gemm<4><<<dim3(H_ / 128, 1, E_), 256>>>(
        actexp, I_, Wd_e, H_, nullptr, out, H_, I_, exptok, expw, expcnt);
    // 12b. expert down overflow slots 128..511 (32-row mma, early-exit)
    mma_gemm_s<4><<<dim3(H_ / 128, 12, E_), 256>>>(
        actexp, I_, Wd_e, H_, out, I_, exptok, expw, expcnt);
}